// round 11
// baseline (speedup 1.0000x reference)
#include <cuda_runtime.h>
#include <cuda_bf16.h>
#include <math.h>

// Problem dims
#define BSZ   256
#define SIG   64
#define LATD  256
#define ENCH  256
#define DECH  512
#define RHSH  512
#define TSTEPS 200

#define NBLK   256   // persistent ODE grid: 8 groups x 32 CTAs, 2 CTAs/SM
#define GRPSZ  32
#define NGRP   8

// ---------------- scratch (device globals; no allocation) ----------------
__device__ float g_z[TSTEPS * BSZ * LATD];        // pred_z
__device__ float g_h1[BSZ * RHSH];
__device__ float g_h2[BSZ * RHSH];
__device__ float g_s[BSZ * RHSH];                 // RK4 combined h2 sum
__device__ float g_G[RHSH * RHSH];                // G = fw0 @ fw2  (512x512)
__device__ float g_g0[RHSH];                      // g0 = fw0 @ fb2
__device__ float g_x0[3 * BSZ * ENCH];
__device__ float g_x1[2 * BSZ * ENCH];
__device__ float g_hd1[(size_t)TSTEPS * BSZ * DECH];
__device__ float g_hd2[(size_t)TSTEPS * BSZ * DECH];

// per-group barrier state (one L2 line per group)
__device__ unsigned g_arr[NGRP * 32];
__device__ unsigned g_gen[NGRP * 32];

// ---------------- f32x2 packed-FMA helpers ----------------
__device__ __forceinline__ void fma2(unsigned long long& d,
                                     unsigned long long a,
                                     unsigned long long b)
{
    asm("fma.rn.f32x2 %0, %1, %2, %0;" : "+l"(d) : "l"(a), "l"(b));
}
__device__ __forceinline__ unsigned long long pack2(float x)
{
    unsigned long long r;
    asm("mov.b64 %0, {%1, %1};" : "=l"(r) : "f"(x));
    return r;
}
__device__ __forceinline__ void unpack2(float& lo, float& hi, unsigned long long v)
{
    asm("mov.b64 {%0, %1}, %2;" : "=f"(lo), "=f"(hi) : "l"(v));
}

// ---------------- group barrier (32 CTAs) ----------------
__device__ __forceinline__ void gsync(unsigned* arr, unsigned* gen, unsigned& lg)
{
    __syncthreads();
    if (threadIdx.x == 0) {
        unsigned ticket;
        asm volatile("atom.acq_rel.gpu.add.u32 %0, [%1], 1;"
                     : "=r"(ticket) : "l"(arr) : "memory");
        const unsigned target = lg + 1;
        if ((ticket & (GRPSZ - 1)) == GRPSZ - 1) {
            asm volatile("st.release.gpu.u32 [%0], %1;"
                         :: "l"(gen), "r"(target) : "memory");
        } else {
            unsigned g;
            do {
                asm volatile("ld.acquire.gpu.u32 %0, [%1];"
                             : "=r"(g) : "l"(gen) : "memory");
            } while ((int)(g - target) < 0);
        }
        lg = target;
    }
    __syncthreads();
}

// ---------------- A staging: 32 rows x 128-k chunk (row stride 512) --------
__device__ __forceinline__ void stageA(float* __restrict__ As,
                                       const float* __restrict__ Abuf,
                                       int m0, int r, int tid)
{
    const int m  = tid & 31;
    const int kq = tid >> 5;
    const float* row = Abuf + (size_t)(m0 + m) * 512 + r * 128;
#pragma unroll
    for (int it = 0; it < 4; ++it) {
        const int k = (it * 8 + kq) * 4;
        const float4 v = __ldcg((const float4*)(row + k));
        As[(k + 0) * 32 + m] = v.x;
        As[(k + 1) * 32 + m] = v.y;
        As[(k + 2) * 32 + m] = v.z;
        As[(k + 3) * 32 + m] = v.w;
    }
}

// ---------------- core GEMM: red = A(32x512) @ Ws(512x16 [k][n]) ----------
// 256 thr = 8 k-splits x (8tm x 4tn), thread tile 4m x 4n, f32x2 accum.
// Leaves partials in red[8][32][16].
__device__ __forceinline__ void gemm16(const float* __restrict__ Abuf,
                                       const float* __restrict__ Ws,
                                       float* __restrict__ As,
                                       float* __restrict__ red,
                                       int m0, int tid)
{
    const int ks = tid >> 5, lane = tid & 31;
    const int tm = lane >> 2, tn = lane & 3;
    unsigned long long acc[2][4] = {{0ULL,0ULL,0ULL,0ULL},{0ULL,0ULL,0ULL,0ULL}};

#pragma unroll
    for (int r = 0; r < 4; ++r) {
        stageA(As, Abuf, m0, r, tid);
        __syncthreads();
        const float* Ag = As + ks * 16 * 32 + tm * 4;
        const float* Wg = Ws + (size_t)(r * 128 + ks * 16) * 16 + tn * 4;
#pragma unroll
        for (int i = 0; i < 16; ++i) {
            const ulonglong2 a2 = *(const ulonglong2*)(Ag + i * 32);
            const float4 b4 = *(const float4*)(Wg + i * 16);
            const unsigned long long b0 = pack2(b4.x), b1 = pack2(b4.y),
                                     b2 = pack2(b4.z), b3 = pack2(b4.w);
            fma2(acc[0][0], a2.x, b0); fma2(acc[1][0], a2.y, b0);
            fma2(acc[0][1], a2.x, b1); fma2(acc[1][1], a2.y, b1);
            fma2(acc[0][2], a2.x, b2); fma2(acc[1][2], a2.y, b2);
            fma2(acc[0][3], a2.x, b3); fma2(acc[1][3], a2.y, b3);
        }
        __syncthreads();
    }
#pragma unroll
    for (int i = 0; i < 2; ++i)
#pragma unroll
        for (int j = 0; j < 4; ++j) {
            float lo, hi;
            unpack2(lo, hi, acc[i][j]);
            red[ks * 512 + (tm * 4 + 2 * i)     * 16 + tn * 4 + j] = lo;
            red[ks * 512 + (tm * 4 + 2 * i + 1) * 16 + tn * 4 + j] = hi;
        }
    __syncthreads();
}

__device__ __forceinline__ float red8(const float* __restrict__ red, int m, int n)
{
    float v = 0.f;
#pragma unroll
    for (int q = 0; q < 8; ++q) v += red[q * 512 + m * 16 + n];
    return v;
}

// ---------------- z GEMM: red = s(32x512) @ W2s(512x8 [k][n]) --------------
// 256 thr = 8 k-splits x (8tm x 4tn), thread tile 4m x 2n.
__device__ __forceinline__ void gemmZ(const float* __restrict__ Abuf,
                                      const float* __restrict__ Ws,
                                      float* __restrict__ As,
                                      float* __restrict__ red,
                                      int m0, int tid)
{
    const int ks = tid >> 5, lane = tid & 31;
    const int tm = lane >> 2, tn = lane & 3;
    unsigned long long acc[2][2] = {{0ULL,0ULL},{0ULL,0ULL}};

#pragma unroll
    for (int r = 0; r < 4; ++r) {
        stageA(As, Abuf, m0, r, tid);
        __syncthreads();
        const float* Ag = As + ks * 16 * 32 + tm * 4;
        const float* Wg = Ws + (size_t)(r * 128 + ks * 16) * 8 + tn * 2;
#pragma unroll
        for (int i = 0; i < 16; ++i) {
            const ulonglong2 a2 = *(const ulonglong2*)(Ag + i * 32);
            const float2 b2 = *(const float2*)(Wg + i * 8);
            const unsigned long long b0 = pack2(b2.x), b1 = pack2(b2.y);
            fma2(acc[0][0], a2.x, b0); fma2(acc[1][0], a2.y, b0);
            fma2(acc[0][1], a2.x, b1); fma2(acc[1][1], a2.y, b1);
        }
        __syncthreads();
    }
#pragma unroll
    for (int i = 0; i < 2; ++i)
#pragma unroll
        for (int j = 0; j < 2; ++j) {
            float lo, hi;
            unpack2(lo, hi, acc[i][j]);
            red[ks * 256 + (tm * 4 + 2 * i)     * 8 + tn * 2 + j] = lo;
            red[ks * 256 + (tm * 4 + 2 * i + 1) * 8 + tn * 2 + j] = hi;
        }
    __syncthreads();
}

// ---------------- persistent ODE kernel (w-space, 2 CTAs/SM) ----------------
__global__ void __launch_bounds__(256, 2) ode_kernel(
    const float* __restrict__ t,
    const float* __restrict__ fw0, const float* __restrict__ fb0,
    const float* __restrict__ fw1, const float* __restrict__ fb1,
    const float* __restrict__ fw2, const float* __restrict__ fb2,
    const float* __restrict__ Gm,  const float* __restrict__ g0,
    float* __restrict__ zbuf, float* __restrict__ h1buf,
    float* __restrict__ h2buf, float* __restrict__ sbuf)
{
    extern __shared__ float smem[];
    float* W1s = smem;                 // 512k x 16n = 8192 f (32 KB)
    float* Gs  = W1s + 8192;           // 512k x 16n = 8192 f (32 KB)
    float* W2s = Gs  + 8192;           // 512k x  8n = 4096 f (16 KB)
    float* As  = W2s + 4096;           // 128k x 32m = 4096 f (16 KB)
    float* red = As  + 4096;           //              4096 f (16 KB)
    float* bS  = red + 4096;           // b1(16) | g0(16) | b2(8) = 40 f
                                       // total 28712 f = 114848 B

    const int tid = threadIdx.x;
    const int c   = blockIdx.x & 31;   // N-slice 0..31
    const int grp = blockIdx.x >> 5;   // batch group 0..7
    const int m0  = grp * 32;
    const int n0  = c * 16;            // 512-dim slice start
    const int nz0 = c * 8;             // 256-dim slice start

    // ---- stage weight slices ([k][n]) + biases
    for (int e = tid; e < 16 * 512; e += 256) {
        const int n = e >> 9, k = e & 511;
        W1s[k * 16 + n] = fw1[(size_t)(n0 + n) * 512 + k];
        Gs [k * 16 + n] = Gm [(size_t)(n0 + n) * 512 + k];
    }
    for (int e = tid; e < 8 * 512; e += 256) {
        const int n = e >> 9, k = e & 511;
        W2s[k * 8 + n] = fw2[(size_t)(nz0 + n) * 512 + k];
    }
    if (tid < 16)       bS[tid] = fb1[n0 + tid];
    else if (tid < 32)  bS[tid] = g0[n0 + tid - 16];
    else if (tid < 40)  bS[tid] = fb2[nz0 + tid - 32];
    __syncthreads();

    // ---- per-thread persistent regs: elem it <-> row (tid>>4)+16*it, col tid&15
    const int mr = tid >> 4;
    const int nn = tid & 15;
    float w[2], u[2] = {0.f, 0.f}, s[2] = {0.f, 0.f};

    // ---- init w = W0 @ z0 + b0 (one-time)
    {
        const float b0v = fb0[n0 + nn];
        float wa[2] = {b0v, b0v};
        const float* w0row = fw0 + (size_t)(n0 + nn) * 256;
#pragma unroll
        for (int r = 0; r < 2; ++r) {
            const int m  = tid & 31;
            const int kq = tid >> 5;
            const float* row = zbuf + (size_t)(m0 + m) * 256 + r * 128;
#pragma unroll
            for (int it = 0; it < 4; ++it) {
                const int k = (it * 8 + kq) * 4;
                const float4 v = __ldcg((const float4*)(row + k));
                As[(k + 0) * 32 + m] = v.x; As[(k + 1) * 32 + m] = v.y;
                As[(k + 2) * 32 + m] = v.z; As[(k + 3) * 32 + m] = v.w;
            }
            __syncthreads();
            for (int l = 0; l < 128; l += 4) {
                const float4 wv = __ldcg((const float4*)(w0row + r * 128 + l));
#pragma unroll
                for (int j = 0; j < 4; ++j) {
                    const float wj = (&wv.x)[j];
                    wa[0] = fmaf(As[(l + j) * 32 + mr],      wj, wa[0]);
                    wa[1] = fmaf(As[(l + j) * 32 + mr + 16], wj, wa[1]);
                }
            }
            __syncthreads();
        }
        w[0] = wa[0]; w[1] = wa[1];
    }

    unsigned* arr = &g_arr[grp * 32];
    unsigned* gen = &g_gen[grp * 32];
    unsigned lg = 0;
    if (tid == 0)
        asm volatile("ld.acquire.gpu.u32 %0, [%1];" : "=r"(lg) : "l"(gen) : "memory");

    for (int n = 0; n < TSTEPS - 1; ++n) {
        const float hh = __ldg(&t[n + 1]) - __ldg(&t[n]);
        const float h6 = hh * (1.f / 6.f);
        const float* zn = zbuf + (size_t)n * (BSZ * LATD);
        float* znx      = zbuf + (size_t)(n + 1) * (BSZ * LATD);

#pragma unroll 1
        for (int st = 0; st < 4; ++st) {
            const float cc = (st == 0) ? 0.f : ((st == 3) ? hh : 0.5f * hh);
            const float sw = (st == 1 || st == 2) ? 2.f : 1.f;

            if (st > 0) {               // u = G @ h2 + g0
                gemm16(h2buf, Gs, As, red, m0, tid);
#pragma unroll
                for (int it = 0; it < 2; ++it)
                    u[it] = red8(red, mr + 16 * it, nn) + bS[16 + nn];
            }
            // h1 = tanh(w + c*u)
#pragma unroll
            for (int it = 0; it < 2; ++it)
                h1buf[(size_t)(m0 + mr + 16 * it) * 512 + n0 + nn] =
                    tanhf(fmaf(cc, u[it], w[it]));
            gsync(arr, gen, lg);

            // h2 = tanh(W1 @ h1 + b1); s += sw*h2
            gemm16(h1buf, W1s, As, red, m0, tid);
#pragma unroll
            for (int it = 0; it < 2; ++it) {
                const int m = mr + 16 * it;
                float v = red8(red, m, nn) + bS[nn];
                v = tanhf(v);
                s[it] = fmaf(sw, v, s[it]);
                if (st < 3) h2buf[(size_t)(m0 + m) * 512 + n0 + nn] = v;
                else        sbuf [(size_t)(m0 + m) * 512 + n0 + nn] = s[it];
            }
            gsync(arr, gen, lg);
        }

        // ---- end of step: w += (h/6) G s + h g0 ; z_{n+1} = z_n + (h/6) W2 s + h b2
        gemm16(sbuf, Gs, As, red, m0, tid);
#pragma unroll
        for (int it = 0; it < 2; ++it)
            w[it] += h6 * red8(red, mr + 16 * it, nn) + hh * bS[16 + nn];

        gemmZ(sbuf, W2s, As, red, m0, tid);
        {
            const int m = tid >> 3, nz = tid & 7;
            float v = 0.f;
#pragma unroll
            for (int q = 0; q < 8; ++q) v += red[q * 256 + m * 8 + nz];
            const size_t idx = (size_t)(m0 + m) * 256 + nz0 + nz;
            znx[idx] = __ldcg(zn + idx) + h6 * v + hh * bS[32 + nz];
        }
        s[0] = 0.f; s[1] = 0.f;
    }
}

// ---------------- G = fw0 @ fw2 precompute (NN GEMM 512x512x256) -----------
__launch_bounds__(256)
__global__ void gemmG_kernel(const float* __restrict__ fw0,
                             const float* __restrict__ fw2,
                             float* __restrict__ G)
{
    __shared__ float As[16][68];
    __shared__ float Bs[16][68];
    const int tid = threadIdx.x;
    const int tx = tid & 15, ty = tid >> 4;
    const int m0 = blockIdx.y * 64, n0 = blockIdx.x * 64;

    float acc[4][4] = {};
    for (int k0 = 0; k0 < 256; k0 += 16) {
        {
            const int ar = tid >> 2, ak = (tid & 3) * 4;
            const float4 av = *(const float4*)(fw0 + (size_t)(m0 + ar) * 256 + k0 + ak);
            As[ak + 0][ar] = av.x; As[ak + 1][ar] = av.y;
            As[ak + 2][ar] = av.z; As[ak + 3][ar] = av.w;
            const int kk = tid >> 4, bn = (tid & 15) * 4;
            const float4 bv = *(const float4*)(fw2 + (size_t)(k0 + kk) * 512 + n0 + bn);
            *(float4*)&Bs[kk][bn] = bv;
        }
        __syncthreads();
#pragma unroll
        for (int k = 0; k < 16; ++k) {
            float a[4], b[4];
#pragma unroll
            for (int i = 0; i < 4; ++i) a[i] = As[k][ty * 4 + i];
#pragma unroll
            for (int j = 0; j < 4; ++j) b[j] = Bs[k][tx * 4 + j];
#pragma unroll
            for (int i = 0; i < 4; ++i)
#pragma unroll
                for (int j = 0; j < 4; ++j) acc[i][j] = fmaf(a[i], b[j], acc[i][j]);
        }
        __syncthreads();
    }
#pragma unroll
    for (int i = 0; i < 4; ++i)
#pragma unroll
        for (int j = 0; j < 4; ++j)
            G[(size_t)(m0 + ty * 4 + i) * 512 + n0 + tx * 4 + j] = acc[i][j];
}

__global__ void g0_kernel(const float* __restrict__ fw0,
                          const float* __restrict__ fb2,
                          float* __restrict__ g0)
{
    const int n = blockIdx.x * 256 + threadIdx.x;
    float acc = 0.f;
    for (int l = 0; l < 256; ++l)
        acc = fmaf(fw0[(size_t)n * 256 + l], fb2[l], acc);
    g0[n] = acc;
}

// ---------------- encoder: fused wcat + im2col gather + GEMM ----------------
template<int G>
__device__ __forceinline__ float gatherA(const float* __restrict__ src, int row, int c)
{
    if (G == 1) {
        const int l = row >> 8, b = row & 255;
        if (c < 192) {
            const int i = c / 3, kk = c - 3 * i, p = l + kk - 1;
            return (p >= 0) ? src[(size_t)b * 65536 + i * 1024 + p] : 0.f;
        }
        return src[(size_t)b * 65536 + (c - 192) * 1024 + l];
    } else if (G == 2) {
        const int l = row >> 8, b = row & 255;
        if (c < 768) {
            const int i = c / 3, kk = c - 3 * i, p = l + kk - 1;
            return (p >= 0) ? src[(size_t)(p * 256 + b) * 256 + i] : 0.f;
        }
        return src[(size_t)(l * 256 + b) * 256 + (c - 768)];
    } else {
        const int b = row;
        if (c < 256)  return src[(size_t)b * 256 + c];
        if (c < 512)  return src[(size_t)(256 + b) * 256 + (c - 256)];
        return src[(size_t)b * 256 + (c - 512)];
    }
}

template<int G>
__device__ __forceinline__ float gatherW(const float* __restrict__ ew,
                                         const float* __restrict__ rw, int o, int c)
{
    if (G == 1) {
        if (c < 192) return ew[o * 192 + c];
        return rw[o * 64 + (c - 192)];
    } else if (G == 2) {
        if (c < 768) return ew[o * 768 + c];
        return rw[o * 256 + (c - 768)];
    } else {
        if (c < 256)  return ew[o * 768 + c * 3 + 1];
        if (c < 512)  return ew[o * 768 + (c - 256) * 3 + 2];
        return rw[o * 256 + (c - 512)];
    }
}

template<int G, int TANH>
__launch_bounds__(256)
__global__ void enc_gemm(const float* __restrict__ Asrc,
                         const float* __restrict__ ew, const float* __restrict__ rw,
                         const float* __restrict__ eb, const float* __restrict__ rb,
                         float* __restrict__ C, int K)
{
    __shared__ float As[32][34];
    __shared__ float Bs[32][34];

    const int tid = threadIdx.x;
    const int tx  = tid & 15;
    const int ty  = tid >> 4;
    const int m0  = blockIdx.y * 32;
    const int n0  = blockIdx.x * 32;

    const int ar = tid >> 3;
    const int ak = (tid & 7) * 4;

    float acc[2][2] = {{0.f, 0.f}, {0.f, 0.f}};

    for (int k0 = 0; k0 < K; k0 += 32) {
#pragma unroll
        for (int j = 0; j < 4; j++) {
            As[ak + j][ar] = gatherA<G>(Asrc, m0 + ar, k0 + ak + j);
            Bs[ak + j][ar] = gatherW<G>(ew, rw, n0 + ar, k0 + ak + j);
        }
        __syncthreads();
#pragma unroll
        for (int k = 0; k < 32; k++) {
            const float a0 = As[k][ty * 2], a1 = As[k][ty * 2 + 1];
            const float b0 = Bs[k][tx * 2], b1 = Bs[k][tx * 2 + 1];
            acc[0][0] = fmaf(a0, b0, acc[0][0]);
            acc[0][1] = fmaf(a0, b1, acc[0][1]);
            acc[1][0] = fmaf(a1, b0, acc[1][0]);
            acc[1][1] = fmaf(a1, b1, acc[1][1]);
        }
        __syncthreads();
    }

#pragma unroll
    for (int i = 0; i < 2; i++) {
        const int m = m0 + ty * 2 + i;
#pragma unroll
        for (int j = 0; j < 2; j++) {
            const int n = n0 + tx * 2 + j;
            float v = acc[i][j] + eb[n] + rb[n];
            if (TANH) v = tanhf(v);
            C[(size_t)m * 256 + n] = v;
        }
    }
}

// ---------------- decoder GEMM: 64x64x16 tile, f32x2 inner ----------------
template<int EPI>
__launch_bounds__(256)
__global__ void dec_gemm(const float* __restrict__ A,
                         const float* __restrict__ W,
                         const float* __restrict__ bias,
                         float* __restrict__ C,
                         int M, int N, int K)
{
    __shared__ float As[16][68];
    __shared__ float Bs[16][68];

    const int tid = threadIdx.x;
    const int tx  = tid & 15;
    const int ty  = tid >> 4;
    const int m0  = blockIdx.y * 64;
    const int n0  = blockIdx.x * 64;

    const int ar = tid >> 2;
    const int ak = (tid & 3) * 4;

    unsigned long long acc2[2][4];
#pragma unroll
    for (int i = 0; i < 2; i++)
#pragma unroll
        for (int j = 0; j < 4; j++) acc2[i][j] = 0ULL;

    const float* Aptr = A + (size_t)(m0 + ar) * K + ak;
    const float* Wptr = W + (size_t)(n0 + ar) * K + ak;

    for (int k0 = 0; k0 < K; k0 += 16) {
        const float4 av = *(const float4*)(Aptr + k0);
        const float4 bv = *(const float4*)(Wptr + k0);
        As[ak + 0][ar] = av.x; As[ak + 1][ar] = av.y;
        As[ak + 2][ar] = av.z; As[ak + 3][ar] = av.w;
        Bs[ak + 0][ar] = bv.x; Bs[ak + 1][ar] = bv.y;
        Bs[ak + 2][ar] = bv.z; Bs[ak + 3][ar] = bv.w;
        __syncthreads();
#pragma unroll
        for (int k = 0; k < 16; k++) {
            const ulonglong2 a2 = *(const ulonglong2*)(&As[k][ty * 4]);
            const float4 b4 = *(const float4*)(&Bs[k][tx * 4]);
            unsigned long long bb[4];
            bb[0] = pack2(b4.x); bb[1] = pack2(b4.y);
            bb[2] = pack2(b4.z); bb[3] = pack2(b4.w);
#pragma unroll
            for (int j = 0; j < 4; j++) {
                fma2(acc2[0][j], a2.x, bb[j]);
                fma2(acc2[1][j], a2.y, bb[j]);
            }
        }
        __syncthreads();
    }

#pragma unroll
    for (int i = 0; i < 2; i++) {
#pragma unroll
        for (int j = 0; j < 4; j++) {
            float lo, hi;
            unpack2(lo, hi, acc2[i][j]);
            const int n = n0 + tx * 4 + j;
            const float bval = bias[n];
#pragma unroll
            for (int half = 0; half < 2; half++) {
                const int m = m0 + ty * 4 + 2 * i + half;
                float v = (half == 0 ? lo : hi) + bval;
                if (EPI == 1) v = tanhf(v);
                if (EPI == 3) {
                    const int tt = m >> 8;
                    const int bb2 = m & 255;
                    C[(size_t)bb2 * (SIG * TSTEPS) + (size_t)n * TSTEPS + tt] = v;
                } else {
                    C[(size_t)m * N + n] = v;
                }
            }
        }
    }
}

extern "C" void kernel_launch(void* const* d_in, const int* in_sizes, int n_in,
                              void* d_out, int out_size)
{
    const float* y   = (const float*)d_in[0];
    const float* t   = (const float*)d_in[1];
    const float* ew0 = (const float*)d_in[2];
    const float* eb0 = (const float*)d_in[3];
    const float* rw0 = (const float*)d_in[4];
    const float* rb0 = (const float*)d_in[5];
    const float* ew1 = (const float*)d_in[6];
    const float* eb1 = (const float*)d_in[7];
    const float* rw1 = (const float*)d_in[8];
    const float* rb1 = (const float*)d_in[9];
    const float* ew2 = (const float*)d_in[10];
    const float* eb2 = (const float*)d_in[11];
    const float* rw2 = (const float*)d_in[12];
    const float* rb2 = (const float*)d_in[13];
    const float* fw0 = (const float*)d_in[14];
    const float* fb0 = (const float*)d_in[15];
    const float* fw1 = (const float*)d_in[16];
    const float* fb1 = (const float*)d_in[17];
    const float* fw2 = (const float*)d_in[18];
    const float* fb2 = (const float*)d_in[19];
    const float* dw0 = (const float*)d_in[20];
    const float* db0 = (const float*)d_in[21];
    const float* dw1 = (const float*)d_in[22];
    const float* db1 = (const float*)d_in[23];
    const float* dw2 = (const float*)d_in[24];
    const float* db2 = (const float*)d_in[25];
    float* out = (float*)d_out;

    float *zbuf, *h1, *h2, *sbuf, *Gm, *g0, *x0, *x1, *hd1, *hd2;
    cudaGetSymbolAddress((void**)&zbuf, g_z);
    cudaGetSymbolAddress((void**)&h1,   g_h1);
    cudaGetSymbolAddress((void**)&h2,   g_h2);
    cudaGetSymbolAddress((void**)&sbuf, g_s);
    cudaGetSymbolAddress((void**)&Gm,   g_G);
    cudaGetSymbolAddress((void**)&g0,   g_g0);
    cudaGetSymbolAddress((void**)&x0,   g_x0);
    cudaGetSymbolAddress((void**)&x1,   g_x1);
    cudaGetSymbolAddress((void**)&hd1,  g_hd1);
    cudaGetSymbolAddress((void**)&hd2,  g_hd2);

    // ---------- encoder: 3 fused gather-GEMMs -> z0 ----------
    { dim3 g(8, 24); enc_gemm<1, 1><<<g, 256>>>(y,  ew0, rw0, eb0, rb0, x0, 256);  }
    { dim3 g(8, 16); enc_gemm<2, 1><<<g, 256>>>(x0, ew1, rw1, eb1, rb1, x1, 1024); }
    { dim3 g(8, 8);  enc_gemm<3, 0><<<g, 256>>>(x1, ew2, rw2, eb2, rb2, zbuf, 768);}

    // ---------- precompute G = fw0 @ fw2, g0 = fw0 @ fb2 ----------
    { dim3 g(8, 8); gemmG_kernel<<<g, 256>>>(fw0, fw2, Gm); }
    g0_kernel<<<2, 256>>>(fw0, fb2, g0);

    // ---------- RK4 ODE: persistent kernel, 8 groups x 32 CTAs, 2 CTAs/SM ----------
    const int smem_bytes = (8192 + 8192 + 4096 + 4096 + 4096 + 40) * 4;
    cudaFuncSetAttribute(ode_kernel, cudaFuncAttributeMaxDynamicSharedMemorySize,
                         smem_bytes);
    ode_kernel<<<NBLK, 256, smem_bytes>>>(t, fw0, fb0, fw1, fb1, fw2, fb2,
                                          Gm, g0, zbuf, h1, h2, sbuf);

    // ---------- decoder over all 200 states ----------
    { dim3 g(DECH / 64, TSTEPS * BSZ / 64); dec_gemm<1><<<g, 256>>>(zbuf, dw0, db0, hd1, TSTEPS * BSZ, DECH, LATD); }
    { dim3 g(DECH / 64, TSTEPS * BSZ / 64); dec_gemm<1><<<g, 256>>>(hd1,  dw1, db1, hd2, TSTEPS * BSZ, DECH, DECH); }
    { dim3 g(SIG  / 64, TSTEPS * BSZ / 64); dec_gemm<3><<<g, 256>>>(hd2,  dw2, db2, out, TSTEPS * BSZ, SIG,  DECH); }
}

// round 12
// speedup vs baseline: 1.0406x; 1.0406x over previous
#include <cuda_runtime.h>
#include <cuda_bf16.h>
#include <math.h>

// Problem dims
#define BSZ   256
#define SIG   64
#define LATD  256
#define ENCH  256
#define DECH  512
#define RHSH  512
#define TSTEPS 200

#define NBLK   128   // persistent ODE grid: 8 groups x 16 CTAs (R7 config)
#define GRPSZ  16
#define NGRP   8

// ---------------- scratch (device globals; no allocation) ----------------
__device__ float g_z[TSTEPS * BSZ * LATD];        // pred_z
__device__ float g_h1[BSZ * RHSH];
__device__ float g_h2[BSZ * RHSH];
__device__ float g_s[BSZ * RHSH];                 // RK4 combined h2 sum
__device__ float g_G[RHSH * RHSH];                // G = fw0 @ fw2
__device__ float g_g0[RHSH];                      // g0 = fw0 @ fb2
__device__ float g_x0[3 * BSZ * ENCH];
__device__ float g_x1[2 * BSZ * ENCH];
__device__ float g_hd1[(size_t)TSTEPS * BSZ * DECH];
__device__ float g_hd2[(size_t)TSTEPS * BSZ * DECH];

// per-group barrier state (one L2 line per group)
__device__ unsigned g_arr[NGRP * 32];
__device__ unsigned g_gen[NGRP * 32];

// ---------------- f32x2 packed-FMA helpers ----------------
__device__ __forceinline__ void fma2(unsigned long long& d,
                                     unsigned long long a,
                                     unsigned long long b)
{
    asm("fma.rn.f32x2 %0, %1, %2, %0;" : "+l"(d) : "l"(a), "l"(b));
}
__device__ __forceinline__ unsigned long long pack2(float x)
{
    unsigned long long r;
    asm("mov.b64 %0, {%1, %1};" : "=l"(r) : "f"(x));
    return r;
}
__device__ __forceinline__ void unpack2(float& lo, float& hi, unsigned long long v)
{
    asm("mov.b64 {%0, %1}, %2;" : "=f"(lo), "=f"(hi) : "l"(v));
}

// ---------------- split-phase group barrier (16 CTAs) ----------------
__device__ __forceinline__ void gsync_arrive(unsigned* arr, unsigned* gen, unsigned& lg)
{
    __syncthreads();
    if (threadIdx.x == 0) {
        unsigned ticket;
        asm volatile("atom.acq_rel.gpu.add.u32 %0, [%1], 1;"
                     : "=r"(ticket) : "l"(arr) : "memory");
        const unsigned target = lg + 1;
        if ((ticket & (GRPSZ - 1)) == GRPSZ - 1) {
            asm volatile("st.release.gpu.u32 [%0], %1;"
                         :: "l"(gen), "r"(target) : "memory");
        }
        lg = target;
    }
}
__device__ __forceinline__ void gsync_wait(unsigned* gen, unsigned lg)
{
    if (threadIdx.x == 0) {
        unsigned g;
        do {
            asm volatile("ld.acquire.gpu.u32 %0, [%1];"
                         : "=r"(g) : "l"(gen) : "memory");
        } while ((int)(g - lg) < 0);
    }
    __syncthreads();
}
__device__ __forceinline__ void gsync(unsigned* arr, unsigned* gen, unsigned& lg)
{
    gsync_arrive(arr, gen, lg);
    gsync_wait(gen, lg);
}

// ---------------- A staging: 32 rows x 256-k chunk (row stride 512) --------
__device__ __forceinline__ void stageA(float* __restrict__ As,
                                       const float* __restrict__ Abuf,
                                       int m0, int r, int tid)
{
    const int m  = tid & 31;
    const int kq = tid >> 5;
    const float* row = Abuf + (size_t)(m0 + m) * 512 + r * 256;
#pragma unroll
    for (int it = 0; it < 8; ++it) {
        const int k = (it * 8 + kq) * 4;
        const float4 v = __ldcg((const float4*)(row + k));
        As[(k + 0) * 32 + m] = v.x;
        As[(k + 1) * 32 + m] = v.y;
        As[(k + 2) * 32 + m] = v.z;
        As[(k + 3) * 32 + m] = v.w;
    }
}

// ---------------- core GEMM: red = A(32x512) @ Ws(512x32 [k][n]) ----------
__device__ __forceinline__ void gemm32(const float* __restrict__ Abuf,
                                       const float* __restrict__ Ws,
                                       float* __restrict__ As,
                                       float* __restrict__ red,
                                       int m0, int tid)
{
    const int ks = tid >> 6, inner = tid & 63;
    const int tm = inner >> 3, tn = inner & 7;
    unsigned long long acc[2][4] = {{0ULL,0ULL,0ULL,0ULL},{0ULL,0ULL,0ULL,0ULL}};

#pragma unroll
    for (int r = 0; r < 2; ++r) {
        stageA(As, Abuf, m0, r, tid);
        __syncthreads();
        const float* Ag = As + ks * 64 * 32 + tm * 4;
        const float* Wg = Ws + (size_t)(r * 256 + ks * 64) * 32 + tn * 4;
#pragma unroll 8
        for (int i = 0; i < 64; ++i) {
            const ulonglong2 a2 = *(const ulonglong2*)(Ag + i * 32);
            const float4 b4 = *(const float4*)(Wg + i * 32);
            const unsigned long long b0 = pack2(b4.x), b1 = pack2(b4.y),
                                     b2 = pack2(b4.z), b3 = pack2(b4.w);
            fma2(acc[0][0], a2.x, b0); fma2(acc[1][0], a2.y, b0);
            fma2(acc[0][1], a2.x, b1); fma2(acc[1][1], a2.y, b1);
            fma2(acc[0][2], a2.x, b2); fma2(acc[1][2], a2.y, b2);
            fma2(acc[0][3], a2.x, b3); fma2(acc[1][3], a2.y, b3);
        }
        __syncthreads();
    }
#pragma unroll
    for (int i = 0; i < 2; ++i)
#pragma unroll
        for (int j = 0; j < 4; ++j) {
            float lo, hi;
            unpack2(lo, hi, acc[i][j]);
            red[ks * 1024 + (tm * 4 + 2 * i)     * 32 + tn * 4 + j] = lo;
            red[ks * 1024 + (tm * 4 + 2 * i + 1) * 32 + tn * 4 + j] = hi;
        }
    __syncthreads();
}

__device__ __forceinline__ float red4(const float* __restrict__ red, int m, int n)
{
    return red[m * 32 + n] + red[1024 + m * 32 + n] +
           red[2048 + m * 32 + n] + red[3072 + m * 32 + n];
}

// ---------------- z GEMM: red = s(32x512) @ W2s(512x16 [k][n]) -------------
__device__ __forceinline__ void gemmZ(const float* __restrict__ Abuf,
                                      const float* __restrict__ Ws,
                                      float* __restrict__ As,
                                      float* __restrict__ red,
                                      int m0, int tid)
{
    const int ks = tid >> 5, inner = tid & 31;
    const int tm = inner >> 2, tn = inner & 3;
    unsigned long long acc[2][4] = {{0ULL,0ULL,0ULL,0ULL},{0ULL,0ULL,0ULL,0ULL}};

#pragma unroll
    for (int r = 0; r < 2; ++r) {
        stageA(As, Abuf, m0, r, tid);
        __syncthreads();
        const float* Ag = As + ks * 32 * 32 + tm * 4;
        const float* Wg = Ws + (size_t)(r * 256 + ks * 32) * 16 + tn * 4;
#pragma unroll 8
        for (int i = 0; i < 32; ++i) {
            const ulonglong2 a2 = *(const ulonglong2*)(Ag + i * 32);
            const float4 b4 = *(const float4*)(Wg + i * 16);
            const unsigned long long b0 = pack2(b4.x), b1 = pack2(b4.y),
                                     b2 = pack2(b4.z), b3 = pack2(b4.w);
            fma2(acc[0][0], a2.x, b0); fma2(acc[1][0], a2.y, b0);
            fma2(acc[0][1], a2.x, b1); fma2(acc[1][1], a2.y, b1);
            fma2(acc[0][2], a2.x, b2); fma2(acc[1][2], a2.y, b2);
            fma2(acc[0][3], a2.x, b3); fma2(acc[1][3], a2.y, b3);
        }
        __syncthreads();
    }
#pragma unroll
    for (int i = 0; i < 2; ++i)
#pragma unroll
        for (int j = 0; j < 4; ++j) {
            float lo, hi;
            unpack2(lo, hi, acc[i][j]);
            red[ks * 512 + (tm * 4 + 2 * i)     * 16 + tn * 4 + j] = lo;
            red[ks * 512 + (tm * 4 + 2 * i + 1) * 16 + tn * 4 + j] = hi;
        }
    __syncthreads();
}

// ================= decoder filler tiles (run between arrive & wait) ========
// All mutable-buffer reads use __ldcg; weight reads via __ldg (immutable).
// red (4096 f) is dead between GEMMs: zc = red[0:2048], wc = red[2048:4096].

// stage1: hd1[t][m0..+32][nd0..+32] = tanh(z_t @ dw0^T + db0), K=256
__device__ void dec_stage1(int t, int m0, int nd0,
                           const float* __restrict__ zbuf,
                           const float* __restrict__ dw0,
                           const float* __restrict__ db0,
                           float* __restrict__ hd1,
                           float* __restrict__ red, int tid)
{
    float* zc = red;
    float* wc = red + 2048;
    const int m = tid >> 3, jj = (tid & 7) * 4;
    float a0 = __ldg(&db0[nd0 + jj]),     a1 = __ldg(&db0[nd0 + jj + 1]);
    float a2 = __ldg(&db0[nd0 + jj + 2]), a3 = __ldg(&db0[nd0 + jj + 3]);
    const int sr = tid & 31, sq = tid >> 5;
    const float* zrow = zbuf + ((size_t)t * BSZ + m0 + sr) * LATD;
    const float* wrow = dw0 + (size_t)(nd0 + sr) * 256;

    for (int kc = 0; kc < 256; kc += 64) {
        __syncthreads();
#pragma unroll
        for (int it = 0; it < 2; ++it) {
            const int k = (it * 8 + sq) * 4;
            const float4 zv = __ldcg((const float4*)(zrow + kc + k));
            zc[(k + 0) * 32 + sr] = zv.x; zc[(k + 1) * 32 + sr] = zv.y;
            zc[(k + 2) * 32 + sr] = zv.z; zc[(k + 3) * 32 + sr] = zv.w;
            const float4 wv = __ldg((const float4*)(wrow + kc + k));
            wc[(k + 0) * 32 + sr] = wv.x; wc[(k + 1) * 32 + sr] = wv.y;
            wc[(k + 2) * 32 + sr] = wv.z; wc[(k + 3) * 32 + sr] = wv.w;
        }
        __syncthreads();
#pragma unroll 8
        for (int k = 0; k < 64; ++k) {
            const float a = zc[k * 32 + m];
            const float4 w4 = *(const float4*)(wc + k * 32 + jj);
            a0 = fmaf(a, w4.x, a0); a1 = fmaf(a, w4.y, a1);
            a2 = fmaf(a, w4.z, a2); a3 = fmaf(a, w4.w, a3);
        }
    }
    float* o = hd1 + ((size_t)t * BSZ + m0 + m) * 512 + nd0 + jj;
    o[0] = tanhf(a0); o[1] = tanhf(a1); o[2] = tanhf(a2); o[3] = tanhf(a3);
}

// stage2 half: hd2[t][m0..+32][nd0..+32] accumulation over K half (256 each)
__device__ void dec_stage2_half(int t, int m0, int nd0, int half,
                                float* __restrict__ dacc,
                                const float* __restrict__ hd1,
                                const float* __restrict__ dw1,
                                const float* __restrict__ db1,
                                float* __restrict__ hd2,
                                float* __restrict__ red, int tid)
{
    float* ac = red;
    float* wc = red + 2048;
    const int m = tid >> 3, jj = (tid & 7) * 4;
    if (half == 0) {
        dacc[0] = __ldg(&db1[nd0 + jj]);     dacc[1] = __ldg(&db1[nd0 + jj + 1]);
        dacc[2] = __ldg(&db1[nd0 + jj + 2]); dacc[3] = __ldg(&db1[nd0 + jj + 3]);
    }
    const int sr = tid & 31, sq = tid >> 5;
    const float* arow = hd1 + ((size_t)t * BSZ + m0 + sr) * 512 + half * 256;
    const float* wrow = dw1 + (size_t)(nd0 + sr) * 512 + half * 256;

    for (int kc = 0; kc < 256; kc += 64) {
        __syncthreads();
#pragma unroll
        for (int it = 0; it < 2; ++it) {
            const int k = (it * 8 + sq) * 4;
            const float4 av = __ldcg((const float4*)(arow + kc + k));
            ac[(k + 0) * 32 + sr] = av.x; ac[(k + 1) * 32 + sr] = av.y;
            ac[(k + 2) * 32 + sr] = av.z; ac[(k + 3) * 32 + sr] = av.w;
            const float4 wv = __ldg((const float4*)(wrow + kc + k));
            wc[(k + 0) * 32 + sr] = wv.x; wc[(k + 1) * 32 + sr] = wv.y;
            wc[(k + 2) * 32 + sr] = wv.z; wc[(k + 3) * 32 + sr] = wv.w;
        }
        __syncthreads();
#pragma unroll 8
        for (int k = 0; k < 64; ++k) {
            const float a = ac[k * 32 + m];
            const float4 w4 = *(const float4*)(wc + k * 32 + jj);
            dacc[0] = fmaf(a, w4.x, dacc[0]); dacc[1] = fmaf(a, w4.y, dacc[1]);
            dacc[2] = fmaf(a, w4.z, dacc[2]); dacc[3] = fmaf(a, w4.w, dacc[3]);
        }
    }
    if (half == 1) {
        float* o = hd2 + ((size_t)t * BSZ + m0 + m) * 512 + nd0 + jj;
        o[0] = tanhf(dacc[0]); o[1] = tanhf(dacc[1]);
        o[2] = tanhf(dacc[2]); o[3] = tanhf(dacc[3]);
    }
}

// stage3: out[b, s, t] for b=m0..+32, s=jd0..+4; K=512
__device__ void dec_stage3(int t, int m0, int jd0,
                           const float* __restrict__ hd2,
                           const float* __restrict__ dw2,
                           const float* __restrict__ db2,
                           float* __restrict__ out,
                           float* __restrict__ red, int tid)
{
    float* ac = red;
    float* wc = red + 2048;
    const int m = (tid & 127) >> 2, j = tid & 3;
    float acc = (tid < 128) ? __ldg(&db2[jd0 + j]) : 0.f;
    const int sr = tid & 31, sq = tid >> 5;
    const float* arow = hd2 + ((size_t)t * BSZ + m0 + sr) * 512;

    for (int kc = 0; kc < 512; kc += 64) {
        __syncthreads();
#pragma unroll
        for (int it = 0; it < 2; ++it) {
            const int k = (it * 8 + sq) * 4;
            const float4 av = __ldcg((const float4*)(arow + kc + k));
            ac[(k + 0) * 32 + sr] = av.x; ac[(k + 1) * 32 + sr] = av.y;
            ac[(k + 2) * 32 + sr] = av.z; ac[(k + 3) * 32 + sr] = av.w;
        }
        if (tid < 64) {
            const int jr = tid & 3, q = tid >> 2;
            const int k = q * 4;
            const float4 wv = __ldg((const float4*)(dw2 + (size_t)(jd0 + jr) * 512 + kc + k));
            wc[(k + 0) * 4 + jr] = wv.x; wc[(k + 1) * 4 + jr] = wv.y;
            wc[(k + 2) * 4 + jr] = wv.z; wc[(k + 3) * 4 + jr] = wv.w;
        }
        __syncthreads();
        if (tid < 128) {
#pragma unroll 8
            for (int k = 0; k < 64; ++k)
                acc = fmaf(ac[k * 32 + m], wc[k * 4 + j], acc);
        }
    }
    if (tid < 128)
        out[(size_t)(m0 + m) * (SIG * TSTEPS) + (size_t)(jd0 + j) * TSTEPS + t] = acc;
}

// ---------------- persistent ODE kernel (w-space + fused decoder) ----------
__global__ void __launch_bounds__(256, 1) ode_kernel(
    const float* __restrict__ t,
    const float* __restrict__ fw0, const float* __restrict__ fb0,
    const float* __restrict__ fw1, const float* __restrict__ fb1,
    const float* __restrict__ fw2, const float* __restrict__ fb2,
    const float* __restrict__ Gm,  const float* __restrict__ g0,
    const float* __restrict__ dw0, const float* __restrict__ db0,
    const float* __restrict__ dw1, const float* __restrict__ db1,
    const float* __restrict__ dw2, const float* __restrict__ db2,
    float* __restrict__ zbuf, float* __restrict__ h1buf,
    float* __restrict__ h2buf, float* __restrict__ sbuf,
    float* __restrict__ hd1, float* __restrict__ hd2,
    float* __restrict__ out)
{
    extern __shared__ float smem[];
    float* W1s = smem;                 // 512k x 32n = 16384 f (64 KB)
    float* Gs  = W1s + 16384;          // 512k x 32n = 16384 f (64 KB)
    float* W2s = Gs  + 16384;          // 512k x 16n =  8192 f (32 KB)
    float* As  = W2s + 8192;           // 256k x 32m =  8192 f (32 KB)
    float* red = As  + 8192;           //               4096 f (16 KB)
    float* bS  = red + 4096;           // b1(32) | g0(32) | b2(16)

    const int tid = threadIdx.x;
    const int c   = blockIdx.x & 15;   // N-slice 0..15
    const int grp = blockIdx.x >> 4;   // batch group 0..7
    const int m0  = grp * 32;
    const int n0  = c * 16;            // ODE 512-dim slice (16 wide)
    const int nz0 = c * 8;             // unused-width helper (see below)
    (void)nz0;
    const int n0w = c * 32;            // ODE slice is 32 wide in this config
    const int nzw = c * 16;            // z 256-dim slice (16 wide)
    const int nd0 = c * 32;            // decoder 512-dim slice
    const int jd0 = c * 4;             // decoder output-signal slice
    (void)n0;

    // ---- stage weight slices ([k][n]) + biases
    for (int e = tid; e < 32 * 512; e += 256) {
        const int n = e >> 9, k = e & 511;
        W1s[k * 32 + n] = fw1[(size_t)(n0w + n) * 512 + k];
        Gs [k * 32 + n] = Gm [(size_t)(n0w + n) * 512 + k];
    }
    for (int e = tid; e < 16 * 512; e += 256) {
        const int n = e >> 9, k = e & 511;
        W2s[k * 16 + n] = fw2[(size_t)(nzw + n) * 512 + k];
    }
    if (tid < 32)       bS[tid] = fb1[n0w + tid];
    else if (tid < 64)  bS[tid] = g0[n0w + tid - 32];
    else if (tid < 80)  bS[tid] = fb2[nzw + tid - 64];
    __syncthreads();

    // ---- per-thread persistent regs: elem it <-> row (tid>>5)+8*it, col tid&31
    const int mr = tid >> 5;
    const int nn = tid & 31;
    float w[4], u[4] = {0.f, 0.f, 0.f, 0.f}, s[4] = {0.f, 0.f, 0.f, 0.f};

    // ---- init w = W0 @ z0 + b0
    {
        const int m  = tid & 31;
        const int kq = tid >> 5;
        const float* row = zbuf + (size_t)(m0 + m) * 256;
#pragma unroll
        for (int it = 0; it < 8; ++it) {
            const int k = (it * 8 + kq) * 4;
            const float4 v = __ldcg((const float4*)(row + k));
            As[(k + 0) * 32 + m] = v.x; As[(k + 1) * 32 + m] = v.y;
            As[(k + 2) * 32 + m] = v.z; As[(k + 3) * 32 + m] = v.w;
        }
        __syncthreads();
        const float b0v = fb0[n0w + nn];
        float wa[4] = {b0v, b0v, b0v, b0v};
        const float* w0row = fw0 + (size_t)(n0w + nn) * 256;
        for (int l = 0; l < 256; l += 4) {
            const float4 wv = __ldcg((const float4*)(w0row + l));
#pragma unroll
            for (int j = 0; j < 4; ++j) {
                const float wj = (&wv.x)[j];
#pragma unroll
                for (int i = 0; i < 4; ++i)
                    wa[i] = fmaf(As[(l + j) * 32 + mr + 8 * i], wj, wa[i]);
            }
        }
#pragma unroll
        for (int i = 0; i < 4; ++i) w[i] = wa[i];
        __syncthreads();
    }

    unsigned* arr = &g_arr[grp * 32];
    unsigned* gen = &g_gen[grp * 32];
    unsigned lg = 0;
    if (tid == 0)
        asm volatile("ld.acquire.gpu.u32 %0, [%1];" : "=r"(lg) : "l"(gen) : "memory");

    for (int n = 0; n < TSTEPS - 1; ++n) {
        const float hh = __ldg(&t[n + 1]) - __ldg(&t[n]);
        const float h6 = hh * (1.f / 6.f);
        const float* zn = zbuf + (size_t)n * (BSZ * LATD);
        float* znx      = zbuf + (size_t)(n + 1) * (BSZ * LATD);
        float dacc[4];

#pragma unroll 1
        for (int st = 0; st < 4; ++st) {
            const float cc = (st == 0) ? 0.f : ((st == 3) ? hh : 0.5f * hh);
            const float sw = (st == 1 || st == 2) ? 2.f : 1.f;

            if (st > 0) {               // u = G @ h2 + g0
                gemm32(h2buf, Gs, As, red, m0, tid);
#pragma unroll
                for (int it = 0; it < 4; ++it)
                    u[it] = red4(red, mr + 8 * it, nn) + bS[32 + nn];
            }
            // h1 = tanh(w + c*u)
#pragma unroll
            for (int it = 0; it < 4; ++it)
                h1buf[(size_t)(m0 + mr + 8 * it) * 512 + n0w + nn] =
                    tanhf(fmaf(cc, u[it], w[it]));
            gsync(arr, gen, lg);

            // h2 = tanh(W1 @ h1 + b1); s += sw*h2
            gemm32(h1buf, W1s, As, red, m0, tid);
#pragma unroll
            for (int it = 0; it < 4; ++it) {
                const int m = mr + 8 * it;
                float v = red4(red, m, nn) + bS[nn];
                v = tanhf(v);
                s[it] = fmaf(sw, v, s[it]);
                if (st < 3) h2buf[(size_t)(m0 + m) * 512 + n0w + nn] = v;
                else        sbuf [(size_t)(m0 + m) * 512 + n0w + nn] = s[it];
            }
            // split-phase barrier with decoder filler
            gsync_arrive(arr, gen, lg);
            if (st == 0)
                dec_stage1(n, m0, nd0, zbuf, dw0, db0, hd1, red, tid);
            else if (st == 1 && n >= 1)
                dec_stage2_half(n - 1, m0, nd0, 0, dacc, hd1, dw1, db1, hd2, red, tid);
            else if (st == 2 && n >= 1)
                dec_stage2_half(n - 1, m0, nd0, 1, dacc, hd1, dw1, db1, hd2, red, tid);
            else if (st == 3 && n >= 2)
                dec_stage3(n - 2, m0, jd0, hd2, dw2, db2, out, red, tid);
            gsync_wait(gen, lg);
        }

        // ---- end of step: w += (h/6) G s + h g0 ; z_{n+1} = z_n + (h/6) W2 s + h b2
        gemm32(sbuf, Gs, As, red, m0, tid);
#pragma unroll
        for (int it = 0; it < 4; ++it)
            w[it] += h6 * red4(red, mr + 8 * it, nn) + hh * bS[32 + nn];

        gemmZ(sbuf, W2s, As, red, m0, tid);
#pragma unroll
        for (int it = 0; it < 2; ++it) {
            const int e = it * 256 + tid;
            const int m = e >> 4, nz = e & 15;
            float v = 0.f;
#pragma unroll
            for (int q = 0; q < 8; ++q) v += red[q * 512 + m * 16 + nz];
            const size_t idx = (size_t)(m0 + m) * 256 + nzw + nz;
            znx[idx] = __ldcg(zn + idx) + h6 * v + hh * bS[64 + nz];
        }
#pragma unroll
        for (int i = 0; i < 4; ++i) s[i] = 0.f;
    }

    // ---- tail: finish decoder pipeline
    gsync(arr, gen, lg);            // publish z_199
    dec_stage1(TSTEPS - 1, m0, nd0, zbuf, dw0, db0, hd1, red, tid);
    gsync(arr, gen, lg);            // publish hd1_199
    {
        float da[4];
        dec_stage2_half(TSTEPS - 2, m0, nd0, 0, da, hd1, dw1, db1, hd2, red, tid);
        dec_stage2_half(TSTEPS - 2, m0, nd0, 1, da, hd1, dw1, db1, hd2, red, tid);
        dec_stage2_half(TSTEPS - 1, m0, nd0, 0, da, hd1, dw1, db1, hd2, red, tid);
        dec_stage2_half(TSTEPS - 1, m0, nd0, 1, da, hd1, dw1, db1, hd2, red, tid);
    }
    gsync(arr, gen, lg);            // publish hd2_{198,199}
    dec_stage3(TSTEPS - 3, m0, jd0, hd2, dw2, db2, out, red, tid);
    dec_stage3(TSTEPS - 2, m0, jd0, hd2, dw2, db2, out, red, tid);
    dec_stage3(TSTEPS - 1, m0, jd0, hd2, dw2, db2, out, red, tid);
}

// ---------------- G = fw0 @ fw2 precompute (NN GEMM 512x512x256) -----------
__launch_bounds__(256)
__global__ void gemmG_kernel(const float* __restrict__ fw0,
                             const float* __restrict__ fw2,
                             float* __restrict__ G)
{
    __shared__ float As[16][68];
    __shared__ float Bs[16][68];
    const int tid = threadIdx.x;
    const int tx = tid & 15, ty = tid >> 4;
    const int m0 = blockIdx.y * 64, n0 = blockIdx.x * 64;

    float acc[4][4] = {};
    for (int k0 = 0; k0 < 256; k0 += 16) {
        {
            const int ar = tid >> 2, ak = (tid & 3) * 4;
            const float4 av = *(const float4*)(fw0 + (size_t)(m0 + ar) * 256 + k0 + ak);
            As[ak + 0][ar] = av.x; As[ak + 1][ar] = av.y;
            As[ak + 2][ar] = av.z; As[ak + 3][ar] = av.w;
            const int kk = tid >> 4, bn = (tid & 15) * 4;
            const float4 bv = *(const float4*)(fw2 + (size_t)(k0 + kk) * 512 + n0 + bn);
            *(float4*)&Bs[kk][bn] = bv;
        }
        __syncthreads();
#pragma unroll
        for (int k = 0; k < 16; ++k) {
            float a[4], b[4];
#pragma unroll
            for (int i = 0; i < 4; ++i) a[i] = As[k][ty * 4 + i];
#pragma unroll
            for (int j = 0; j < 4; ++j) b[j] = Bs[k][tx * 4 + j];
#pragma unroll
            for (int i = 0; i < 4; ++i)
#pragma unroll
                for (int j = 0; j < 4; ++j) acc[i][j] = fmaf(a[i], b[j], acc[i][j]);
        }
        __syncthreads();
    }
#pragma unroll
    for (int i = 0; i < 4; ++i)
#pragma unroll
        for (int j = 0; j < 4; ++j)
            G[(size_t)(m0 + ty * 4 + i) * 512 + n0 + tx * 4 + j] = acc[i][j];
}

__global__ void g0_kernel(const float* __restrict__ fw0,
                          const float* __restrict__ fb2,
                          float* __restrict__ g0)
{
    const int n = blockIdx.x * 256 + threadIdx.x;
    float acc = 0.f;
    for (int l = 0; l < 256; ++l)
        acc = fmaf(fw0[(size_t)n * 256 + l], fb2[l], acc);
    g0[n] = acc;
}

// ---------------- encoder: fused wcat + im2col gather + GEMM ----------------
template<int G>
__device__ __forceinline__ float gatherA(const float* __restrict__ src, int row, int c)
{
    if (G == 1) {
        const int l = row >> 8, b = row & 255;
        if (c < 192) {
            const int i = c / 3, kk = c - 3 * i, p = l + kk - 1;
            return (p >= 0) ? src[(size_t)b * 65536 + i * 1024 + p] : 0.f;
        }
        return src[(size_t)b * 65536 + (c - 192) * 1024 + l];
    } else if (G == 2) {
        const int l = row >> 8, b = row & 255;
        if (c < 768) {
            const int i = c / 3, kk = c - 3 * i, p = l + kk - 1;
            return (p >= 0) ? src[(size_t)(p * 256 + b) * 256 + i] : 0.f;
        }
        return src[(size_t)(l * 256 + b) * 256 + (c - 768)];
    } else {
        const int b = row;
        if (c < 256)  return src[(size_t)b * 256 + c];
        if (c < 512)  return src[(size_t)(256 + b) * 256 + (c - 256)];
        return src[(size_t)b * 256 + (c - 512)];
    }
}

template<int G>
__device__ __forceinline__ float gatherW(const float* __restrict__ ew,
                                         const float* __restrict__ rw, int o, int c)
{
    if (G == 1) {
        if (c < 192) return ew[o * 192 + c];
        return rw[o * 64 + (c - 192)];
    } else if (G == 2) {
        if (c < 768) return ew[o * 768 + c];
        return rw[o * 256 + (c - 768)];
    } else {
        if (c < 256)  return ew[o * 768 + c * 3 + 1];
        if (c < 512)  return ew[o * 768 + (c - 256) * 3 + 2];
        return rw[o * 256 + (c - 512)];
    }
}

template<int G, int TANH>
__launch_bounds__(256)
__global__ void enc_gemm(const float* __restrict__ Asrc,
                         const float* __restrict__ ew, const float* __restrict__ rw,
                         const float* __restrict__ eb, const float* __restrict__ rb,
                         float* __restrict__ C, int K)
{
    __shared__ float As[32][34];
    __shared__ float Bs[32][34];

    const int tid = threadIdx.x;
    const int tx  = tid & 15;
    const int ty  = tid >> 4;
    const int m0  = blockIdx.y * 32;
    const int n0  = blockIdx.x * 32;

    const int ar = tid >> 3;
    const int ak = (tid & 7) * 4;

    float acc[2][2] = {{0.f, 0.f}, {0.f, 0.f}};

    for (int k0 = 0; k0 < K; k0 += 32) {
#pragma unroll
        for (int j = 0; j < 4; j++) {
            As[ak + j][ar] = gatherA<G>(Asrc, m0 + ar, k0 + ak + j);
            Bs[ak + j][ar] = gatherW<G>(ew, rw, n0 + ar, k0 + ak + j);
        }
        __syncthreads();
#pragma unroll
        for (int k = 0; k < 32; k++) {
            const float a0 = As[k][ty * 2], a1 = As[k][ty * 2 + 1];
            const float b0 = Bs[k][tx * 2], b1 = Bs[k][tx * 2 + 1];
            acc[0][0] = fmaf(a0, b0, acc[0][0]);
            acc[0][1] = fmaf(a0, b1, acc[0][1]);
            acc[1][0] = fmaf(a1, b0, acc[1][0]);
            acc[1][1] = fmaf(a1, b1, acc[1][1]);
        }
        __syncthreads();
    }

#pragma unroll
    for (int i = 0; i < 2; i++) {
        const int m = m0 + ty * 2 + i;
#pragma unroll
        for (int j = 0; j < 2; j++) {
            const int n = n0 + tx * 2 + j;
            float v = acc[i][j] + eb[n] + rb[n];
            if (TANH) v = tanhf(v);
            C[(size_t)m * 256 + n] = v;
        }
    }
}

extern "C" void kernel_launch(void* const* d_in, const int* in_sizes, int n_in,
                              void* d_out, int out_size)
{
    const float* y   = (const float*)d_in[0];
    const float* t   = (const float*)d_in[1];
    const float* ew0 = (const float*)d_in[2];
    const float* eb0 = (const float*)d_in[3];
    const float* rw0 = (const float*)d_in[4];
    const float* rb0 = (const float*)d_in[5];
    const float* ew1 = (const float*)d_in[6];
    const float* eb1 = (const float*)d_in[7];
    const float* rw1 = (const float*)d_in[8];
    const float* rb1 = (const float*)d_in[9];
    const float* ew2 = (const float*)d_in[10];
    const float* eb2 = (const float*)d_in[11];
    const float* rw2 = (const float*)d_in[12];
    const float* rb2 = (const float*)d_in[13];
    const float* fw0 = (const float*)d_in[14];
    const float* fb0 = (const float*)d_in[15];
    const float* fw1 = (const float*)d_in[16];
    const float* fb1 = (const float*)d_in[17];
    const float* fw2 = (const float*)d_in[18];
    const float* fb2 = (const float*)d_in[19];
    const float* dw0 = (const float*)d_in[20];
    const float* db0 = (const float*)d_in[21];
    const float* dw1 = (const float*)d_in[22];
    const float* db1 = (const float*)d_in[23];
    const float* dw2 = (const float*)d_in[24];
    const float* db2 = (const float*)d_in[25];
    float* out = (float*)d_out;

    float *zbuf, *h1, *h2, *sbuf, *Gm, *g0, *x0, *x1, *hd1, *hd2;
    cudaGetSymbolAddress((void**)&zbuf, g_z);
    cudaGetSymbolAddress((void**)&h1,   g_h1);
    cudaGetSymbolAddress((void**)&h2,   g_h2);
    cudaGetSymbolAddress((void**)&sbuf, g_s);
    cudaGetSymbolAddress((void**)&Gm,   g_G);
    cudaGetSymbolAddress((void**)&g0,   g_g0);
    cudaGetSymbolAddress((void**)&x0,   g_x0);
    cudaGetSymbolAddress((void**)&x1,   g_x1);
    cudaGetSymbolAddress((void**)&hd1,  g_hd1);
    cudaGetSymbolAddress((void**)&hd2,  g_hd2);

    // ---------- encoder: 3 fused gather-GEMMs -> z0 ----------
    { dim3 g(8, 24); enc_gemm<1, 1><<<g, 256>>>(y,  ew0, rw0, eb0, rb0, x0, 256);  }
    { dim3 g(8, 16); enc_gemm<2, 1><<<g, 256>>>(x0, ew1, rw1, eb1, rb1, x1, 1024); }
    { dim3 g(8, 8);  enc_gemm<3, 0><<<g, 256>>>(x1, ew2, rw2, eb2, rb2, zbuf, 768);}

    // ---------- precompute G = fw0 @ fw2, g0 = fw0 @ fb2 ----------
    { dim3 g(8, 8); gemmG_kernel<<<g, 256>>>(fw0, fw2, Gm); }
    g0_kernel<<<2, 256>>>(fw0, fb2, g0);

    // ---------- RK4 ODE + fused decoder: one persistent kernel ----------
    const int smem_bytes = (16384 + 16384 + 8192 + 8192 + 4096 + 80) * 4;
    cudaFuncSetAttribute(ode_kernel, cudaFuncAttributeMaxDynamicSharedMemorySize,
                         smem_bytes);
    ode_kernel<<<NBLK, 256, smem_bytes>>>(t, fw0, fb0, fw1, fb1, fw2, fb2,
                                          Gm, g0, dw0, db0, dw1, db1, dw2, db2,
                                          zbuf, h1, h2, sbuf, hd1, hd2, out);
}

// round 13
// speedup vs baseline: 1.3922x; 1.3379x over previous
#include <cuda_runtime.h>
#include <cuda_bf16.h>
#include <math.h>

// Problem dims
#define BSZ   256
#define SIG   64
#define LATD  256
#define ENCH  256
#define DECH  512
#define RHSH  512
#define TSTEPS 200

#define NBLK   128   // persistent ODE grid: 8 groups x 16 CTAs
#define NTHR   512   // 16 warps per CTA
#define GRPSZ  16
#define NGRP   8

// ---------------- scratch (device globals; no allocation) ----------------
__device__ float g_z[TSTEPS * BSZ * LATD];        // pred_z
__device__ float g_h1[BSZ * RHSH];
__device__ float g_h2[BSZ * RHSH];
__device__ float g_s[BSZ * RHSH];                 // RK4 combined h2 sum
__device__ float g_G[RHSH * RHSH];                // G = fw0 @ fw2
__device__ float g_g0[RHSH];                      // g0 = fw0 @ fb2
__device__ float g_x0[3 * BSZ * ENCH];
__device__ float g_x1[2 * BSZ * ENCH];
__device__ float g_hd1[(size_t)TSTEPS * BSZ * DECH];
__device__ float g_hd2[(size_t)TSTEPS * BSZ * DECH];

// per-group barrier state (one L2 line per group)
__device__ unsigned g_arr[NGRP * 32];
__device__ unsigned g_gen[NGRP * 32];

// ---------------- f32x2 packed-FMA helpers ----------------
__device__ __forceinline__ void fma2(unsigned long long& d,
                                     unsigned long long a,
                                     unsigned long long b)
{
    asm("fma.rn.f32x2 %0, %1, %2, %0;" : "+l"(d) : "l"(a), "l"(b));
}
__device__ __forceinline__ unsigned long long pack2(float x)
{
    unsigned long long r;
    asm("mov.b64 %0, {%1, %1};" : "=l"(r) : "f"(x));
    return r;
}
__device__ __forceinline__ void unpack2(float& lo, float& hi, unsigned long long v)
{
    asm("mov.b64 {%0, %1}, %2;" : "=f"(lo), "=f"(hi) : "l"(v));
}

// ---------------- group barrier (16 CTAs) ----------------
__device__ __forceinline__ void gsync(unsigned* arr, unsigned* gen, unsigned& lg)
{
    __syncthreads();
    if (threadIdx.x == 0) {
        unsigned ticket;
        asm volatile("atom.acq_rel.gpu.add.u32 %0, [%1], 1;"
                     : "=r"(ticket) : "l"(arr) : "memory");
        const unsigned target = lg + 1;
        if ((ticket & (GRPSZ - 1)) == GRPSZ - 1) {
            asm volatile("st.release.gpu.u32 [%0], %1;"
                         :: "l"(gen), "r"(target) : "memory");
        } else {
            unsigned g;
            do {
                asm volatile("ld.acquire.gpu.u32 %0, [%1];"
                             : "=r"(g) : "l"(gen) : "memory");
            } while ((int)(g - target) < 0);
        }
        lg = target;
    }
    __syncthreads();
}

// ---------------- one-shot A staging: 32 rows x 512 k into As[k][32] -------
__device__ __forceinline__ void stageA(float* __restrict__ As,
                                       const float* __restrict__ Abuf,
                                       int m0, int tid)
{
    const int m  = tid & 31;
    const int kq = tid >> 5;          // 0..15, 32 k each
    const float* row = Abuf + (size_t)(m0 + m) * 512 + kq * 32;
#pragma unroll
    for (int it = 0; it < 8; ++it) {
        const float4 v = __ldcg((const float4*)(row + it * 4));
        const int k = kq * 32 + it * 4;
        As[(k + 0) * 32 + m] = v.x;
        As[(k + 1) * 32 + m] = v.y;
        As[(k + 2) * 32 + m] = v.z;
        As[(k + 3) * 32 + m] = v.w;
    }
}

// ---------------- core GEMM: red = A(32x512) @ Ws(512x32 [k][n]) ----------
// 512 thr = 8 k-splits x (8tm x 8tn), thread tile 4m x 4n, f32x2 accum.
// Partials in red[8][32][32].  Only 2 __syncthreads per call.
__device__ __forceinline__ void gemm32(const float* __restrict__ Abuf,
                                       const float* __restrict__ Ws,
                                       float* __restrict__ As,
                                       float* __restrict__ red,
                                       int m0, int tid)
{
    stageA(As, Abuf, m0, tid);
    __syncthreads();

    const int ks = tid >> 6, inner = tid & 63;
    const int tm = inner >> 3, tn = inner & 7;
    unsigned long long acc[2][4] = {{0ULL,0ULL,0ULL,0ULL},{0ULL,0ULL,0ULL,0ULL}};

    const float* Ag = As + ks * 64 * 32 + tm * 4;
    const float* Wg = Ws + (size_t)(ks * 64) * 32 + tn * 4;
#pragma unroll 8
    for (int i = 0; i < 64; ++i) {
        const ulonglong2 a2 = *(const ulonglong2*)(Ag + i * 32);
        const float4 b4 = *(const float4*)(Wg + i * 32);
        const unsigned long long b0 = pack2(b4.x), b1 = pack2(b4.y),
                                 b2 = pack2(b4.z), b3 = pack2(b4.w);
        fma2(acc[0][0], a2.x, b0); fma2(acc[1][0], a2.y, b0);
        fma2(acc[0][1], a2.x, b1); fma2(acc[1][1], a2.y, b1);
        fma2(acc[0][2], a2.x, b2); fma2(acc[1][2], a2.y, b2);
        fma2(acc[0][3], a2.x, b3); fma2(acc[1][3], a2.y, b3);
    }

#pragma unroll
    for (int i = 0; i < 2; ++i)
#pragma unroll
        for (int j = 0; j < 4; ++j) {
            float lo, hi;
            unpack2(lo, hi, acc[i][j]);
            red[ks * 1024 + (tm * 4 + 2 * i)     * 32 + tn * 4 + j] = lo;
            red[ks * 1024 + (tm * 4 + 2 * i + 1) * 32 + tn * 4 + j] = hi;
        }
    __syncthreads();
}

__device__ __forceinline__ float red8(const float* __restrict__ red, int m, int n)
{
    float v = 0.f;
#pragma unroll
    for (int q = 0; q < 8; ++q) v += red[q * 1024 + m * 32 + n];
    return v;
}

// ---------------- z GEMM: red = s(32x512) @ W2(512x16), W2 streamed --------
// 512 thr = 16 k-splits x (8tm x 4tn), thread tile 4m x 4n.
__device__ __forceinline__ void gemmZ(const float* __restrict__ Abuf,
                                      const float* __restrict__ fw2, int nzw,
                                      float* __restrict__ As,
                                      float* __restrict__ red,
                                      int m0, int tid)
{
    stageA(As, Abuf, m0, tid);
    __syncthreads();

    const int ks = tid >> 5, lane = tid & 31;   // ks 0..15, 32 k each
    const int tm = lane >> 2, tn = lane & 3;
    unsigned long long acc[2][4] = {{0ULL,0ULL,0ULL,0ULL},{0ULL,0ULL,0ULL,0ULL}};

    const float* w2base = fw2 + (size_t)(nzw + tn * 4) * 512 + ks * 32;
#pragma unroll
    for (int g4 = 0; g4 < 8; ++g4) {
        float4 b[4];
#pragma unroll
        for (int j = 0; j < 4; ++j)
            b[j] = __ldg((const float4*)(w2base + (size_t)j * 512 + g4 * 4));
#pragma unroll
        for (int kk = 0; kk < 4; ++kk) {
            const ulonglong2 a2 =
                *(const ulonglong2*)(As + (ks * 32 + g4 * 4 + kk) * 32 + tm * 4);
#pragma unroll
            for (int j = 0; j < 4; ++j) {
                const unsigned long long bb = pack2(((const float*)&b[j])[kk]);
                fma2(acc[0][j], a2.x, bb);
                fma2(acc[1][j], a2.y, bb);
            }
        }
    }
#pragma unroll
    for (int i = 0; i < 2; ++i)
#pragma unroll
        for (int j = 0; j < 4; ++j) {
            float lo, hi;
            unpack2(lo, hi, acc[i][j]);
            red[ks * 512 + (tm * 4 + 2 * i)     * 16 + tn * 4 + j] = lo;
            red[ks * 512 + (tm * 4 + 2 * i + 1) * 16 + tn * 4 + j] = hi;
        }
    __syncthreads();
}

// ---------------- persistent ODE kernel (w-space, 512 threads) -------------
__global__ void __launch_bounds__(NTHR, 1) ode_kernel(
    const float* __restrict__ t,
    const float* __restrict__ fw0, const float* __restrict__ fb0,
    const float* __restrict__ fw1, const float* __restrict__ fb1,
    const float* __restrict__ fw2, const float* __restrict__ fb2,
    const float* __restrict__ Gm,  const float* __restrict__ g0,
    float* __restrict__ zbuf, float* __restrict__ h1buf,
    float* __restrict__ h2buf, float* __restrict__ sbuf)
{
    extern __shared__ float smem[];
    float* W1s = smem;                 // 512k x 32n = 16384 f (64 KB)
    float* Gs  = W1s + 16384;          // 512k x 32n = 16384 f (64 KB)
    float* As  = Gs  + 16384;          // 512k x 32m = 16384 f (64 KB)
    float* red = As  + 16384;          //               8192 f (32 KB)
    float* bS  = red + 8192;           // b1(32) | g0(32) | b2(16) = 80 f
                                       // total 57424 f = 229696 B

    const int tid = threadIdx.x;
    const int c   = blockIdx.x & 15;   // N-slice 0..15
    const int grp = blockIdx.x >> 4;   // batch group 0..7
    const int m0  = grp * 32;
    const int n0w = c * 32;            // 512-dim slice start
    const int nzw = c * 16;            // 256-dim slice start

    // ---- stage weight slices ([k][n]) + biases
    for (int e = tid; e < 32 * 512; e += NTHR) {
        const int n = e >> 9, k = e & 511;
        W1s[k * 32 + n] = fw1[(size_t)(n0w + n) * 512 + k];
        Gs [k * 32 + n] = Gm [(size_t)(n0w + n) * 512 + k];
    }
    if (tid < 32)       bS[tid] = fb1[n0w + tid];
    else if (tid < 64)  bS[tid] = g0[n0w + tid - 32];
    else if (tid < 80)  bS[tid] = fb2[nzw + tid - 64];
    __syncthreads();

    // ---- per-thread persistent regs: elem it <-> row (tid>>5)+16*it, col tid&31
    const int mr = tid >> 5;           // 0..15
    const int nn = tid & 31;
    float w[2], u[2] = {0.f, 0.f}, s[2] = {0.f, 0.f};

    // ---- init w = W0 @ z0 + b0
    {
        const int m  = tid & 31;
        const int kq = tid >> 5;       // 0..15, 16 k each
        const float* row = zbuf + (size_t)(m0 + m) * 256 + kq * 16;
#pragma unroll
        for (int it = 0; it < 4; ++it) {
            const float4 v = __ldcg((const float4*)(row + it * 4));
            const int k = kq * 16 + it * 4;
            As[(k + 0) * 32 + m] = v.x; As[(k + 1) * 32 + m] = v.y;
            As[(k + 2) * 32 + m] = v.z; As[(k + 3) * 32 + m] = v.w;
        }
        __syncthreads();
        const float b0v = fb0[n0w + nn];
        float wa[2] = {b0v, b0v};
        const float* w0row = fw0 + (size_t)(n0w + nn) * 256;
        for (int l = 0; l < 256; l += 4) {
            const float4 wv = __ldcg((const float4*)(w0row + l));
#pragma unroll
            for (int j = 0; j < 4; ++j) {
                const float wj = (&wv.x)[j];
                wa[0] = fmaf(As[(l + j) * 32 + mr],      wj, wa[0]);
                wa[1] = fmaf(As[(l + j) * 32 + mr + 16], wj, wa[1]);
            }
        }
        w[0] = wa[0]; w[1] = wa[1];
        __syncthreads();
    }

    unsigned* arr = &g_arr[grp * 32];
    unsigned* gen = &g_gen[grp * 32];
    unsigned lg = 0;
    if (tid == 0)
        asm volatile("ld.acquire.gpu.u32 %0, [%1];" : "=r"(lg) : "l"(gen) : "memory");

    for (int n = 0; n < TSTEPS - 1; ++n) {
        const float hh = __ldg(&t[n + 1]) - __ldg(&t[n]);
        const float h6 = hh * (1.f / 6.f);
        const float* zn = zbuf + (size_t)n * (BSZ * LATD);
        float* znx      = zbuf + (size_t)(n + 1) * (BSZ * LATD);

#pragma unroll 1
        for (int st = 0; st < 4; ++st) {
            const float cc = (st == 0) ? 0.f : ((st == 3) ? hh : 0.5f * hh);
            const float sw = (st == 1 || st == 2) ? 2.f : 1.f;

            if (st > 0) {               // u = G @ h2 + g0
                gemm32(h2buf, Gs, As, red, m0, tid);
#pragma unroll
                for (int it = 0; it < 2; ++it)
                    u[it] = red8(red, mr + 16 * it, nn) + bS[32 + nn];
            }
            // h1 = tanh(w + c*u)
#pragma unroll
            for (int it = 0; it < 2; ++it)
                h1buf[(size_t)(m0 + mr + 16 * it) * 512 + n0w + nn] =
                    tanhf(fmaf(cc, u[it], w[it]));
            gsync(arr, gen, lg);

            // h2 = tanh(W1 @ h1 + b1); s += sw*h2
            gemm32(h1buf, W1s, As, red, m0, tid);
#pragma unroll
            for (int it = 0; it < 2; ++it) {
                const int m = mr + 16 * it;
                float v = red8(red, m, nn) + bS[nn];
                v = tanhf(v);
                s[it] = fmaf(sw, v, s[it]);
                if (st < 3) h2buf[(size_t)(m0 + m) * 512 + n0w + nn] = v;
                else        sbuf [(size_t)(m0 + m) * 512 + n0w + nn] = s[it];
            }
            gsync(arr, gen, lg);
        }

        // ---- end of step: w += (h/6) G s + h g0 ; z_{n+1} = z_n + (h/6) W2 s + h b2
        gemm32(sbuf, Gs, As, red, m0, tid);
#pragma unroll
        for (int it = 0; it < 2; ++it)
            w[it] += h6 * red8(red, mr + 16 * it, nn) + hh * bS[32 + nn];

        gemmZ(sbuf, fw2, nzw, As, red, m0, tid);
        {
            const int m = tid >> 4, nz = tid & 15;
            float v = 0.f;
#pragma unroll
            for (int q = 0; q < 16; ++q) v += red[q * 512 + m * 16 + nz];
            const size_t idx = (size_t)(m0 + m) * 256 + nzw + nz;
            znx[idx] = __ldcg(zn + idx) + h6 * v + hh * bS[64 + nz];
        }
        s[0] = 0.f; s[1] = 0.f;
    }
}

// ---------------- G = fw0 @ fw2 precompute (NN GEMM 512x512x256) -----------
__launch_bounds__(256)
__global__ void gemmG_kernel(const float* __restrict__ fw0,
                             const float* __restrict__ fw2,
                             float* __restrict__ G)
{
    __shared__ float As[16][68];
    __shared__ float Bs[16][68];
    const int tid = threadIdx.x;
    const int tx = tid & 15, ty = tid >> 4;
    const int m0 = blockIdx.y * 64, n0 = blockIdx.x * 64;

    float acc[4][4] = {};
    for (int k0 = 0; k0 < 256; k0 += 16) {
        {
            const int ar = tid >> 2, ak = (tid & 3) * 4;
            const float4 av = *(const float4*)(fw0 + (size_t)(m0 + ar) * 256 + k0 + ak);
            As[ak + 0][ar] = av.x; As[ak + 1][ar] = av.y;
            As[ak + 2][ar] = av.z; As[ak + 3][ar] = av.w;
            const int kk = tid >> 4, bn = (tid & 15) * 4;
            const float4 bv = *(const float4*)(fw2 + (size_t)(k0 + kk) * 512 + n0 + bn);
            *(float4*)&Bs[kk][bn] = bv;
        }
        __syncthreads();
#pragma unroll
        for (int k = 0; k < 16; ++k) {
            float a[4], b[4];
#pragma unroll
            for (int i = 0; i < 4; ++i) a[i] = As[k][ty * 4 + i];
#pragma unroll
            for (int j = 0; j < 4; ++j) b[j] = Bs[k][tx * 4 + j];
#pragma unroll
            for (int i = 0; i < 4; ++i)
#pragma unroll
                for (int j = 0; j < 4; ++j) acc[i][j] = fmaf(a[i], b[j], acc[i][j]);
        }
        __syncthreads();
    }
#pragma unroll
    for (int i = 0; i < 4; ++i)
#pragma unroll
        for (int j = 0; j < 4; ++j)
            G[(size_t)(m0 + ty * 4 + i) * 512 + n0 + tx * 4 + j] = acc[i][j];
}

__global__ void g0_kernel(const float* __restrict__ fw0,
                          const float* __restrict__ fb2,
                          float* __restrict__ g0)
{
    const int n = blockIdx.x * 256 + threadIdx.x;
    float acc = 0.f;
    for (int l = 0; l < 256; ++l)
        acc = fmaf(fw0[(size_t)n * 256 + l], fb2[l], acc);
    g0[n] = acc;
}

// ---------------- encoder: fused wcat + im2col gather + GEMM ----------------
template<int G>
__device__ __forceinline__ float gatherA(const float* __restrict__ src, int row, int c)
{
    if (G == 1) {
        const int l = row >> 8, b = row & 255;
        if (c < 192) {
            const int i = c / 3, kk = c - 3 * i, p = l + kk - 1;
            return (p >= 0) ? src[(size_t)b * 65536 + i * 1024 + p] : 0.f;
        }
        return src[(size_t)b * 65536 + (c - 192) * 1024 + l];
    } else if (G == 2) {
        const int l = row >> 8, b = row & 255;
        if (c < 768) {
            const int i = c / 3, kk = c - 3 * i, p = l + kk - 1;
            return (p >= 0) ? src[(size_t)(p * 256 + b) * 256 + i] : 0.f;
        }
        return src[(size_t)(l * 256 + b) * 256 + (c - 768)];
    } else {
        const int b = row;
        if (c < 256)  return src[(size_t)b * 256 + c];
        if (c < 512)  return src[(size_t)(256 + b) * 256 + (c - 256)];
        return src[(size_t)b * 256 + (c - 512)];
    }
}

template<int G>
__device__ __forceinline__ float gatherW(const float* __restrict__ ew,
                                         const float* __restrict__ rw, int o, int c)
{
    if (G == 1) {
        if (c < 192) return ew[o * 192 + c];
        return rw[o * 64 + (c - 192)];
    } else if (G == 2) {
        if (c < 768) return ew[o * 768 + c];
        return rw[o * 256 + (c - 768)];
    } else {
        if (c < 256)  return ew[o * 768 + c * 3 + 1];
        if (c < 512)  return ew[o * 768 + (c - 256) * 3 + 2];
        return rw[o * 256 + (c - 512)];
    }
}

template<int G, int TANH>
__launch_bounds__(256)
__global__ void enc_gemm(const float* __restrict__ Asrc,
                         const float* __restrict__ ew, const float* __restrict__ rw,
                         const float* __restrict__ eb, const float* __restrict__ rb,
                         float* __restrict__ C, int K)
{
    __shared__ float As[32][34];
    __shared__ float Bs[32][34];

    const int tid = threadIdx.x;
    const int tx  = tid & 15;
    const int ty  = tid >> 4;
    const int m0  = blockIdx.y * 32;
    const int n0  = blockIdx.x * 32;

    const int ar = tid >> 3;
    const int ak = (tid & 7) * 4;

    float acc[2][2] = {{0.f, 0.f}, {0.f, 0.f}};

    for (int k0 = 0; k0 < K; k0 += 32) {
#pragma unroll
        for (int j = 0; j < 4; j++) {
            As[ak + j][ar] = gatherA<G>(Asrc, m0 + ar, k0 + ak + j);
            Bs[ak + j][ar] = gatherW<G>(ew, rw, n0 + ar, k0 + ak + j);
        }
        __syncthreads();
#pragma unroll
        for (int k = 0; k < 32; k++) {
            const float a0 = As[k][ty * 2], a1 = As[k][ty * 2 + 1];
            const float b0 = Bs[k][tx * 2], b1 = Bs[k][tx * 2 + 1];
            acc[0][0] = fmaf(a0, b0, acc[0][0]);
            acc[0][1] = fmaf(a0, b1, acc[0][1]);
            acc[1][0] = fmaf(a1, b0, acc[1][0]);
            acc[1][1] = fmaf(a1, b1, acc[1][1]);
        }
        __syncthreads();
    }

#pragma unroll
    for (int i = 0; i < 2; i++) {
        const int m = m0 + ty * 2 + i;
#pragma unroll
        for (int j = 0; j < 2; j++) {
            const int n = n0 + tx * 2 + j;
            float v = acc[i][j] + eb[n] + rb[n];
            if (TANH) v = tanhf(v);
            C[(size_t)m * 256 + n] = v;
        }
    }
}

// ---------------- decoder GEMM: 64x64x16 tile, f32x2 inner ----------------
template<int EPI>
__launch_bounds__(256)
__global__ void dec_gemm(const float* __restrict__ A,
                         const float* __restrict__ W,
                         const float* __restrict__ bias,
                         float* __restrict__ C,
                         int M, int N, int K)
{
    __shared__ float As[16][68];
    __shared__ float Bs[16][68];

    const int tid = threadIdx.x;
    const int tx  = tid & 15;
    const int ty  = tid >> 4;
    const int m0  = blockIdx.y * 64;
    const int n0  = blockIdx.x * 64;

    const int ar = tid >> 2;
    const int ak = (tid & 3) * 4;

    unsigned long long acc2[2][4];
#pragma unroll
    for (int i = 0; i < 2; i++)
#pragma unroll
        for (int j = 0; j < 4; j++) acc2[i][j] = 0ULL;

    const float* Aptr = A + (size_t)(m0 + ar) * K + ak;
    const float* Wptr = W + (size_t)(n0 + ar) * K + ak;

    for (int k0 = 0; k0 < K; k0 += 16) {
        const float4 av = *(const float4*)(Aptr + k0);
        const float4 bv = *(const float4*)(Wptr + k0);
        As[ak + 0][ar] = av.x; As[ak + 1][ar] = av.y;
        As[ak + 2][ar] = av.z; As[ak + 3][ar] = av.w;
        Bs[ak + 0][ar] = bv.x; Bs[ak + 1][ar] = bv.y;
        Bs[ak + 2][ar] = bv.z; Bs[ak + 3][ar] = bv.w;
        __syncthreads();
#pragma unroll
        for (int k = 0; k < 16; k++) {
            const ulonglong2 a2 = *(const ulonglong2*)(&As[k][ty * 4]);
            const float4 b4 = *(const float4*)(&Bs[k][tx * 4]);
            unsigned long long bb[4];
            bb[0] = pack2(b4.x); bb[1] = pack2(b4.y);
            bb[2] = pack2(b4.z); bb[3] = pack2(b4.w);
#pragma unroll
            for (int j = 0; j < 4; j++) {
                fma2(acc2[0][j], a2.x, bb[j]);
                fma2(acc2[1][j], a2.y, bb[j]);
            }
        }
        __syncthreads();
    }

#pragma unroll
    for (int i = 0; i < 2; i++) {
#pragma unroll
        for (int j = 0; j < 4; j++) {
            float lo, hi;
            unpack2(lo, hi, acc2[i][j]);
            const int n = n0 + tx * 4 + j;
            const float bval = bias[n];
#pragma unroll
            for (int half = 0; half < 2; half++) {
                const int m = m0 + ty * 4 + 2 * i + half;
                float v = (half == 0 ? lo : hi) + bval;
                if (EPI == 1) v = tanhf(v);
                if (EPI == 3) {
                    const int tt = m >> 8;
                    const int bb2 = m & 255;
                    C[(size_t)bb2 * (SIG * TSTEPS) + (size_t)n * TSTEPS + tt] = v;
                } else {
                    C[(size_t)m * N + n] = v;
                }
            }
        }
    }
}

extern "C" void kernel_launch(void* const* d_in, const int* in_sizes, int n_in,
                              void* d_out, int out_size)
{
    const float* y   = (const float*)d_in[0];
    const float* t   = (const float*)d_in[1];
    const float* ew0 = (const float*)d_in[2];
    const float* eb0 = (const float*)d_in[3];
    const float* rw0 = (const float*)d_in[4];
    const float* rb0 = (const float*)d_in[5];
    const float* ew1 = (const float*)d_in[6];
    const float* eb1 = (const float*)d_in[7];
    const float* rw1 = (const float*)d_in[8];
    const float* rb1 = (const float*)d_in[9];
    const float* ew2 = (const float*)d_in[10];
    const float* eb2 = (const float*)d_in[11];
    const float* rw2 = (const float*)d_in[12];
    const float* rb2 = (const float*)d_in[13];
    const float* fw0 = (const float*)d_in[14];
    const float* fb0 = (const float*)d_in[15];
    const float* fw1 = (const float*)d_in[16];
    const float* fb1 = (const float*)d_in[17];
    const float* fw2 = (const float*)d_in[18];
    const float* fb2 = (const float*)d_in[19];
    const float* dw0 = (const float*)d_in[20];
    const float* db0 = (const float*)d_in[21];
    const float* dw1 = (const float*)d_in[22];
    const float* db1 = (const float*)d_in[23];
    const float* dw2 = (const float*)d_in[24];
    const float* db2 = (const float*)d_in[25];
    float* out = (float*)d_out;

    float *zbuf, *h1, *h2, *sbuf, *Gm, *g0, *x0, *x1, *hd1, *hd2;
    cudaGetSymbolAddress((void**)&zbuf, g_z);
    cudaGetSymbolAddress((void**)&h1,   g_h1);
    cudaGetSymbolAddress((void**)&h2,   g_h2);
    cudaGetSymbolAddress((void**)&sbuf, g_s);
    cudaGetSymbolAddress((void**)&Gm,   g_G);
    cudaGetSymbolAddress((void**)&g0,   g_g0);
    cudaGetSymbolAddress((void**)&x0,   g_x0);
    cudaGetSymbolAddress((void**)&x1,   g_x1);
    cudaGetSymbolAddress((void**)&hd1,  g_hd1);
    cudaGetSymbolAddress((void**)&hd2,  g_hd2);

    // ---------- precompute G = fw0 @ fw2, g0 = fw0 @ fb2 (launches 1-2) ----
    { dim3 g(8, 8); gemmG_kernel<<<g, 256>>>(fw0, fw2, Gm); }
    g0_kernel<<<2, 256>>>(fw0, fb2, g0);

    // ---------- encoder: 3 fused gather-GEMMs -> z0 (launches 3-5) ----------
    { dim3 g(8, 24); enc_gemm<1, 1><<<g, 256>>>(y,  ew0, rw0, eb0, rb0, x0, 256);  }
    { dim3 g(8, 16); enc_gemm<2, 1><<<g, 256>>>(x0, ew1, rw1, eb1, rb1, x1, 1024); }
    { dim3 g(8, 8);  enc_gemm<3, 0><<<g, 256>>>(x1, ew2, rw2, eb2, rb2, zbuf, 768);}

    // ---------- RK4 ODE: persistent kernel (launch 6 -> ncu -s 5 target) ---
    const int smem_bytes = (16384 + 16384 + 16384 + 8192 + 80) * 4;
    cudaFuncSetAttribute(ode_kernel, cudaFuncAttributeMaxDynamicSharedMemorySize,
                         smem_bytes);
    ode_kernel<<<NBLK, NTHR, smem_bytes>>>(t, fw0, fb0, fw1, fb1, fw2, fb2,
                                           Gm, g0, zbuf, h1, h2, sbuf);

    // ---------- decoder over all 200 states ----------
    { dim3 g(DECH / 64, TSTEPS * BSZ / 64); dec_gemm<1><<<g, 256>>>(zbuf, dw0, db0, hd1, TSTEPS * BSZ, DECH, LATD); }
    { dim3 g(DECH / 64, TSTEPS * BSZ / 64); dec_gemm<1><<<g, 256>>>(hd1,  dw1, db1, hd2, TSTEPS * BSZ, DECH, DECH); }
    { dim3 g(SIG  / 64, TSTEPS * BSZ / 64); dec_gemm<3><<<g, 256>>>(hd2,  dw2, db2, out, TSTEPS * BSZ, SIG,  DECH); }
}

// round 14
// speedup vs baseline: 1.4114x; 1.0138x over previous
#include <cuda_runtime.h>
#include <cuda_bf16.h>
#include <math.h>

// Problem dims
#define BSZ   256
#define SIG   64
#define LATD  256
#define ENCH  256
#define DECH  512
#define RHSH  512
#define TSTEPS 200

#define NBLK   128   // persistent ODE grid: 8 groups x 16 CTAs (R7 config)
#define GRPSZ  16
#define NGRP   8

// ---------------- scratch (device globals; no allocation) ----------------
__device__ float g_z[TSTEPS * BSZ * LATD];        // pred_z
__device__ float g_h1[BSZ * RHSH];
__device__ float g_h2[BSZ * RHSH];
__device__ float g_s[BSZ * RHSH];                 // RK4 combined h2 sum
__device__ float g_G[RHSH * RHSH];                // G = fw0 @ fw2
__device__ float g_g0[RHSH];                      // g0 = fw0 @ fb2
__device__ float g_x0[3 * BSZ * ENCH];
__device__ float g_x1[2 * BSZ * ENCH];
__device__ float g_hd1[(size_t)TSTEPS * BSZ * DECH];
__device__ float g_hd2[(size_t)TSTEPS * BSZ * DECH];

// per-group barrier state (one L2 line per group)
__device__ unsigned g_arr[NGRP * 32];
__device__ unsigned g_gen[NGRP * 32];

// ---------------- f32x2 packed-FMA helpers ----------------
__device__ __forceinline__ void fma2(unsigned long long& d,
                                     unsigned long long a,
                                     unsigned long long b)
{
    asm("fma.rn.f32x2 %0, %1, %2, %0;" : "+l"(d) : "l"(a), "l"(b));
}
__device__ __forceinline__ unsigned long long pack2(float x)
{
    unsigned long long r;
    asm("mov.b64 %0, {%1, %1};" : "=l"(r) : "f"(x));
    return r;
}
__device__ __forceinline__ void unpack2(float& lo, float& hi, unsigned long long v)
{
    asm("mov.b64 {%0, %1}, %2;" : "=f"(lo), "=f"(hi) : "l"(v));
}

// ---------------- group barrier (16 CTAs) ----------------
__device__ __forceinline__ void gsync(unsigned* arr, unsigned* gen, unsigned& lg)
{
    __syncthreads();
    if (threadIdx.x == 0) {
        unsigned ticket;
        asm volatile("atom.acq_rel.gpu.add.u32 %0, [%1], 1;"
                     : "=r"(ticket) : "l"(arr) : "memory");
        const unsigned target = lg + 1;
        if ((ticket & (GRPSZ - 1)) == GRPSZ - 1) {
            asm volatile("st.release.gpu.u32 [%0], %1;"
                         :: "l"(gen), "r"(target) : "memory");
        } else {
            unsigned g;
            do {
                asm volatile("ld.acquire.gpu.u32 %0, [%1];"
                             : "=r"(g) : "l"(gen) : "memory");
            } while ((int)(g - target) < 0);
        }
        lg = target;
    }
    __syncthreads();
}

// ---------------- A staging: 32 rows x 256-k chunk (row stride 512) --------
__device__ __forceinline__ void stageA(float* __restrict__ As,
                                       const float* __restrict__ Abuf,
                                       int m0, int r, int tid)
{
    const int m  = tid & 31;
    const int kq = tid >> 5;
    const float* row = Abuf + (size_t)(m0 + m) * 512 + r * 256;
#pragma unroll
    for (int it = 0; it < 8; ++it) {
        const int k = (it * 8 + kq) * 4;
        const float4 v = __ldcg((const float4*)(row + k));
        As[(k + 0) * 32 + m] = v.x;
        As[(k + 1) * 32 + m] = v.y;
        As[(k + 2) * 32 + m] = v.z;
        As[(k + 3) * 32 + m] = v.w;
    }
}

// ---------------- core GEMM: red = A(32x512) @ Ws(512x32 [k][n]) ----------
__device__ __forceinline__ void gemm32(const float* __restrict__ Abuf,
                                       const float* __restrict__ Ws,
                                       float* __restrict__ As,
                                       float* __restrict__ red,
                                       int m0, int tid)
{
    const int ks = tid >> 6, inner = tid & 63;
    const int tm = inner >> 3, tn = inner & 7;
    unsigned long long acc[2][4] = {{0ULL,0ULL,0ULL,0ULL},{0ULL,0ULL,0ULL,0ULL}};

#pragma unroll
    for (int r = 0; r < 2; ++r) {
        stageA(As, Abuf, m0, r, tid);
        __syncthreads();
        const float* Ag = As + ks * 64 * 32 + tm * 4;
        const float* Wg = Ws + (size_t)(r * 256 + ks * 64) * 32 + tn * 4;
#pragma unroll 8
        for (int i = 0; i < 64; ++i) {
            const ulonglong2 a2 = *(const ulonglong2*)(Ag + i * 32);
            const float4 b4 = *(const float4*)(Wg + i * 32);
            const unsigned long long b0 = pack2(b4.x), b1 = pack2(b4.y),
                                     b2 = pack2(b4.z), b3 = pack2(b4.w);
            fma2(acc[0][0], a2.x, b0); fma2(acc[1][0], a2.y, b0);
            fma2(acc[0][1], a2.x, b1); fma2(acc[1][1], a2.y, b1);
            fma2(acc[0][2], a2.x, b2); fma2(acc[1][2], a2.y, b2);
            fma2(acc[0][3], a2.x, b3); fma2(acc[1][3], a2.y, b3);
        }
        __syncthreads();
    }
#pragma unroll
    for (int i = 0; i < 2; ++i)
#pragma unroll
        for (int j = 0; j < 4; ++j) {
            float lo, hi;
            unpack2(lo, hi, acc[i][j]);
            red[ks * 1024 + (tm * 4 + 2 * i)     * 32 + tn * 4 + j] = lo;
            red[ks * 1024 + (tm * 4 + 2 * i + 1) * 32 + tn * 4 + j] = hi;
        }
    __syncthreads();
}

__device__ __forceinline__ float red4(const float* __restrict__ red, int m, int n)
{
    return red[m * 32 + n] + red[1024 + m * 32 + n] +
           red[2048 + m * 32 + n] + red[3072 + m * 32 + n];
}

// ---------------- z GEMM: red = s(32x512) @ W2s(512x16 [k][n]) -------------
__device__ __forceinline__ void gemmZ(const float* __restrict__ Abuf,
                                      const float* __restrict__ Ws,
                                      float* __restrict__ As,
                                      float* __restrict__ red,
                                      int m0, int tid)
{
    const int ks = tid >> 5, inner = tid & 31;
    const int tm = inner >> 2, tn = inner & 3;
    unsigned long long acc[2][4] = {{0ULL,0ULL,0ULL,0ULL},{0ULL,0ULL,0ULL,0ULL}};

#pragma unroll
    for (int r = 0; r < 2; ++r) {
        stageA(As, Abuf, m0, r, tid);
        __syncthreads();
        const float* Ag = As + ks * 32 * 32 + tm * 4;
        const float* Wg = Ws + (size_t)(r * 256 + ks * 32) * 16 + tn * 4;
#pragma unroll 8
        for (int i = 0; i < 32; ++i) {
            const ulonglong2 a2 = *(const ulonglong2*)(Ag + i * 32);
            const float4 b4 = *(const float4*)(Wg + i * 16);
            const unsigned long long b0 = pack2(b4.x), b1 = pack2(b4.y),
                                     b2 = pack2(b4.z), b3 = pack2(b4.w);
            fma2(acc[0][0], a2.x, b0); fma2(acc[1][0], a2.y, b0);
            fma2(acc[0][1], a2.x, b1); fma2(acc[1][1], a2.y, b1);
            fma2(acc[0][2], a2.x, b2); fma2(acc[1][2], a2.y, b2);
            fma2(acc[0][3], a2.x, b3); fma2(acc[1][3], a2.y, b3);
        }
        __syncthreads();
    }
#pragma unroll
    for (int i = 0; i < 2; ++i)
#pragma unroll
        for (int j = 0; j < 4; ++j) {
            float lo, hi;
            unpack2(lo, hi, acc[i][j]);
            red[ks * 512 + (tm * 4 + 2 * i)     * 16 + tn * 4 + j] = lo;
            red[ks * 512 + (tm * 4 + 2 * i + 1) * 16 + tn * 4 + j] = hi;
        }
    __syncthreads();
}

// ---------------- persistent ODE kernel (w-space, R7 config) ---------------
__global__ void __launch_bounds__(256, 1) ode_kernel(
    const float* __restrict__ t,
    const float* __restrict__ fw0, const float* __restrict__ fb0,
    const float* __restrict__ fw1, const float* __restrict__ fb1,
    const float* __restrict__ fw2, const float* __restrict__ fb2,
    const float* __restrict__ Gm,  const float* __restrict__ g0,
    float* __restrict__ zbuf, float* __restrict__ h1buf,
    float* __restrict__ h2buf, float* __restrict__ sbuf)
{
    extern __shared__ float smem[];
    float* W1s = smem;                 // 512k x 32n = 16384 f (64 KB)
    float* Gs  = W1s + 16384;          // 512k x 32n = 16384 f (64 KB)
    float* W2s = Gs  + 16384;          // 512k x 16n =  8192 f (32 KB)
    float* As  = W2s + 8192;           // 256k x 32m =  8192 f (32 KB)
    float* red = As  + 8192;           //               4096 f (16 KB)
    float* bS  = red + 4096;           // b1(32) | g0(32) | b2(16) = 80 f

    const int tid = threadIdx.x;
    const int c   = blockIdx.x & 15;   // N-slice 0..15
    const int grp = blockIdx.x >> 4;   // batch group 0..7
    const int m0  = grp * 32;
    const int n0w = c * 32;            // 512-dim slice start
    const int nzw = c * 16;            // 256-dim slice start

    // ---- stage weight slices ([k][n]) + biases
    for (int e = tid; e < 32 * 512; e += 256) {
        const int n = e >> 9, k = e & 511;
        W1s[k * 32 + n] = fw1[(size_t)(n0w + n) * 512 + k];
        Gs [k * 32 + n] = Gm [(size_t)(n0w + n) * 512 + k];
    }
    for (int e = tid; e < 16 * 512; e += 256) {
        const int n = e >> 9, k = e & 511;
        W2s[k * 16 + n] = fw2[(size_t)(nzw + n) * 512 + k];
    }
    if (tid < 32)       bS[tid] = fb1[n0w + tid];
    else if (tid < 64)  bS[tid] = g0[n0w + tid - 32];
    else if (tid < 80)  bS[tid] = fb2[nzw + tid - 64];
    __syncthreads();

    // ---- per-thread persistent regs: elem it <-> row (tid>>5)+8*it, col tid&31
    const int mr = tid >> 5;
    const int nn = tid & 31;
    float w[4], u[4] = {0.f, 0.f, 0.f, 0.f}, s[4] = {0.f, 0.f, 0.f, 0.f};

    // ---- init w = W0 @ z0 + b0
    {
        const int m  = tid & 31;
        const int kq = tid >> 5;
        const float* row = zbuf + (size_t)(m0 + m) * 256;
#pragma unroll
        for (int it = 0; it < 8; ++it) {
            const int k = (it * 8 + kq) * 4;
            const float4 v = __ldcg((const float4*)(row + k));
            As[(k + 0) * 32 + m] = v.x; As[(k + 1) * 32 + m] = v.y;
            As[(k + 2) * 32 + m] = v.z; As[(k + 3) * 32 + m] = v.w;
        }
        __syncthreads();
        const float b0v = fb0[n0w + nn];
        float wa[4] = {b0v, b0v, b0v, b0v};
        const float* w0row = fw0 + (size_t)(n0w + nn) * 256;
        for (int l = 0; l < 256; l += 4) {
            const float4 wv = __ldcg((const float4*)(w0row + l));
#pragma unroll
            for (int j = 0; j < 4; ++j) {
                const float wj = (&wv.x)[j];
#pragma unroll
                for (int i = 0; i < 4; ++i)
                    wa[i] = fmaf(As[(l + j) * 32 + mr + 8 * i], wj, wa[i]);
            }
        }
#pragma unroll
        for (int i = 0; i < 4; ++i) w[i] = wa[i];
        __syncthreads();
    }

    unsigned* arr = &g_arr[grp * 32];
    unsigned* gen = &g_gen[grp * 32];
    unsigned lg = 0;
    if (tid == 0)
        asm volatile("ld.acquire.gpu.u32 %0, [%1];" : "=r"(lg) : "l"(gen) : "memory");

    for (int n = 0; n < TSTEPS - 1; ++n) {
        const float hh = __ldg(&t[n + 1]) - __ldg(&t[n]);
        const float h6 = hh * (1.f / 6.f);
        const float* zn = zbuf + (size_t)n * (BSZ * LATD);
        float* znx      = zbuf + (size_t)(n + 1) * (BSZ * LATD);

#pragma unroll 1
        for (int st = 0; st < 4; ++st) {
            const float cc = (st == 0) ? 0.f : ((st == 3) ? hh : 0.5f * hh);
            const float sw = (st == 1 || st == 2) ? 2.f : 1.f;

            if (st > 0) {               // u = G @ h2 + g0
                gemm32(h2buf, Gs, As, red, m0, tid);
#pragma unroll
                for (int it = 0; it < 4; ++it)
                    u[it] = red4(red, mr + 8 * it, nn) + bS[32 + nn];
            }
            // h1 = tanh(w + c*u)
#pragma unroll
            for (int it = 0; it < 4; ++it)
                h1buf[(size_t)(m0 + mr + 8 * it) * 512 + n0w + nn] =
                    tanhf(fmaf(cc, u[it], w[it]));
            gsync(arr, gen, lg);

            // h2 = tanh(W1 @ h1 + b1); s += sw*h2
            gemm32(h1buf, W1s, As, red, m0, tid);
#pragma unroll
            for (int it = 0; it < 4; ++it) {
                const int m = mr + 8 * it;
                float v = red4(red, m, nn) + bS[nn];
                v = tanhf(v);
                s[it] = fmaf(sw, v, s[it]);
                if (st < 3) h2buf[(size_t)(m0 + m) * 512 + n0w + nn] = v;
                else        sbuf [(size_t)(m0 + m) * 512 + n0w + nn] = s[it];
            }
            gsync(arr, gen, lg);
        }

        // ---- end of step: w += (h/6) G s + h g0 ; z_{n+1} = z_n + (h/6) W2 s + h b2
        gemm32(sbuf, Gs, As, red, m0, tid);
#pragma unroll
        for (int it = 0; it < 4; ++it)
            w[it] += h6 * red4(red, mr + 8 * it, nn) + hh * bS[32 + nn];

        gemmZ(sbuf, W2s, As, red, m0, tid);
#pragma unroll
        for (int it = 0; it < 2; ++it) {
            const int e = it * 256 + tid;
            const int m = e >> 4, nz = e & 15;
            float v = 0.f;
#pragma unroll
            for (int q = 0; q < 8; ++q) v += red[q * 512 + m * 16 + nz];
            const size_t idx = (size_t)(m0 + m) * 256 + nzw + nz;
            znx[idx] = __ldcg(zn + idx) + h6 * v + hh * bS[64 + nz];
        }
#pragma unroll
        for (int i = 0; i < 4; ++i) s[i] = 0.f;
    }
}

// ---------------- G = fw0 @ fw2 precompute (NN GEMM 512x512x256) -----------
__launch_bounds__(256)
__global__ void gemmG_kernel(const float* __restrict__ fw0,
                             const float* __restrict__ fw2,
                             float* __restrict__ G)
{
    __shared__ float As[16][68];
    __shared__ float Bs[16][68];
    const int tid = threadIdx.x;
    const int tx = tid & 15, ty = tid >> 4;
    const int m0 = blockIdx.y * 64, n0 = blockIdx.x * 64;

    float acc[4][4] = {};
    for (int k0 = 0; k0 < 256; k0 += 16) {
        {
            const int ar = tid >> 2, ak = (tid & 3) * 4;
            const float4 av = *(const float4*)(fw0 + (size_t)(m0 + ar) * 256 + k0 + ak);
            As[ak + 0][ar] = av.x; As[ak + 1][ar] = av.y;
            As[ak + 2][ar] = av.z; As[ak + 3][ar] = av.w;
            const int kk = tid >> 4, bn = (tid & 15) * 4;
            const float4 bv = *(const float4*)(fw2 + (size_t)(k0 + kk) * 512 + n0 + bn);
            *(float4*)&Bs[kk][bn] = bv;
        }
        __syncthreads();
#pragma unroll
        for (int k = 0; k < 16; ++k) {
            float a[4], b[4];
#pragma unroll
            for (int i = 0; i < 4; ++i) a[i] = As[k][ty * 4 + i];
#pragma unroll
            for (int j = 0; j < 4; ++j) b[j] = Bs[k][tx * 4 + j];
#pragma unroll
            for (int i = 0; i < 4; ++i)
#pragma unroll
                for (int j = 0; j < 4; ++j) acc[i][j] = fmaf(a[i], b[j], acc[i][j]);
        }
        __syncthreads();
    }
#pragma unroll
    for (int i = 0; i < 4; ++i)
#pragma unroll
        for (int j = 0; j < 4; ++j)
            G[(size_t)(m0 + ty * 4 + i) * 512 + n0 + tx * 4 + j] = acc[i][j];
}

__global__ void g0_kernel(const float* __restrict__ fw0,
                          const float* __restrict__ fb2,
                          float* __restrict__ g0)
{
    const int n = blockIdx.x * 256 + threadIdx.x;
    float acc = 0.f;
    for (int l = 0; l < 256; ++l)
        acc = fmaf(fw0[(size_t)n * 256 + l], fb2[l], acc);
    g0[n] = acc;
}

// ---------------- encoder: fused wcat + im2col gather + GEMM ----------------
template<int G>
__device__ __forceinline__ float gatherA(const float* __restrict__ src, int row, int c)
{
    if (G == 1) {
        const int l = row >> 8, b = row & 255;
        if (c < 192) {
            const int i = c / 3, kk = c - 3 * i, p = l + kk - 1;
            return (p >= 0) ? src[(size_t)b * 65536 + i * 1024 + p] : 0.f;
        }
        return src[(size_t)b * 65536 + (c - 192) * 1024 + l];
    } else if (G == 2) {
        const int l = row >> 8, b = row & 255;
        if (c < 768) {
            const int i = c / 3, kk = c - 3 * i, p = l + kk - 1;
            return (p >= 0) ? src[(size_t)(p * 256 + b) * 256 + i] : 0.f;
        }
        return src[(size_t)(l * 256 + b) * 256 + (c - 768)];
    } else {
        const int b = row;
        if (c < 256)  return src[(size_t)b * 256 + c];
        if (c < 512)  return src[(size_t)(256 + b) * 256 + (c - 256)];
        return src[(size_t)b * 256 + (c - 512)];
    }
}

template<int G>
__device__ __forceinline__ float gatherW(const float* __restrict__ ew,
                                         const float* __restrict__ rw, int o, int c)
{
    if (G == 1) {
        if (c < 192) return ew[o * 192 + c];
        return rw[o * 64 + (c - 192)];
    } else if (G == 2) {
        if (c < 768) return ew[o * 768 + c];
        return rw[o * 256 + (c - 768)];
    } else {
        if (c < 256)  return ew[o * 768 + c * 3 + 1];
        if (c < 512)  return ew[o * 768 + (c - 256) * 3 + 2];
        return rw[o * 256 + (c - 512)];
    }
}

template<int G, int TANH>
__launch_bounds__(256)
__global__ void enc_gemm(const float* __restrict__ Asrc,
                         const float* __restrict__ ew, const float* __restrict__ rw,
                         const float* __restrict__ eb, const float* __restrict__ rb,
                         float* __restrict__ C, int K)
{
    __shared__ float As[32][34];
    __shared__ float Bs[32][34];

    const int tid = threadIdx.x;
    const int tx  = tid & 15;
    const int ty  = tid >> 4;
    const int m0  = blockIdx.y * 32;
    const int n0  = blockIdx.x * 32;

    const int ar = tid >> 3;
    const int ak = (tid & 7) * 4;

    float acc[2][2] = {{0.f, 0.f}, {0.f, 0.f}};

    for (int k0 = 0; k0 < K; k0 += 32) {
#pragma unroll
        for (int j = 0; j < 4; j++) {
            As[ak + j][ar] = gatherA<G>(Asrc, m0 + ar, k0 + ak + j);
            Bs[ak + j][ar] = gatherW<G>(ew, rw, n0 + ar, k0 + ak + j);
        }
        __syncthreads();
#pragma unroll
        for (int k = 0; k < 32; k++) {
            const float a0 = As[k][ty * 2], a1 = As[k][ty * 2 + 1];
            const float b0 = Bs[k][tx * 2], b1 = Bs[k][tx * 2 + 1];
            acc[0][0] = fmaf(a0, b0, acc[0][0]);
            acc[0][1] = fmaf(a0, b1, acc[0][1]);
            acc[1][0] = fmaf(a1, b0, acc[1][0]);
            acc[1][1] = fmaf(a1, b1, acc[1][1]);
        }
        __syncthreads();
    }

#pragma unroll
    for (int i = 0; i < 2; i++) {
        const int m = m0 + ty * 2 + i;
#pragma unroll
        for (int j = 0; j < 2; j++) {
            const int n = n0 + tx * 2 + j;
            float v = acc[i][j] + eb[n] + rb[n];
            if (TANH) v = tanhf(v);
            C[(size_t)m * 256 + n] = v;
        }
    }
}

// ---------------- decoder GEMM: 128x64x32, double-buffered, 8x4 tiles ------
// EPI: 1 = bias+tanh, 3 = bias + transposed store into (B,SIG,T)
template<int EPI>
__launch_bounds__(256, 2)
__global__ void dec_gemm(const float* __restrict__ A,
                         const float* __restrict__ W,
                         const float* __restrict__ bias,
                         float* __restrict__ C,
                         int M, int N, int K)
{
    __shared__ float As[2][32][128];   // [buf][k][m]
    __shared__ float Bs[2][32][64];    // [buf][k][n]   (48 KB total)

    const int tid = threadIdx.x;
    const int tx  = tid & 15;          // 4 n-cols each
    const int ty  = tid >> 4;          // 8 m-rows each
    const int m0  = blockIdx.y * 128;
    const int n0  = blockIdx.x * 64;

    // loader mapping
    const int ar  = tid & 127;         // A row
    const int akh = (tid >> 7) * 16;   // A k-half (16 wide, 4 float4)
    const int br  = tid & 63;          // B row (n)
    const int bkh = (tid >> 6) * 8;    // B k-eighth (8 wide, 2 float4)

    const float* Arow = A + (size_t)(m0 + ar) * K + akh;
    const float* Wrow = W + (size_t)(n0 + br) * K + bkh;

    unsigned long long acc[4][4];
#pragma unroll
    for (int p = 0; p < 4; ++p)
#pragma unroll
        for (int j = 0; j < 4; ++j) acc[p][j] = 0ULL;

    float4 pa[4], pb[2];
    // prologue: load chunk 0
#pragma unroll
    for (int q = 0; q < 4; ++q) pa[q] = *(const float4*)(Arow + q * 4);
#pragma unroll
    for (int q = 0; q < 2; ++q) pb[q] = *(const float4*)(Wrow + q * 4);
#pragma unroll
    for (int q = 0; q < 4; ++q) {
        const int k = akh + q * 4;
        As[0][k + 0][ar] = pa[q].x; As[0][k + 1][ar] = pa[q].y;
        As[0][k + 2][ar] = pa[q].z; As[0][k + 3][ar] = pa[q].w;
    }
#pragma unroll
    for (int q = 0; q < 2; ++q) {
        const int k = bkh + q * 4;
        Bs[0][k + 0][br] = pb[q].x; Bs[0][k + 1][br] = pb[q].y;
        Bs[0][k + 2][br] = pb[q].z; Bs[0][k + 3][br] = pb[q].w;
    }
    __syncthreads();

    const int nch = K >> 5;
    for (int c = 0; c < nch; ++c) {
        const int buf = c & 1;
        if (c + 1 < nch) {             // prefetch next chunk into registers
            const int kc = (c + 1) << 5;
#pragma unroll
            for (int q = 0; q < 4; ++q) pa[q] = *(const float4*)(Arow + kc + q * 4);
#pragma unroll
            for (int q = 0; q < 2; ++q) pb[q] = *(const float4*)(Wrow + kc + q * 4);
        }
#pragma unroll 8
        for (int k = 0; k < 32; ++k) {
            const ulonglong2 a01 = *(const ulonglong2*)&As[buf][k][ty * 8];
            const ulonglong2 a23 = *(const ulonglong2*)&As[buf][k][ty * 8 + 4];
            const float4 b4 = *(const float4*)&Bs[buf][k][tx * 4];
            const unsigned long long b0 = pack2(b4.x), b1 = pack2(b4.y),
                                     b2 = pack2(b4.z), b3 = pack2(b4.w);
            fma2(acc[0][0], a01.x, b0); fma2(acc[1][0], a01.y, b0);
            fma2(acc[2][0], a23.x, b0); fma2(acc[3][0], a23.y, b0);
            fma2(acc[0][1], a01.x, b1); fma2(acc[1][1], a01.y, b1);
            fma2(acc[2][1], a23.x, b1); fma2(acc[3][1], a23.y, b1);
            fma2(acc[0][2], a01.x, b2); fma2(acc[1][2], a01.y, b2);
            fma2(acc[2][2], a23.x, b2); fma2(acc[3][2], a23.y, b2);
            fma2(acc[0][3], a01.x, b3); fma2(acc[1][3], a01.y, b3);
            fma2(acc[2][3], a23.x, b3); fma2(acc[3][3], a23.y, b3);
        }
        if (c + 1 < nch) {
            const int nb = 1 - buf;
#pragma unroll
            for (int q = 0; q < 4; ++q) {
                const int k = akh + q * 4;
                As[nb][k + 0][ar] = pa[q].x; As[nb][k + 1][ar] = pa[q].y;
                As[nb][k + 2][ar] = pa[q].z; As[nb][k + 3][ar] = pa[q].w;
            }
#pragma unroll
            for (int q = 0; q < 2; ++q) {
                const int k = bkh + q * 4;
                Bs[nb][k + 0][br] = pb[q].x; Bs[nb][k + 1][br] = pb[q].y;
                Bs[nb][k + 2][br] = pb[q].z; Bs[nb][k + 3][br] = pb[q].w;
            }
            __syncthreads();
        }
    }

    // epilogue
#pragma unroll
    for (int j = 0; j < 4; ++j) {
        const int n = n0 + tx * 4 + j;
        const float bval = __ldg(&bias[n]);
#pragma unroll
        for (int p = 0; p < 4; ++p) {
            float lo, hi;
            unpack2(lo, hi, acc[p][j]);
#pragma unroll
            for (int half = 0; half < 2; ++half) {
                const int m = m0 + ty * 8 + 2 * p + half;
                float v = (half == 0 ? lo : hi) + bval;
                if (EPI == 1) v = tanhf(v);
                if (EPI == 3) {
                    const int tt = m >> 8;
                    const int bb = m & 255;
                    C[(size_t)bb * (SIG * TSTEPS) + (size_t)n * TSTEPS + tt] = v;
                } else {
                    C[(size_t)m * N + n] = v;
                }
            }
        }
    }
}

extern "C" void kernel_launch(void* const* d_in, const int* in_sizes, int n_in,
                              void* d_out, int out_size)
{
    const float* y   = (const float*)d_in[0];
    const float* t   = (const float*)d_in[1];
    const float* ew0 = (const float*)d_in[2];
    const float* eb0 = (const float*)d_in[3];
    const float* rw0 = (const float*)d_in[4];
    const float* rb0 = (const float*)d_in[5];
    const float* ew1 = (const float*)d_in[6];
    const float* eb1 = (const float*)d_in[7];
    const float* rw1 = (const float*)d_in[8];
    const float* rb1 = (const float*)d_in[9];
    const float* ew2 = (const float*)d_in[10];
    const float* eb2 = (const float*)d_in[11];
    const float* rw2 = (const float*)d_in[12];
    const float* rb2 = (const float*)d_in[13];
    const float* fw0 = (const float*)d_in[14];
    const float* fb0 = (const float*)d_in[15];
    const float* fw1 = (const float*)d_in[16];
    const float* fb1 = (const float*)d_in[17];
    const float* fw2 = (const float*)d_in[18];
    const float* fb2 = (const float*)d_in[19];
    const float* dw0 = (const float*)d_in[20];
    const float* db0 = (const float*)d_in[21];
    const float* dw1 = (const float*)d_in[22];
    const float* db1 = (const float*)d_in[23];
    const float* dw2 = (const float*)d_in[24];
    const float* db2 = (const float*)d_in[25];
    float* out = (float*)d_out;

    float *zbuf, *h1, *h2, *sbuf, *Gm, *g0, *x0, *x1, *hd1, *hd2;
    cudaGetSymbolAddress((void**)&zbuf, g_z);
    cudaGetSymbolAddress((void**)&h1,   g_h1);
    cudaGetSymbolAddress((void**)&h2,   g_h2);
    cudaGetSymbolAddress((void**)&sbuf, g_s);
    cudaGetSymbolAddress((void**)&Gm,   g_G);
    cudaGetSymbolAddress((void**)&g0,   g_g0);
    cudaGetSymbolAddress((void**)&x0,   g_x0);
    cudaGetSymbolAddress((void**)&x1,   g_x1);
    cudaGetSymbolAddress((void**)&hd1,  g_hd1);
    cudaGetSymbolAddress((void**)&hd2,  g_hd2);

    // ---------- precompute G = fw0 @ fw2, g0 = fw0 @ fb2 (launches 1-2) ----
    { dim3 g(8, 8); gemmG_kernel<<<g, 256>>>(fw0, fw2, Gm); }
    g0_kernel<<<2, 256>>>(fw0, fb2, g0);

    // ---------- encoder: 3 fused gather-GEMMs -> z0 (launches 3-5) ---------
    { dim3 g(8, 24); enc_gemm<1, 1><<<g, 256>>>(y,  ew0, rw0, eb0, rb0, x0, 256);  }
    { dim3 g(8, 16); enc_gemm<2, 1><<<g, 256>>>(x0, ew1, rw1, eb1, rb1, x1, 1024); }
    { dim3 g(8, 8);  enc_gemm<3, 0><<<g, 256>>>(x1, ew2, rw2, eb2, rb2, zbuf, 768);}

    // ---------- RK4 ODE: persistent kernel (launch 6 -> ncu -s 5 target) ---
    const int smem_bytes = (16384 + 16384 + 8192 + 8192 + 4096 + 80) * 4;
    cudaFuncSetAttribute(ode_kernel, cudaFuncAttributeMaxDynamicSharedMemorySize,
                         smem_bytes);
    ode_kernel<<<NBLK, 256, smem_bytes>>>(t, fw0, fb0, fw1, fb1, fw2, fb2,
                                          Gm, g0, zbuf, h1, h2, sbuf);

    // ---------- decoder over all 200 states (128x64 tiles) ----------
    { dim3 g(DECH / 64, TSTEPS * BSZ / 128); dec_gemm<1><<<g, 256>>>(zbuf, dw0, db0, hd1, TSTEPS * BSZ, DECH, LATD); }
    { dim3 g(DECH / 64, TSTEPS * BSZ / 128); dec_gemm<1><<<g, 256>>>(hd1,  dw1, db1, hd2, TSTEPS * BSZ, DECH, DECH); }
    { dim3 g(SIG  / 64, TSTEPS * BSZ / 128); dec_gemm<3><<<g, 256>>>(hd2,  dw2, db2, out, TSTEPS * BSZ, SIG,  DECH); }
}

// round 15
// speedup vs baseline: 1.4792x; 1.0480x over previous
#include <cuda_runtime.h>
#include <cuda_bf16.h>
#include <math.h>

// Problem dims
#define BSZ   256
#define SIG   64
#define LATD  256
#define ENCH  256
#define DECH  512
#define RHSH  512
#define TSTEPS 200

#define NBLK   128   // persistent ODE grid: 8 groups x 16 CTAs
#define GRPSZ  16
#define NGRP   8

// ---------------- scratch (device globals; no allocation) ----------------
__device__ float g_z[TSTEPS * BSZ * LATD];        // pred_z
__device__ float g_h1[BSZ * RHSH];
__device__ float g_h2[BSZ * RHSH];
__device__ float g_s[BSZ * RHSH];                 // RK4 combined h2 sum
__device__ float g_G[RHSH * RHSH];                // G = fw0 @ fw2
__device__ float g_g0[RHSH];                      // g0 = fw0 @ fb2
__device__ float g_x0[3 * BSZ * ENCH];
__device__ float g_x1[2 * BSZ * ENCH];
__device__ float g_hd1[(size_t)TSTEPS * BSZ * DECH];
__device__ float g_hd2[(size_t)TSTEPS * BSZ * DECH];

// per-group barrier state (one L2 line per group)
__device__ unsigned g_arr[NGRP * 32];
__device__ unsigned g_gen[NGRP * 32];

// ---------------- f32x2 packed-FMA helpers ----------------
__device__ __forceinline__ void fma2(unsigned long long& d,
                                     unsigned long long a,
                                     unsigned long long b)
{
    asm("fma.rn.f32x2 %0, %1, %2, %0;" : "+l"(d) : "l"(a), "l"(b));
}
__device__ __forceinline__ unsigned long long pack2(float x)
{
    unsigned long long r;
    asm("mov.b64 %0, {%1, %1};" : "=l"(r) : "f"(x));
    return r;
}
__device__ __forceinline__ void unpack2(float& lo, float& hi, unsigned long long v)
{
    asm("mov.b64 {%0, %1}, %2;" : "=f"(lo), "=f"(hi) : "l"(v));
}

// ---------------- group barrier (16 CTAs) ----------------
__device__ __forceinline__ void gsync(unsigned* arr, unsigned* gen, unsigned& lg)
{
    __syncthreads();
    if (threadIdx.x == 0) {
        unsigned ticket;
        asm volatile("atom.acq_rel.gpu.add.u32 %0, [%1], 1;"
                     : "=r"(ticket) : "l"(arr) : "memory");
        const unsigned target = lg + 1;
        if ((ticket & (GRPSZ - 1)) == GRPSZ - 1) {
            asm volatile("st.release.gpu.u32 [%0], %1;"
                         :: "l"(gen), "r"(target) : "memory");
        } else {
            unsigned g;
            do {
                asm volatile("ld.acquire.gpu.u32 %0, [%1];"
                             : "=r"(g) : "l"(gen) : "memory");
            } while ((int)(g - target) < 0);
        }
        lg = target;
    }
    __syncthreads();
}

// ---------------- core GEMM: red = A(32x512) @ Ws(512x32 [k][n]) ----------
// Register-prefetch pipelined: chunk1 LDG latency hidden under chunk0 FMAs.
__device__ __forceinline__ void gemm32(const float* __restrict__ Abuf,
                                       const float* __restrict__ Ws,
                                       float* __restrict__ As,
                                       float* __restrict__ red,
                                       int m0, int tid)
{
    const int ks = tid >> 6, inner = tid & 63;
    const int tm = inner >> 3, tn = inner & 7;
    const int m  = tid & 31;
    const int kq = tid >> 5;
    const float* row = Abuf + (size_t)(m0 + m) * 512;

    unsigned long long acc[2][4] = {{0ULL,0ULL,0ULL,0ULL},{0ULL,0ULL,0ULL,0ULL}};

    float4 pf[8];
    // ---- load + store chunk 0
#pragma unroll
    for (int it = 0; it < 8; ++it)
        pf[it] = __ldcg((const float4*)(row + (it * 8 + kq) * 4));
#pragma unroll
    for (int it = 0; it < 8; ++it) {
        const int k = (it * 8 + kq) * 4;
        As[(k + 0) * 32 + m] = pf[it].x;
        As[(k + 1) * 32 + m] = pf[it].y;
        As[(k + 2) * 32 + m] = pf[it].z;
        As[(k + 3) * 32 + m] = pf[it].w;
    }
    __syncthreads();

    // ---- prefetch chunk 1 (latency hides under chunk-0 compute)
#pragma unroll
    for (int it = 0; it < 8; ++it)
        pf[it] = __ldcg((const float4*)(row + 256 + (it * 8 + kq) * 4));

    // ---- compute chunk 0
    {
        const float* Ag = As + ks * 64 * 32 + tm * 4;
        const float* Wg = Ws + (size_t)(ks * 64) * 32 + tn * 4;
#pragma unroll 8
        for (int i = 0; i < 64; ++i) {
            const ulonglong2 a2 = *(const ulonglong2*)(Ag + i * 32);
            const float4 b4 = *(const float4*)(Wg + i * 32);
            const unsigned long long b0 = pack2(b4.x), b1 = pack2(b4.y),
                                     b2 = pack2(b4.z), b3 = pack2(b4.w);
            fma2(acc[0][0], a2.x, b0); fma2(acc[1][0], a2.y, b0);
            fma2(acc[0][1], a2.x, b1); fma2(acc[1][1], a2.y, b1);
            fma2(acc[0][2], a2.x, b2); fma2(acc[1][2], a2.y, b2);
            fma2(acc[0][3], a2.x, b3); fma2(acc[1][3], a2.y, b3);
        }
    }
    __syncthreads();

    // ---- store + compute chunk 1
#pragma unroll
    for (int it = 0; it < 8; ++it) {
        const int k = (it * 8 + kq) * 4;
        As[(k + 0) * 32 + m] = pf[it].x;
        As[(k + 1) * 32 + m] = pf[it].y;
        As[(k + 2) * 32 + m] = pf[it].z;
        As[(k + 3) * 32 + m] = pf[it].w;
    }
    __syncthreads();
    {
        const float* Ag = As + ks * 64 * 32 + tm * 4;
        const float* Wg = Ws + (size_t)(256 + ks * 64) * 32 + tn * 4;
#pragma unroll 8
        for (int i = 0; i < 64; ++i) {
            const ulonglong2 a2 = *(const ulonglong2*)(Ag + i * 32);
            const float4 b4 = *(const float4*)(Wg + i * 32);
            const unsigned long long b0 = pack2(b4.x), b1 = pack2(b4.y),
                                     b2 = pack2(b4.z), b3 = pack2(b4.w);
            fma2(acc[0][0], a2.x, b0); fma2(acc[1][0], a2.y, b0);
            fma2(acc[0][1], a2.x, b1); fma2(acc[1][1], a2.y, b1);
            fma2(acc[0][2], a2.x, b2); fma2(acc[1][2], a2.y, b2);
            fma2(acc[0][3], a2.x, b3); fma2(acc[1][3], a2.y, b3);
        }
    }

#pragma unroll
    for (int i = 0; i < 2; ++i)
#pragma unroll
        for (int j = 0; j < 4; ++j) {
            float lo, hi;
            unpack2(lo, hi, acc[i][j]);
            red[ks * 1024 + (tm * 4 + 2 * i)     * 32 + tn * 4 + j] = lo;
            red[ks * 1024 + (tm * 4 + 2 * i + 1) * 32 + tn * 4 + j] = hi;
        }
    __syncthreads();
}

__device__ __forceinline__ float red4(const float* __restrict__ red, int m, int n)
{
    return red[m * 32 + n] + red[1024 + m * 32 + n] +
           red[2048 + m * 32 + n] + red[3072 + m * 32 + n];
}

// ---------------- z GEMM: red = s(32x512) @ W2s(512x16 [k][n]), pipelined --
__device__ __forceinline__ void gemmZ(const float* __restrict__ Abuf,
                                      const float* __restrict__ Ws,
                                      float* __restrict__ As,
                                      float* __restrict__ red,
                                      int m0, int tid)
{
    const int ks = tid >> 5, inner = tid & 31;
    const int tm = inner >> 2, tn = inner & 3;
    const int m  = tid & 31;
    const int kq = tid >> 5;
    const float* row = Abuf + (size_t)(m0 + m) * 512;

    unsigned long long acc[2][4] = {{0ULL,0ULL,0ULL,0ULL},{0ULL,0ULL,0ULL,0ULL}};

    float4 pf[8];
#pragma unroll
    for (int it = 0; it < 8; ++it)
        pf[it] = __ldcg((const float4*)(row + (it * 8 + kq) * 4));
#pragma unroll
    for (int it = 0; it < 8; ++it) {
        const int k = (it * 8 + kq) * 4;
        As[(k + 0) * 32 + m] = pf[it].x;
        As[(k + 1) * 32 + m] = pf[it].y;
        As[(k + 2) * 32 + m] = pf[it].z;
        As[(k + 3) * 32 + m] = pf[it].w;
    }
    __syncthreads();

#pragma unroll
    for (int it = 0; it < 8; ++it)
        pf[it] = __ldcg((const float4*)(row + 256 + (it * 8 + kq) * 4));

    {
        const float* Ag = As + ks * 32 * 32 + tm * 4;
        const float* Wg = Ws + (size_t)(ks * 32) * 16 + tn * 4;
#pragma unroll 8
        for (int i = 0; i < 32; ++i) {
            const ulonglong2 a2 = *(const ulonglong2*)(Ag + i * 32);
            const float4 b4 = *(const float4*)(Wg + i * 16);
            const unsigned long long b0 = pack2(b4.x), b1 = pack2(b4.y),
                                     b2 = pack2(b4.z), b3 = pack2(b4.w);
            fma2(acc[0][0], a2.x, b0); fma2(acc[1][0], a2.y, b0);
            fma2(acc[0][1], a2.x, b1); fma2(acc[1][1], a2.y, b1);
            fma2(acc[0][2], a2.x, b2); fma2(acc[1][2], a2.y, b2);
            fma2(acc[0][3], a2.x, b3); fma2(acc[1][3], a2.y, b3);
        }
    }
    __syncthreads();

#pragma unroll
    for (int it = 0; it < 8; ++it) {
        const int k = (it * 8 + kq) * 4;
        As[(k + 0) * 32 + m] = pf[it].x;
        As[(k + 1) * 32 + m] = pf[it].y;
        As[(k + 2) * 32 + m] = pf[it].z;
        As[(k + 3) * 32 + m] = pf[it].w;
    }
    __syncthreads();
    {
        const float* Ag = As + ks * 32 * 32 + tm * 4;
        const float* Wg = Ws + (size_t)(256 + ks * 32) * 16 + tn * 4;
#pragma unroll 8
        for (int i = 0; i < 32; ++i) {
            const ulonglong2 a2 = *(const ulonglong2*)(Ag + i * 32);
            const float4 b4 = *(const float4*)(Wg + i * 16);
            const unsigned long long b0 = pack2(b4.x), b1 = pack2(b4.y),
                                     b2 = pack2(b4.z), b3 = pack2(b4.w);
            fma2(acc[0][0], a2.x, b0); fma2(acc[1][0], a2.y, b0);
            fma2(acc[0][1], a2.x, b1); fma2(acc[1][1], a2.y, b1);
            fma2(acc[0][2], a2.x, b2); fma2(acc[1][2], a2.y, b2);
            fma2(acc[0][3], a2.x, b3); fma2(acc[1][3], a2.y, b3);
        }
    }

#pragma unroll
    for (int i = 0; i < 2; ++i)
#pragma unroll
        for (int j = 0; j < 4; ++j) {
            float lo, hi;
            unpack2(lo, hi, acc[i][j]);
            red[ks * 512 + (tm * 4 + 2 * i)     * 16 + tn * 4 + j] = lo;
            red[ks * 512 + (tm * 4 + 2 * i + 1) * 16 + tn * 4 + j] = hi;
        }
    __syncthreads();
}

// ---------------- persistent ODE kernel (w-space, R7 config) ---------------
__global__ void __launch_bounds__(256, 1) ode_kernel(
    const float* __restrict__ t,
    const float* __restrict__ fw0, const float* __restrict__ fb0,
    const float* __restrict__ fw1, const float* __restrict__ fb1,
    const float* __restrict__ fw2, const float* __restrict__ fb2,
    const float* __restrict__ Gm,  const float* __restrict__ g0,
    float* __restrict__ zbuf, float* __restrict__ h1buf,
    float* __restrict__ h2buf, float* __restrict__ sbuf)
{
    extern __shared__ float smem[];
    float* W1s = smem;                 // 512k x 32n = 16384 f (64 KB)
    float* Gs  = W1s + 16384;          // 512k x 32n = 16384 f (64 KB)
    float* W2s = Gs  + 16384;          // 512k x 16n =  8192 f (32 KB)
    float* As  = W2s + 8192;           // 256k x 32m =  8192 f (32 KB)
    float* red = As  + 8192;           //               4096 f (16 KB)
    float* bS  = red + 4096;           // b1(32) | g0(32) | b2(16) = 80 f

    const int tid = threadIdx.x;
    const int c   = blockIdx.x & 15;   // N-slice 0..15
    const int grp = blockIdx.x >> 4;   // batch group 0..7
    const int m0  = grp * 32;
    const int n0w = c * 32;            // 512-dim slice start
    const int nzw = c * 16;            // 256-dim slice start

    // ---- stage weight slices ([k][n]) + biases
    for (int e = tid; e < 32 * 512; e += 256) {
        const int n = e >> 9, k = e & 511;
        W1s[k * 32 + n] = fw1[(size_t)(n0w + n) * 512 + k];
        Gs [k * 32 + n] = Gm [(size_t)(n0w + n) * 512 + k];
    }
    for (int e = tid; e < 16 * 512; e += 256) {
        const int n = e >> 9, k = e & 511;
        W2s[k * 16 + n] = fw2[(size_t)(nzw + n) * 512 + k];
    }
    if (tid < 32)       bS[tid] = fb1[n0w + tid];
    else if (tid < 64)  bS[tid] = g0[n0w + tid - 32];
    else if (tid < 80)  bS[tid] = fb2[nzw + tid - 64];
    __syncthreads();

    // ---- per-thread persistent regs: elem it <-> row (tid>>5)+8*it, col tid&31
    const int mr = tid >> 5;
    const int nn = tid & 31;
    float w[4], u[4] = {0.f, 0.f, 0.f, 0.f}, s[4] = {0.f, 0.f, 0.f, 0.f};

    // ---- init w = W0 @ z0 + b0
    {
        const int m  = tid & 31;
        const int kq = tid >> 5;
        const float* row = zbuf + (size_t)(m0 + m) * 256;
#pragma unroll
        for (int it = 0; it < 8; ++it) {
            const int k = (it * 8 + kq) * 4;
            const float4 v = __ldcg((const float4*)(row + k));
            As[(k + 0) * 32 + m] = v.x; As[(k + 1) * 32 + m] = v.y;
            As[(k + 2) * 32 + m] = v.z; As[(k + 3) * 32 + m] = v.w;
        }
        __syncthreads();
        const float b0v = fb0[n0w + nn];
        float wa[4] = {b0v, b0v, b0v, b0v};
        const float* w0row = fw0 + (size_t)(n0w + nn) * 256;
        for (int l = 0; l < 256; l += 4) {
            const float4 wv = __ldcg((const float4*)(w0row + l));
#pragma unroll
            for (int j = 0; j < 4; ++j) {
                const float wj = (&wv.x)[j];
#pragma unroll
                for (int i = 0; i < 4; ++i)
                    wa[i] = fmaf(As[(l + j) * 32 + mr + 8 * i], wj, wa[i]);
            }
        }
#pragma unroll
        for (int i = 0; i < 4; ++i) w[i] = wa[i];
        __syncthreads();
    }

    unsigned* arr = &g_arr[grp * 32];
    unsigned* gen = &g_gen[grp * 32];
    unsigned lg = 0;
    if (tid == 0)
        asm volatile("ld.acquire.gpu.u32 %0, [%1];" : "=r"(lg) : "l"(gen) : "memory");

    for (int n = 0; n < TSTEPS - 1; ++n) {
        const float hh = __ldg(&t[n + 1]) - __ldg(&t[n]);
        const float h6 = hh * (1.f / 6.f);
        const float* zn = zbuf + (size_t)n * (BSZ * LATD);
        float* znx      = zbuf + (size_t)(n + 1) * (BSZ * LATD);

#pragma unroll 1
        for (int st = 0; st < 4; ++st) {
            const float cc = (st == 0) ? 0.f : ((st == 3) ? hh : 0.5f * hh);
            const float sw = (st == 1 || st == 2) ? 2.f : 1.f;

            if (st > 0) {               // u = G @ h2 + g0
                gemm32(h2buf, Gs, As, red, m0, tid);
#pragma unroll
                for (int it = 0; it < 4; ++it)
                    u[it] = red4(red, mr + 8 * it, nn) + bS[32 + nn];
            }
            // h1 = tanh(w + c*u)
#pragma unroll
            for (int it = 0; it < 4; ++it)
                h1buf[(size_t)(m0 + mr + 8 * it) * 512 + n0w + nn] =
                    tanhf(fmaf(cc, u[it], w[it]));
            gsync(arr, gen, lg);

            // h2 = tanh(W1 @ h1 + b1); s += sw*h2
            gemm32(h1buf, W1s, As, red, m0, tid);
#pragma unroll
            for (int it = 0; it < 4; ++it) {
                const int m = mr + 8 * it;
                float v = red4(red, m, nn) + bS[nn];
                v = tanhf(v);
                s[it] = fmaf(sw, v, s[it]);
                if (st < 3) h2buf[(size_t)(m0 + m) * 512 + n0w + nn] = v;
                else        sbuf [(size_t)(m0 + m) * 512 + n0w + nn] = s[it];
            }
            gsync(arr, gen, lg);
        }

        // ---- end of step: w += (h/6) G s + h g0 ; z_{n+1} = z_n + (h/6) W2 s + h b2
        gemm32(sbuf, Gs, As, red, m0, tid);
#pragma unroll
        for (int it = 0; it < 4; ++it)
            w[it] += h6 * red4(red, mr + 8 * it, nn) + hh * bS[32 + nn];

        gemmZ(sbuf, W2s, As, red, m0, tid);
#pragma unroll
        for (int it = 0; it < 2; ++it) {
            const int e = it * 256 + tid;
            const int m = e >> 4, nz = e & 15;
            float v = 0.f;
#pragma unroll
            for (int q = 0; q < 8; ++q) v += red[q * 512 + m * 16 + nz];
            const size_t idx = (size_t)(m0 + m) * 256 + nzw + nz;
            znx[idx] = __ldcg(zn + idx) + h6 * v + hh * bS[64 + nz];
        }
#pragma unroll
        for (int i = 0; i < 4; ++i) s[i] = 0.f;
    }
}

// ---------------- G = fw0 @ fw2 precompute (NN GEMM 512x512x256) -----------
__launch_bounds__(256)
__global__ void gemmG_kernel(const float* __restrict__ fw0,
                             const float* __restrict__ fw2,
                             float* __restrict__ G)
{
    __shared__ float As[16][68];
    __shared__ float Bs[16][68];
    const int tid = threadIdx.x;
    const int tx = tid & 15, ty = tid >> 4;
    const int m0 = blockIdx.y * 64, n0 = blockIdx.x * 64;

    float acc[4][4] = {};
    for (int k0 = 0; k0 < 256; k0 += 16) {
        {
            const int ar = tid >> 2, ak = (tid & 3) * 4;
            const float4 av = *(const float4*)(fw0 + (size_t)(m0 + ar) * 256 + k0 + ak);
            As[ak + 0][ar] = av.x; As[ak + 1][ar] = av.y;
            As[ak + 2][ar] = av.z; As[ak + 3][ar] = av.w;
            const int kk = tid >> 4, bn = (tid & 15) * 4;
            const float4 bv = *(const float4*)(fw2 + (size_t)(k0 + kk) * 512 + n0 + bn);
            *(float4*)&Bs[kk][bn] = bv;
        }
        __syncthreads();
#pragma unroll
        for (int k = 0; k < 16; ++k) {
            float a[4], b[4];
#pragma unroll
            for (int i = 0; i < 4; ++i) a[i] = As[k][ty * 4 + i];
#pragma unroll
            for (int j = 0; j < 4; ++j) b[j] = Bs[k][tx * 4 + j];
#pragma unroll
            for (int i = 0; i < 4; ++i)
#pragma unroll
                for (int j = 0; j < 4; ++j) acc[i][j] = fmaf(a[i], b[j], acc[i][j]);
        }
        __syncthreads();
    }
#pragma unroll
    for (int i = 0; i < 4; ++i)
#pragma unroll
        for (int j = 0; j < 4; ++j)
            G[(size_t)(m0 + ty * 4 + i) * 512 + n0 + tx * 4 + j] = acc[i][j];
}

__global__ void g0_kernel(const float* __restrict__ fw0,
                          const float* __restrict__ fb2,
                          float* __restrict__ g0)
{
    const int n = blockIdx.x * 256 + threadIdx.x;
    float acc = 0.f;
    for (int l = 0; l < 256; ++l)
        acc = fmaf(fw0[(size_t)n * 256 + l], fb2[l], acc);
    g0[n] = acc;
}

// ---------------- encoder: fused wcat + im2col gather + GEMM ----------------
template<int G>
__device__ __forceinline__ float gatherA(const float* __restrict__ src, int row, int c)
{
    if (G == 1) {
        const int l = row >> 8, b = row & 255;
        if (c < 192) {
            const int i = c / 3, kk = c - 3 * i, p = l + kk - 1;
            return (p >= 0) ? src[(size_t)b * 65536 + i * 1024 + p] : 0.f;
        }
        return src[(size_t)b * 65536 + (c - 192) * 1024 + l];
    } else if (G == 2) {
        const int l = row >> 8, b = row & 255;
        if (c < 768) {
            const int i = c / 3, kk = c - 3 * i, p = l + kk - 1;
            return (p >= 0) ? src[(size_t)(p * 256 + b) * 256 + i] : 0.f;
        }
        return src[(size_t)(l * 256 + b) * 256 + (c - 768)];
    } else {
        const int b = row;
        if (c < 256)  return src[(size_t)b * 256 + c];
        if (c < 512)  return src[(size_t)(256 + b) * 256 + (c - 256)];
        return src[(size_t)b * 256 + (c - 512)];
    }
}

template<int G>
__device__ __forceinline__ float gatherW(const float* __restrict__ ew,
                                         const float* __restrict__ rw, int o, int c)
{
    if (G == 1) {
        if (c < 192) return ew[o * 192 + c];
        return rw[o * 64 + (c - 192)];
    } else if (G == 2) {
        if (c < 768) return ew[o * 768 + c];
        return rw[o * 256 + (c - 768)];
    } else {
        if (c < 256)  return ew[o * 768 + c * 3 + 1];
        if (c < 512)  return ew[o * 768 + (c - 256) * 3 + 2];
        return rw[o * 256 + (c - 512)];
    }
}

template<int G, int TANH>
__launch_bounds__(256)
__global__ void enc_gemm(const float* __restrict__ Asrc,
                         const float* __restrict__ ew, const float* __restrict__ rw,
                         const float* __restrict__ eb, const float* __restrict__ rb,
                         float* __restrict__ C, int K)
{
    __shared__ float As[32][34];
    __shared__ float Bs[32][34];

    const int tid = threadIdx.x;
    const int tx  = tid & 15;
    const int ty  = tid >> 4;
    const int m0  = blockIdx.y * 32;
    const int n0  = blockIdx.x * 32;

    const int ar = tid >> 3;
    const int ak = (tid & 7) * 4;

    float acc[2][2] = {{0.f, 0.f}, {0.f, 0.f}};

    for (int k0 = 0; k0 < K; k0 += 32) {
#pragma unroll
        for (int j = 0; j < 4; j++) {
            As[ak + j][ar] = gatherA<G>(Asrc, m0 + ar, k0 + ak + j);
            Bs[ak + j][ar] = gatherW<G>(ew, rw, n0 + ar, k0 + ak + j);
        }
        __syncthreads();
#pragma unroll
        for (int k = 0; k < 32; k++) {
            const float a0 = As[k][ty * 2], a1 = As[k][ty * 2 + 1];
            const float b0 = Bs[k][tx * 2], b1 = Bs[k][tx * 2 + 1];
            acc[0][0] = fmaf(a0, b0, acc[0][0]);
            acc[0][1] = fmaf(a0, b1, acc[0][1]);
            acc[1][0] = fmaf(a1, b0, acc[1][0]);
            acc[1][1] = fmaf(a1, b1, acc[1][1]);
        }
        __syncthreads();
    }

#pragma unroll
    for (int i = 0; i < 2; i++) {
        const int m = m0 + ty * 2 + i;
#pragma unroll
        for (int j = 0; j < 2; j++) {
            const int n = n0 + tx * 2 + j;
            float v = acc[i][j] + eb[n] + rb[n];
            if (TANH) v = tanhf(v);
            C[(size_t)m * 256 + n] = v;
        }
    }
}

// ---------------- decoder GEMM: 64x64x16 tile, f32x2 inner (R7) ------------
template<int EPI>
__launch_bounds__(256)
__global__ void dec_gemm(const float* __restrict__ A,
                         const float* __restrict__ W,
                         const float* __restrict__ bias,
                         float* __restrict__ C,
                         int M, int N, int K)
{
    __shared__ float As[16][68];
    __shared__ float Bs[16][68];

    const int tid = threadIdx.x;
    const int tx  = tid & 15;
    const int ty  = tid >> 4;
    const int m0  = blockIdx.y * 64;
    const int n0  = blockIdx.x * 64;

    const int ar = tid >> 2;
    const int ak = (tid & 3) * 4;

    unsigned long long acc2[2][4];
#pragma unroll
    for (int i = 0; i < 2; i++)
#pragma unroll
        for (int j = 0; j < 4; j++) acc2[i][j] = 0ULL;

    const float* Aptr = A + (size_t)(m0 + ar) * K + ak;
    const float* Wptr = W + (size_t)(n0 + ar) * K + ak;

    for (int k0 = 0; k0 < K; k0 += 16) {
        const float4 av = *(const float4*)(Aptr + k0);
        const float4 bv = *(const float4*)(Wptr + k0);
        As[ak + 0][ar] = av.x; As[ak + 1][ar] = av.y;
        As[ak + 2][ar] = av.z; As[ak + 3][ar] = av.w;
        Bs[ak + 0][ar] = bv.x; Bs[ak + 1][ar] = bv.y;
        Bs[ak + 2][ar] = bv.z; Bs[ak + 3][ar] = bv.w;
        __syncthreads();
#pragma unroll
        for (int k = 0; k < 16; k++) {
            const ulonglong2 a2 = *(const ulonglong2*)(&As[k][ty * 4]);
            const float4 b4 = *(const float4*)(&Bs[k][tx * 4]);
            unsigned long long bb[4];
            bb[0] = pack2(b4.x); bb[1] = pack2(b4.y);
            bb[2] = pack2(b4.z); bb[3] = pack2(b4.w);
#pragma unroll
            for (int j = 0; j < 4; j++) {
                fma2(acc2[0][j], a2.x, bb[j]);
                fma2(acc2[1][j], a2.y, bb[j]);
            }
        }
        __syncthreads();
    }

#pragma unroll
    for (int i = 0; i < 2; i++) {
#pragma unroll
        for (int j = 0; j < 4; j++) {
            float lo, hi;
            unpack2(lo, hi, acc2[i][j]);
            const int n = n0 + tx * 4 + j;
            const float bval = bias[n];
#pragma unroll
            for (int half = 0; half < 2; half++) {
                const int m = m0 + ty * 4 + 2 * i + half;
                float v = (half == 0 ? lo : hi) + bval;
                if (EPI == 1) v = tanhf(v);
                if (EPI == 3) {
                    const int tt = m >> 8;
                    const int bb2 = m & 255;
                    C[(size_t)bb2 * (SIG * TSTEPS) + (size_t)n * TSTEPS + tt] = v;
                } else {
                    C[(size_t)m * N + n] = v;
                }
            }
        }
    }
}

extern "C" void kernel_launch(void* const* d_in, const int* in_sizes, int n_in,
                              void* d_out, int out_size)
{
    const float* y   = (const float*)d_in[0];
    const float* t   = (const float*)d_in[1];
    const float* ew0 = (const float*)d_in[2];
    const float* eb0 = (const float*)d_in[3];
    const float* rw0 = (const float*)d_in[4];
    const float* rb0 = (const float*)d_in[5];
    const float* ew1 = (const float*)d_in[6];
    const float* eb1 = (const float*)d_in[7];
    const float* rw1 = (const float*)d_in[8];
    const float* rb1 = (const float*)d_in[9];
    const float* ew2 = (const float*)d_in[10];
    const float* eb2 = (const float*)d_in[11];
    const float* rw2 = (const float*)d_in[12];
    const float* rb2 = (const float*)d_in[13];
    const float* fw0 = (const float*)d_in[14];
    const float* fb0 = (const float*)d_in[15];
    const float* fw1 = (const float*)d_in[16];
    const float* fb1 = (const float*)d_in[17];
    const float* fw2 = (const float*)d_in[18];
    const float* fb2 = (const float*)d_in[19];
    const float* dw0 = (const float*)d_in[20];
    const float* db0 = (const float*)d_in[21];
    const float* dw1 = (const float*)d_in[22];
    const float* db1 = (const float*)d_in[23];
    const float* dw2 = (const float*)d_in[24];
    const float* db2 = (const float*)d_in[25];
    float* out = (float*)d_out;

    float *zbuf, *h1, *h2, *sbuf, *Gm, *g0, *x0, *x1, *hd1, *hd2;
    cudaGetSymbolAddress((void**)&zbuf, g_z);
    cudaGetSymbolAddress((void**)&h1,   g_h1);
    cudaGetSymbolAddress((void**)&h2,   g_h2);
    cudaGetSymbolAddress((void**)&sbuf, g_s);
    cudaGetSymbolAddress((void**)&Gm,   g_G);
    cudaGetSymbolAddress((void**)&g0,   g_g0);
    cudaGetSymbolAddress((void**)&x0,   g_x0);
    cudaGetSymbolAddress((void**)&x1,   g_x1);
    cudaGetSymbolAddress((void**)&hd1,  g_hd1);
    cudaGetSymbolAddress((void**)&hd2,  g_hd2);

    // ---------- precompute G = fw0 @ fw2, g0 = fw0 @ fb2 ----------
    { dim3 g(8, 8); gemmG_kernel<<<g, 256>>>(fw0, fw2, Gm); }
    g0_kernel<<<2, 256>>>(fw0, fb2, g0);

    // ---------- encoder: 3 fused gather-GEMMs -> z0 ----------
    { dim3 g(8, 24); enc_gemm<1, 1><<<g, 256>>>(y,  ew0, rw0, eb0, rb0, x0, 256);  }
    { dim3 g(8, 16); enc_gemm<2, 1><<<g, 256>>>(x0, ew1, rw1, eb1, rb1, x1, 1024); }
    { dim3 g(8, 8);  enc_gemm<3, 0><<<g, 256>>>(x1, ew2, rw2, eb2, rb2, zbuf, 768);}

    // ---------- RK4 ODE: persistent kernel, pipelined GEMMs ----------
    const int smem_bytes = (16384 + 16384 + 8192 + 8192 + 4096 + 80) * 4;
    cudaFuncSetAttribute(ode_kernel, cudaFuncAttributeMaxDynamicSharedMemorySize,
                         smem_bytes);
    ode_kernel<<<NBLK, 256, smem_bytes>>>(t, fw0, fb0, fw1, fb1, fw2, fb2,
                                          Gm, g0, zbuf, h1, h2, sbuf);

    // ---------- decoder over all 200 states ----------
    { dim3 g(DECH / 64, TSTEPS * BSZ / 64); dec_gemm<1><<<g, 256>>>(zbuf, dw0, db0, hd1, TSTEPS * BSZ, DECH, LATD); }
    { dim3 g(DECH / 64, TSTEPS * BSZ / 64); dec_gemm<1><<<g, 256>>>(hd1,  dw1, db1, hd2, TSTEPS * BSZ, DECH, DECH); }
    { dim3 g(SIG  / 64, TSTEPS * BSZ / 64); dec_gemm<3><<<g, 256>>>(hd2,  dw2, db2, out, TSTEPS * BSZ, SIG,  DECH); }
}

// round 16
// speedup vs baseline: 1.5415x; 1.0421x over previous
#include <cuda_runtime.h>
#include <cuda_bf16.h>
#include <math.h>

// Problem dims
#define BSZ   256
#define SIG   64
#define LATD  256
#define ENCH  256
#define DECH  512
#define RHSH  512
#define TSTEPS 200

#define NBLK   128   // persistent ODE grid: 8 groups x 16 CTAs
#define GRPSZ  16
#define NGRP   8

// ---------------- scratch (device globals; no allocation) ----------------
__device__ float g_z[TSTEPS * BSZ * LATD];        // pred_z
__device__ float g_h1[BSZ * RHSH];
__device__ float g_h2[BSZ * RHSH];
__device__ float g_s[BSZ * RHSH];                 // RK4 combined h2 sum
__device__ float g_G[RHSH * RHSH];                // G = fw0 @ fw2
__device__ float g_g0[RHSH];                      // g0 = fw0 @ fb2
__device__ float g_x0[3 * BSZ * ENCH];
__device__ float g_x1[2 * BSZ * ENCH];
__device__ float g_hd1[(size_t)TSTEPS * BSZ * DECH];
__device__ float g_hd2[(size_t)TSTEPS * BSZ * DECH];

// distributed barrier flags: one padded L2 line per CTA, monotonic counters
__device__ unsigned g_flags[NGRP * GRPSZ * 32];

// ---------------- f32x2 packed-FMA helpers ----------------
__device__ __forceinline__ void fma2(unsigned long long& d,
                                     unsigned long long a,
                                     unsigned long long b)
{
    asm("fma.rn.f32x2 %0, %1, %2, %0;" : "+l"(d) : "l"(a), "l"(b));
}
__device__ __forceinline__ unsigned long long pack2(float x)
{
    unsigned long long r;
    asm("mov.b64 %0, {%1, %1};" : "=l"(r) : "f"(x));
    return r;
}
__device__ __forceinline__ void unpack2(float& lo, float& hi, unsigned long long v)
{
    asm("mov.b64 {%0, %1}, %2;" : "=f"(lo), "=f"(hi) : "l"(v));
}

// ---------------- distributed-flag group barrier (16 CTAs) ----------------
// Each CTA stores its own flag (parallel, no atomic chain); threads 0..15
// poll one flag each (parallel L2 round trips). Monotonic => race-free.
__device__ __forceinline__ void gsync(unsigned* flags, int cta, unsigned& lg)
{
    ++lg;
    __syncthreads();
    if (threadIdx.x == 0)
        asm volatile("st.release.gpu.u32 [%0], %1;"
                     :: "l"(flags + cta * 32), "r"(lg) : "memory");
    if (threadIdx.x < GRPSZ) {
        const unsigned* p = flags + threadIdx.x * 32;
        unsigned g;
        do {
            asm volatile("ld.acquire.gpu.u32 %0, [%1];"
                         : "=r"(g) : "l"(p) : "memory");
        } while ((int)(g - lg) < 0);
    }
    __syncthreads();
}

// ---------------- core GEMM: red = A(32x512) @ Ws(512x32 [k][n]) ----------
// Register-prefetch pipelined: chunk1 LDG latency hidden under chunk0 FMAs.
__device__ __forceinline__ void gemm32(const float* __restrict__ Abuf,
                                       const float* __restrict__ Ws,
                                       float* __restrict__ As,
                                       float* __restrict__ red,
                                       int m0, int tid)
{
    const int ks = tid >> 6, inner = tid & 63;
    const int tm = inner >> 3, tn = inner & 7;
    const int m  = tid & 31;
    const int kq = tid >> 5;
    const float* row = Abuf + (size_t)(m0 + m) * 512;

    unsigned long long acc[2][4] = {{0ULL,0ULL,0ULL,0ULL},{0ULL,0ULL,0ULL,0ULL}};

    float4 pf[8];
    // ---- load + store chunk 0
#pragma unroll
    for (int it = 0; it < 8; ++it)
        pf[it] = __ldcg((const float4*)(row + (it * 8 + kq) * 4));
#pragma unroll
    for (int it = 0; it < 8; ++it) {
        const int k = (it * 8 + kq) * 4;
        As[(k + 0) * 32 + m] = pf[it].x;
        As[(k + 1) * 32 + m] = pf[it].y;
        As[(k + 2) * 32 + m] = pf[it].z;
        As[(k + 3) * 32 + m] = pf[it].w;
    }
    __syncthreads();

    // ---- prefetch chunk 1 (latency hides under chunk-0 compute)
#pragma unroll
    for (int it = 0; it < 8; ++it)
        pf[it] = __ldcg((const float4*)(row + 256 + (it * 8 + kq) * 4));

    // ---- compute chunk 0
    {
        const float* Ag = As + ks * 64 * 32 + tm * 4;
        const float* Wg = Ws + (size_t)(ks * 64) * 32 + tn * 4;
#pragma unroll 8
        for (int i = 0; i < 64; ++i) {
            const ulonglong2 a2 = *(const ulonglong2*)(Ag + i * 32);
            const float4 b4 = *(const float4*)(Wg + i * 32);
            const unsigned long long b0 = pack2(b4.x), b1 = pack2(b4.y),
                                     b2 = pack2(b4.z), b3 = pack2(b4.w);
            fma2(acc[0][0], a2.x, b0); fma2(acc[1][0], a2.y, b0);
            fma2(acc[0][1], a2.x, b1); fma2(acc[1][1], a2.y, b1);
            fma2(acc[0][2], a2.x, b2); fma2(acc[1][2], a2.y, b2);
            fma2(acc[0][3], a2.x, b3); fma2(acc[1][3], a2.y, b3);
        }
    }
    __syncthreads();

    // ---- store + compute chunk 1
#pragma unroll
    for (int it = 0; it < 8; ++it) {
        const int k = (it * 8 + kq) * 4;
        As[(k + 0) * 32 + m] = pf[it].x;
        As[(k + 1) * 32 + m] = pf[it].y;
        As[(k + 2) * 32 + m] = pf[it].z;
        As[(k + 3) * 32 + m] = pf[it].w;
    }
    __syncthreads();
    {
        const float* Ag = As + ks * 64 * 32 + tm * 4;
        const float* Wg = Ws + (size_t)(256 + ks * 64) * 32 + tn * 4;
#pragma unroll 8
        for (int i = 0; i < 64; ++i) {
            const ulonglong2 a2 = *(const ulonglong2*)(Ag + i * 32);
            const float4 b4 = *(const float4*)(Wg + i * 32);
            const unsigned long long b0 = pack2(b4.x), b1 = pack2(b4.y),
                                     b2 = pack2(b4.z), b3 = pack2(b4.w);
            fma2(acc[0][0], a2.x, b0); fma2(acc[1][0], a2.y, b0);
            fma2(acc[0][1], a2.x, b1); fma2(acc[1][1], a2.y, b1);
            fma2(acc[0][2], a2.x, b2); fma2(acc[1][2], a2.y, b2);
            fma2(acc[0][3], a2.x, b3); fma2(acc[1][3], a2.y, b3);
        }
    }

#pragma unroll
    for (int i = 0; i < 2; ++i)
#pragma unroll
        for (int j = 0; j < 4; ++j) {
            float lo, hi;
            unpack2(lo, hi, acc[i][j]);
            red[ks * 1024 + (tm * 4 + 2 * i)     * 32 + tn * 4 + j] = lo;
            red[ks * 1024 + (tm * 4 + 2 * i + 1) * 32 + tn * 4 + j] = hi;
        }
    __syncthreads();
}

__device__ __forceinline__ float red4(const float* __restrict__ red, int m, int n)
{
    return red[m * 32 + n] + red[1024 + m * 32 + n] +
           red[2048 + m * 32 + n] + red[3072 + m * 32 + n];
}

// ---------------- z GEMM: red = s(32x512) @ W2s(512x16 [k][n]), pipelined --
__device__ __forceinline__ void gemmZ(const float* __restrict__ Abuf,
                                      const float* __restrict__ Ws,
                                      float* __restrict__ As,
                                      float* __restrict__ red,
                                      int m0, int tid)
{
    const int ks = tid >> 5, inner = tid & 31;
    const int tm = inner >> 2, tn = inner & 3;
    const int m  = tid & 31;
    const int kq = tid >> 5;
    const float* row = Abuf + (size_t)(m0 + m) * 512;

    unsigned long long acc[2][4] = {{0ULL,0ULL,0ULL,0ULL},{0ULL,0ULL,0ULL,0ULL}};

    float4 pf[8];
#pragma unroll
    for (int it = 0; it < 8; ++it)
        pf[it] = __ldcg((const float4*)(row + (it * 8 + kq) * 4));
#pragma unroll
    for (int it = 0; it < 8; ++it) {
        const int k = (it * 8 + kq) * 4;
        As[(k + 0) * 32 + m] = pf[it].x;
        As[(k + 1) * 32 + m] = pf[it].y;
        As[(k + 2) * 32 + m] = pf[it].z;
        As[(k + 3) * 32 + m] = pf[it].w;
    }
    __syncthreads();

#pragma unroll
    for (int it = 0; it < 8; ++it)
        pf[it] = __ldcg((const float4*)(row + 256 + (it * 8 + kq) * 4));

    {
        const float* Ag = As + ks * 32 * 32 + tm * 4;
        const float* Wg = Ws + (size_t)(ks * 32) * 16 + tn * 4;
#pragma unroll 8
        for (int i = 0; i < 32; ++i) {
            const ulonglong2 a2 = *(const ulonglong2*)(Ag + i * 32);
            const float4 b4 = *(const float4*)(Wg + i * 16);
            const unsigned long long b0 = pack2(b4.x), b1 = pack2(b4.y),
                                     b2 = pack2(b4.z), b3 = pack2(b4.w);
            fma2(acc[0][0], a2.x, b0); fma2(acc[1][0], a2.y, b0);
            fma2(acc[0][1], a2.x, b1); fma2(acc[1][1], a2.y, b1);
            fma2(acc[0][2], a2.x, b2); fma2(acc[1][2], a2.y, b2);
            fma2(acc[0][3], a2.x, b3); fma2(acc[1][3], a2.y, b3);
        }
    }
    __syncthreads();

#pragma unroll
    for (int it = 0; it < 8; ++it) {
        const int k = (it * 8 + kq) * 4;
        As[(k + 0) * 32 + m] = pf[it].x;
        As[(k + 1) * 32 + m] = pf[it].y;
        As[(k + 2) * 32 + m] = pf[it].z;
        As[(k + 3) * 32 + m] = pf[it].w;
    }
    __syncthreads();
    {
        const float* Ag = As + ks * 32 * 32 + tm * 4;
        const float* Wg = Ws + (size_t)(256 + ks * 32) * 16 + tn * 4;
#pragma unroll 8
        for (int i = 0; i < 32; ++i) {
            const ulonglong2 a2 = *(const ulonglong2*)(Ag + i * 32);
            const float4 b4 = *(const float4*)(Wg + i * 16);
            const unsigned long long b0 = pack2(b4.x), b1 = pack2(b4.y),
                                     b2 = pack2(b4.z), b3 = pack2(b4.w);
            fma2(acc[0][0], a2.x, b0); fma2(acc[1][0], a2.y, b0);
            fma2(acc[0][1], a2.x, b1); fma2(acc[1][1], a2.y, b1);
            fma2(acc[0][2], a2.x, b2); fma2(acc[1][2], a2.y, b2);
            fma2(acc[0][3], a2.x, b3); fma2(acc[1][3], a2.y, b3);
        }
    }

#pragma unroll
    for (int i = 0; i < 2; ++i)
#pragma unroll
        for (int j = 0; j < 4; ++j) {
            float lo, hi;
            unpack2(lo, hi, acc[i][j]);
            red[ks * 512 + (tm * 4 + 2 * i)     * 16 + tn * 4 + j] = lo;
            red[ks * 512 + (tm * 4 + 2 * i + 1) * 16 + tn * 4 + j] = hi;
        }
    __syncthreads();
}

// ---------------- persistent ODE kernel (w-space) ---------------
__global__ void __launch_bounds__(256, 1) ode_kernel(
    const float* __restrict__ t,
    const float* __restrict__ fw0, const float* __restrict__ fb0,
    const float* __restrict__ fw1, const float* __restrict__ fb1,
    const float* __restrict__ fw2, const float* __restrict__ fb2,
    const float* __restrict__ Gm,  const float* __restrict__ g0,
    float* __restrict__ zbuf, float* __restrict__ h1buf,
    float* __restrict__ h2buf, float* __restrict__ sbuf)
{
    extern __shared__ float smem[];
    float* W1s = smem;                 // 512k x 32n = 16384 f (64 KB)
    float* Gs  = W1s + 16384;          // 512k x 32n = 16384 f (64 KB)
    float* W2s = Gs  + 16384;          // 512k x 16n =  8192 f (32 KB)
    float* As  = W2s + 8192;           // 256k x 32m =  8192 f (32 KB)
    float* red = As  + 8192;           //               4096 f (16 KB)
    float* bS  = red + 4096;           // b1(32) | g0(32) | b2(16) = 80 f

    const int tid = threadIdx.x;
    const int c   = blockIdx.x & 15;   // N-slice 0..15
    const int grp = blockIdx.x >> 4;   // batch group 0..7
    const int m0  = grp * 32;
    const int n0w = c * 32;            // 512-dim slice start
    const int nzw = c * 16;            // 256-dim slice start

    // ---- stage weight slices ([k][n]) + biases
    for (int e = tid; e < 32 * 512; e += 256) {
        const int n = e >> 9, k = e & 511;
        W1s[k * 32 + n] = fw1[(size_t)(n0w + n) * 512 + k];
        Gs [k * 32 + n] = Gm [(size_t)(n0w + n) * 512 + k];
    }
    for (int e = tid; e < 16 * 512; e += 256) {
        const int n = e >> 9, k = e & 511;
        W2s[k * 16 + n] = fw2[(size_t)(nzw + n) * 512 + k];
    }
    if (tid < 32)       bS[tid] = fb1[n0w + tid];
    else if (tid < 64)  bS[tid] = g0[n0w + tid - 32];
    else if (tid < 80)  bS[tid] = fb2[nzw + tid - 64];
    __syncthreads();

    // ---- per-thread persistent regs: elem it <-> row (tid>>5)+8*it, col tid&31
    const int mr = tid >> 5;
    const int nn = tid & 31;
    float w[4], u[4] = {0.f, 0.f, 0.f, 0.f}, s[4] = {0.f, 0.f, 0.f, 0.f};

    // ---- init w = W0 @ z0 + b0
    {
        const int m  = tid & 31;
        const int kq = tid >> 5;
        const float* row = zbuf + (size_t)(m0 + m) * 256;
#pragma unroll
        for (int it = 0; it < 8; ++it) {
            const int k = (it * 8 + kq) * 4;
            const float4 v = __ldcg((const float4*)(row + k));
            As[(k + 0) * 32 + m] = v.x; As[(k + 1) * 32 + m] = v.y;
            As[(k + 2) * 32 + m] = v.z; As[(k + 3) * 32 + m] = v.w;
        }
        __syncthreads();
        const float b0v = fb0[n0w + nn];
        float wa[4] = {b0v, b0v, b0v, b0v};
        const float* w0row = fw0 + (size_t)(n0w + nn) * 256;
        for (int l = 0; l < 256; l += 4) {
            const float4 wv = __ldcg((const float4*)(w0row + l));
#pragma unroll
            for (int j = 0; j < 4; ++j) {
                const float wj = (&wv.x)[j];
#pragma unroll
                for (int i = 0; i < 4; ++i)
                    wa[i] = fmaf(As[(l + j) * 32 + mr + 8 * i], wj, wa[i]);
            }
        }
#pragma unroll
        for (int i = 0; i < 4; ++i) w[i] = wa[i];
        __syncthreads();
    }

    unsigned* flags = &g_flags[grp * (GRPSZ * 32)];
    unsigned lg;
    asm volatile("ld.acquire.gpu.u32 %0, [%1];"
                 : "=r"(lg) : "l"(flags + c * 32) : "memory");

    for (int n = 0; n < TSTEPS - 1; ++n) {
        const float hh = __ldg(&t[n + 1]) - __ldg(&t[n]);
        const float h6 = hh * (1.f / 6.f);
        const float* zn = zbuf + (size_t)n * (BSZ * LATD);
        float* znx      = zbuf + (size_t)(n + 1) * (BSZ * LATD);

#pragma unroll 1
        for (int st = 0; st < 4; ++st) {
            const float cc = (st == 0) ? 0.f : ((st == 3) ? hh : 0.5f * hh);
            const float sw = (st == 1 || st == 2) ? 2.f : 1.f;

            if (st > 0) {               // u = G @ h2 + g0
                gemm32(h2buf, Gs, As, red, m0, tid);
#pragma unroll
                for (int it = 0; it < 4; ++it)
                    u[it] = red4(red, mr + 8 * it, nn) + bS[32 + nn];
            }
            // h1 = tanh(w + c*u)
#pragma unroll
            for (int it = 0; it < 4; ++it)
                h1buf[(size_t)(m0 + mr + 8 * it) * 512 + n0w + nn] =
                    tanhf(fmaf(cc, u[it], w[it]));
            gsync(flags, c, lg);

            // h2 = tanh(W1 @ h1 + b1); s += sw*h2
            gemm32(h1buf, W1s, As, red, m0, tid);
#pragma unroll
            for (int it = 0; it < 4; ++it) {
                const int m = mr + 8 * it;
                float v = red4(red, m, nn) + bS[nn];
                v = tanhf(v);
                s[it] = fmaf(sw, v, s[it]);
                if (st < 3) h2buf[(size_t)(m0 + m) * 512 + n0w + nn] = v;
                else        sbuf [(size_t)(m0 + m) * 512 + n0w + nn] = s[it];
            }
            gsync(flags, c, lg);
        }

        // ---- end of step: w += (h/6) G s + h g0 ; z_{n+1} = z_n + (h/6) W2 s + h b2
        gemm32(sbuf, Gs, As, red, m0, tid);
#pragma unroll
        for (int it = 0; it < 4; ++it)
            w[it] += h6 * red4(red, mr + 8 * it, nn) + hh * bS[32 + nn];

        gemmZ(sbuf, W2s, As, red, m0, tid);
#pragma unroll
        for (int it = 0; it < 2; ++it) {
            const int e = it * 256 + tid;
            const int m = e >> 4, nz = e & 15;
            float v = 0.f;
#pragma unroll
            for (int q = 0; q < 8; ++q) v += red[q * 512 + m * 16 + nz];
            const size_t idx = (size_t)(m0 + m) * 256 + nzw + nz;
            znx[idx] = __ldcg(zn + idx) + h6 * v + hh * bS[64 + nz];
        }
#pragma unroll
        for (int i = 0; i < 4; ++i) s[i] = 0.f;
    }
}

// ---------------- G = fw0 @ fw2 precompute (NN GEMM 512x512x256) -----------
__launch_bounds__(256)
__global__ void gemmG_kernel(const float* __restrict__ fw0,
                             const float* __restrict__ fw2,
                             float* __restrict__ G)
{
    __shared__ float As[16][68];
    __shared__ float Bs[16][68];
    const int tid = threadIdx.x;
    const int tx = tid & 15, ty = tid >> 4;
    const int m0 = blockIdx.y * 64, n0 = blockIdx.x * 64;

    float acc[4][4] = {};
    for (int k0 = 0; k0 < 256; k0 += 16) {
        {
            const int ar = tid >> 2, ak = (tid & 3) * 4;
            const float4 av = *(const float4*)(fw0 + (size_t)(m0 + ar) * 256 + k0 + ak);
            As[ak + 0][ar] = av.x; As[ak + 1][ar] = av.y;
            As[ak + 2][ar] = av.z; As[ak + 3][ar] = av.w;
            const int kk = tid >> 4, bn = (tid & 15) * 4;
            const float4 bv = *(const float4*)(fw2 + (size_t)(k0 + kk) * 512 + n0 + bn);
            *(float4*)&Bs[kk][bn] = bv;
        }
        __syncthreads();
#pragma unroll
        for (int k = 0; k < 16; ++k) {
            float a[4], b[4];
#pragma unroll
            for (int i = 0; i < 4; ++i) a[i] = As[k][ty * 4 + i];
#pragma unroll
            for (int j = 0; j < 4; ++j) b[j] = Bs[k][tx * 4 + j];
#pragma unroll
            for (int i = 0; i < 4; ++i)
#pragma unroll
                for (int j = 0; j < 4; ++j) acc[i][j] = fmaf(a[i], b[j], acc[i][j]);
        }
        __syncthreads();
    }
#pragma unroll
    for (int i = 0; i < 4; ++i)
#pragma unroll
        for (int j = 0; j < 4; ++j)
            G[(size_t)(m0 + ty * 4 + i) * 512 + n0 + tx * 4 + j] = acc[i][j];
}

__global__ void g0_kernel(const float* __restrict__ fw0,
                          const float* __restrict__ fb2,
                          float* __restrict__ g0)
{
    const int n = blockIdx.x * 256 + threadIdx.x;
    float acc = 0.f;
    for (int l = 0; l < 256; ++l)
        acc = fmaf(fw0[(size_t)n * 256 + l], fb2[l], acc);
    g0[n] = acc;
}

// ---------------- encoder: fused wcat + im2col gather + GEMM ----------------
template<int G>
__device__ __forceinline__ float gatherA(const float* __restrict__ src, int row, int c)
{
    if (G == 1) {
        const int l = row >> 8, b = row & 255;
        if (c < 192) {
            const int i = c / 3, kk = c - 3 * i, p = l + kk - 1;
            return (p >= 0) ? src[(size_t)b * 65536 + i * 1024 + p] : 0.f;
        }
        return src[(size_t)b * 65536 + (c - 192) * 1024 + l];
    } else if (G == 2) {
        const int l = row >> 8, b = row & 255;
        if (c < 768) {
            const int i = c / 3, kk = c - 3 * i, p = l + kk - 1;
            return (p >= 0) ? src[(size_t)(p * 256 + b) * 256 + i] : 0.f;
        }
        return src[(size_t)(l * 256 + b) * 256 + (c - 768)];
    } else {
        const int b = row;
        if (c < 256)  return src[(size_t)b * 256 + c];
        if (c < 512)  return src[(size_t)(256 + b) * 256 + (c - 256)];
        return src[(size_t)b * 256 + (c - 512)];
    }
}

template<int G>
__device__ __forceinline__ float gatherW(const float* __restrict__ ew,
                                         const float* __restrict__ rw, int o, int c)
{
    if (G == 1) {
        if (c < 192) return ew[o * 192 + c];
        return rw[o * 64 + (c - 192)];
    } else if (G == 2) {
        if (c < 768) return ew[o * 768 + c];
        return rw[o * 256 + (c - 768)];
    } else {
        if (c < 256)  return ew[o * 768 + c * 3 + 1];
        if (c < 512)  return ew[o * 768 + (c - 256) * 3 + 2];
        return rw[o * 256 + (c - 512)];
    }
}

template<int G, int TANH>
__launch_bounds__(256)
__global__ void enc_gemm(const float* __restrict__ Asrc,
                         const float* __restrict__ ew, const float* __restrict__ rw,
                         const float* __restrict__ eb, const float* __restrict__ rb,
                         float* __restrict__ C, int K)
{
    __shared__ float As[32][34];
    __shared__ float Bs[32][34];

    const int tid = threadIdx.x;
    const int tx  = tid & 15;
    const int ty  = tid >> 4;
    const int m0  = blockIdx.y * 32;
    const int n0  = blockIdx.x * 32;

    const int ar = tid >> 3;
    const int ak = (tid & 7) * 4;

    float acc[2][2] = {{0.f, 0.f}, {0.f, 0.f}};

    for (int k0 = 0; k0 < K; k0 += 32) {
#pragma unroll
        for (int j = 0; j < 4; j++) {
            As[ak + j][ar] = gatherA<G>(Asrc, m0 + ar, k0 + ak + j);
            Bs[ak + j][ar] = gatherW<G>(ew, rw, n0 + ar, k0 + ak + j);
        }
        __syncthreads();
#pragma unroll
        for (int k = 0; k < 32; k++) {
            const float a0 = As[k][ty * 2], a1 = As[k][ty * 2 + 1];
            const float b0 = Bs[k][tx * 2], b1 = Bs[k][tx * 2 + 1];
            acc[0][0] = fmaf(a0, b0, acc[0][0]);
            acc[0][1] = fmaf(a0, b1, acc[0][1]);
            acc[1][0] = fmaf(a1, b0, acc[1][0]);
            acc[1][1] = fmaf(a1, b1, acc[1][1]);
        }
        __syncthreads();
    }

#pragma unroll
    for (int i = 0; i < 2; i++) {
        const int m = m0 + ty * 2 + i;
#pragma unroll
        for (int j = 0; j < 2; j++) {
            const int n = n0 + tx * 2 + j;
            float v = acc[i][j] + eb[n] + rb[n];
            if (TANH) v = tanhf(v);
            C[(size_t)m * 256 + n] = v;
        }
    }
}

// ---------------- decoder GEMM: 64x64x16 tile, f32x2 inner ------------
template<int EPI>
__launch_bounds__(256)
__global__ void dec_gemm(const float* __restrict__ A,
                         const float* __restrict__ W,
                         const float* __restrict__ bias,
                         float* __restrict__ C,
                         int M, int N, int K)
{
    __shared__ float As[16][68];
    __shared__ float Bs[16][68];

    const int tid = threadIdx.x;
    const int tx  = tid & 15;
    const int ty  = tid >> 4;
    const int m0  = blockIdx.y * 64;
    const int n0  = blockIdx.x * 64;

    const int ar = tid >> 2;
    const int ak = (tid & 3) * 4;

    unsigned long long acc2[2][4];
#pragma unroll
    for (int i = 0; i < 2; i++)
#pragma unroll
        for (int j = 0; j < 4; j++) acc2[i][j] = 0ULL;

    const float* Aptr = A + (size_t)(m0 + ar) * K + ak;
    const float* Wptr = W + (size_t)(n0 + ar) * K + ak;

    for (int k0 = 0; k0 < K; k0 += 16) {
        const float4 av = *(const float4*)(Aptr + k0);
        const float4 bv = *(const float4*)(Wptr + k0);
        As[ak + 0][ar] = av.x; As[ak + 1][ar] = av.y;
        As[ak + 2][ar] = av.z; As[ak + 3][ar] = av.w;
        Bs[ak + 0][ar] = bv.x; Bs[ak + 1][ar] = bv.y;
        Bs[ak + 2][ar] = bv.z; Bs[ak + 3][ar] = bv.w;
        __syncthreads();
#pragma unroll
        for (int k = 0; k < 16; k++) {
            const ulonglong2 a2 = *(const ulonglong2*)(&As[k][ty * 4]);
            const float4 b4 = *(const float4*)(&Bs[k][tx * 4]);
            unsigned long long bb[4];
            bb[0] = pack2(b4.x); bb[1] = pack2(b4.y);
            bb[2] = pack2(b4.z); bb[3] = pack2(b4.w);
#pragma unroll
            for (int j = 0; j < 4; j++) {
                fma2(acc2[0][j], a2.x, bb[j]);
                fma2(acc2[1][j], a2.y, bb[j]);
            }
        }
        __syncthreads();
    }

#pragma unroll
    for (int i = 0; i < 2; i++) {
#pragma unroll
        for (int j = 0; j < 4; j++) {
            float lo, hi;
            unpack2(lo, hi, acc2[i][j]);
            const int n = n0 + tx * 4 + j;
            const float bval = bias[n];
#pragma unroll
            for (int half = 0; half < 2; half++) {
                const int m = m0 + ty * 4 + 2 * i + half;
                float v = (half == 0 ? lo : hi) + bval;
                if (EPI == 1) v = tanhf(v);
                if (EPI == 3) {
                    const int tt = m >> 8;
                    const int bb2 = m & 255;
                    C[(size_t)bb2 * (SIG * TSTEPS) + (size_t)n * TSTEPS + tt] = v;
                } else {
                    C[(size_t)m * N + n] = v;
                }
            }
        }
    }
}

extern "C" void kernel_launch(void* const* d_in, const int* in_sizes, int n_in,
                              void* d_out, int out_size)
{
    const float* y   = (const float*)d_in[0];
    const float* t   = (const float*)d_in[1];
    const float* ew0 = (const float*)d_in[2];
    const float* eb0 = (const float*)d_in[3];
    const float* rw0 = (const float*)d_in[4];
    const float* rb0 = (const float*)d_in[5];
    const float* ew1 = (const float*)d_in[6];
    const float* eb1 = (const float*)d_in[7];
    const float* rw1 = (const float*)d_in[8];
    const float* rb1 = (const float*)d_in[9];
    const float* ew2 = (const float*)d_in[10];
    const float* eb2 = (const float*)d_in[11];
    const float* rw2 = (const float*)d_in[12];
    const float* rb2 = (const float*)d_in[13];
    const float* fw0 = (const float*)d_in[14];
    const float* fb0 = (const float*)d_in[15];
    const float* fw1 = (const float*)d_in[16];
    const float* fb1 = (const float*)d_in[17];
    const float* fw2 = (const float*)d_in[18];
    const float* fb2 = (const float*)d_in[19];
    const float* dw0 = (const float*)d_in[20];
    const float* db0 = (const float*)d_in[21];
    const float* dw1 = (const float*)d_in[22];
    const float* db1 = (const float*)d_in[23];
    const float* dw2 = (const float*)d_in[24];
    const float* db2 = (const float*)d_in[25];
    float* out = (float*)d_out;

    float *zbuf, *h1, *h2, *sbuf, *Gm, *g0, *x0, *x1, *hd1, *hd2;
    cudaGetSymbolAddress((void**)&zbuf, g_z);
    cudaGetSymbolAddress((void**)&h1,   g_h1);
    cudaGetSymbolAddress((void**)&h2,   g_h2);
    cudaGetSymbolAddress((void**)&sbuf, g_s);
    cudaGetSymbolAddress((void**)&Gm,   g_G);
    cudaGetSymbolAddress((void**)&g0,   g_g0);
    cudaGetSymbolAddress((void**)&x0,   g_x0);
    cudaGetSymbolAddress((void**)&x1,   g_x1);
    cudaGetSymbolAddress((void**)&hd1,  g_hd1);
    cudaGetSymbolAddress((void**)&hd2,  g_hd2);

    // ---------- precompute G = fw0 @ fw2, g0 = fw0 @ fb2 ----------
    { dim3 g(8, 8); gemmG_kernel<<<g, 256>>>(fw0, fw2, Gm); }
    g0_kernel<<<2, 256>>>(fw0, fb2, g0);

    // ---------- encoder: 3 fused gather-GEMMs -> z0 ----------
    { dim3 g(8, 24); enc_gemm<1, 1><<<g, 256>>>(y,  ew0, rw0, eb0, rb0, x0, 256);  }
    { dim3 g(8, 16); enc_gemm<2, 1><<<g, 256>>>(x0, ew1, rw1, eb1, rb1, x1, 1024); }
    { dim3 g(8, 8);  enc_gemm<3, 0><<<g, 256>>>(x1, ew2, rw2, eb2, rb2, zbuf, 768);}

    // ---------- RK4 ODE: persistent kernel, flag barriers ----------
    const int smem_bytes = (16384 + 16384 + 8192 + 8192 + 4096 + 80) * 4;
    cudaFuncSetAttribute(ode_kernel, cudaFuncAttributeMaxDynamicSharedMemorySize,
                         smem_bytes);
    ode_kernel<<<NBLK, 256, smem_bytes>>>(t, fw0, fb0, fw1, fb1, fw2, fb2,
                                          Gm, g0, zbuf, h1, h2, sbuf);

    // ---------- decoder over all 200 states ----------
    { dim3 g(DECH / 64, TSTEPS * BSZ / 64); dec_gemm<1><<<g, 256>>>(zbuf, dw0, db0, hd1, TSTEPS * BSZ, DECH, LATD); }
    { dim3 g(DECH / 64, TSTEPS * BSZ / 64); dec_gemm<1><<<g, 256>>>(hd1,  dw1, db1, hd2, TSTEPS * BSZ, DECH, DECH); }
    { dim3 g(SIG  / 64, TSTEPS * BSZ / 64); dec_gemm<3><<<g, 256>>>(hd2,  dw2, db2, out, TSTEPS * BSZ, SIG,  DECH); }
}

// round 17
// speedup vs baseline: 1.5622x; 1.0134x over previous
#include <cuda_runtime.h>
#include <cuda_bf16.h>
#include <math.h>

// Problem dims
#define BSZ   256
#define SIG   64
#define LATD  256
#define ENCH  256
#define DECH  512
#define RHSH  512
#define TSTEPS 200

#define NBLK   128   // persistent ODE grid: 8 groups x 16 CTAs
#define GRPSZ  16
#define NGRP   8
#define EBLK   96    // fused encoder grid

// ---------------- scratch (device globals; no allocation) ----------------
__device__ float g_z[TSTEPS * BSZ * LATD];        // pred_z
__device__ float g_h1[BSZ * RHSH];
__device__ float g_h2[BSZ * RHSH];
__device__ float g_s[BSZ * RHSH];                 // RK4 combined h2 sum
__device__ float g_G[RHSH * RHSH];                // G = fw0 @ fw2
__device__ float g_g0[RHSH];                      // g0 = fw0 @ fb2
__device__ float g_x0[3 * BSZ * ENCH];
__device__ float g_x1[2 * BSZ * ENCH];
__device__ float g_hd1[(size_t)TSTEPS * BSZ * DECH];
__device__ float g_hd2[(size_t)TSTEPS * BSZ * DECH];

// distributed barrier flags (monotonic, one padded L2 line per CTA)
__device__ unsigned g_flags[NGRP * GRPSZ * 32];
__device__ unsigned g_eflags[EBLK * 32];

// ---------------- f32x2 packed-FMA helpers ----------------
__device__ __forceinline__ void fma2(unsigned long long& d,
                                     unsigned long long a,
                                     unsigned long long b)
{
    asm("fma.rn.f32x2 %0, %1, %2, %0;" : "+l"(d) : "l"(a), "l"(b));
}
__device__ __forceinline__ unsigned long long pack2(float x)
{
    unsigned long long r;
    asm("mov.b64 %0, {%1, %1};" : "=l"(r) : "f"(x));
    return r;
}
__device__ __forceinline__ void unpack2(float& lo, float& hi, unsigned long long v)
{
    asm("mov.b64 {%0, %1}, %2;" : "=f"(lo), "=f"(hi) : "l"(v));
}

// ---------------- split-phase distributed-flag barrier ----------------
__device__ __forceinline__ void gpub(unsigned* flags, int cta, unsigned& lg)
{
    ++lg;
    __syncthreads();
    if (threadIdx.x == 0)
        asm volatile("st.release.gpu.u32 [%0], %1;"
                     :: "l"(flags + cta * 32), "r"(lg) : "memory");
}
__device__ __forceinline__ void gwait(unsigned* flags, int nflag, unsigned lg)
{
    if (threadIdx.x < nflag) {
        const unsigned* p = flags + threadIdx.x * 32;
        unsigned g;
        do {
            asm volatile("ld.acquire.gpu.u32 %0, [%1];"
                         : "=r"(g) : "l"(p) : "memory");
        } while ((int)(g - lg) < 0);
    }
    __syncthreads();
}

// ---------------- core GEMM: red = A(32x512) @ Ws(512x32 [k][n]) ----------
// Register-prefetch pipelined: chunk1 LDG latency hidden under chunk0 FMAs.
__device__ __forceinline__ void gemm32(const float* __restrict__ Abuf,
                                       const float* __restrict__ Ws,
                                       float* __restrict__ As,
                                       float* __restrict__ red,
                                       int m0, int tid)
{
    const int ks = tid >> 6, inner = tid & 63;
    const int tm = inner >> 3, tn = inner & 7;
    const int m  = tid & 31;
    const int kq = tid >> 5;
    const float* row = Abuf + (size_t)(m0 + m) * 512;

    unsigned long long acc[2][4] = {{0ULL,0ULL,0ULL,0ULL},{0ULL,0ULL,0ULL,0ULL}};

    float4 pf[8];
#pragma unroll
    for (int it = 0; it < 8; ++it)
        pf[it] = __ldcg((const float4*)(row + (it * 8 + kq) * 4));
#pragma unroll
    for (int it = 0; it < 8; ++it) {
        const int k = (it * 8 + kq) * 4;
        As[(k + 0) * 32 + m] = pf[it].x;
        As[(k + 1) * 32 + m] = pf[it].y;
        As[(k + 2) * 32 + m] = pf[it].z;
        As[(k + 3) * 32 + m] = pf[it].w;
    }
    __syncthreads();

#pragma unroll
    for (int it = 0; it < 8; ++it)
        pf[it] = __ldcg((const float4*)(row + 256 + (it * 8 + kq) * 4));

    {
        const float* Ag = As + ks * 64 * 32 + tm * 4;
        const float* Wg = Ws + (size_t)(ks * 64) * 32 + tn * 4;
#pragma unroll 8
        for (int i = 0; i < 64; ++i) {
            const ulonglong2 a2 = *(const ulonglong2*)(Ag + i * 32);
            const float4 b4 = *(const float4*)(Wg + i * 32);
            const unsigned long long b0 = pack2(b4.x), b1 = pack2(b4.y),
                                     b2 = pack2(b4.z), b3 = pack2(b4.w);
            fma2(acc[0][0], a2.x, b0); fma2(acc[1][0], a2.y, b0);
            fma2(acc[0][1], a2.x, b1); fma2(acc[1][1], a2.y, b1);
            fma2(acc[0][2], a2.x, b2); fma2(acc[1][2], a2.y, b2);
            fma2(acc[0][3], a2.x, b3); fma2(acc[1][3], a2.y, b3);
        }
    }
    __syncthreads();

#pragma unroll
    for (int it = 0; it < 8; ++it) {
        const int k = (it * 8 + kq) * 4;
        As[(k + 0) * 32 + m] = pf[it].x;
        As[(k + 1) * 32 + m] = pf[it].y;
        As[(k + 2) * 32 + m] = pf[it].z;
        As[(k + 3) * 32 + m] = pf[it].w;
    }
    __syncthreads();
    {
        const float* Ag = As + ks * 64 * 32 + tm * 4;
        const float* Wg = Ws + (size_t)(256 + ks * 64) * 32 + tn * 4;
#pragma unroll 8
        for (int i = 0; i < 64; ++i) {
            const ulonglong2 a2 = *(const ulonglong2*)(Ag + i * 32);
            const float4 b4 = *(const float4*)(Wg + i * 32);
            const unsigned long long b0 = pack2(b4.x), b1 = pack2(b4.y),
                                     b2 = pack2(b4.z), b3 = pack2(b4.w);
            fma2(acc[0][0], a2.x, b0); fma2(acc[1][0], a2.y, b0);
            fma2(acc[0][1], a2.x, b1); fma2(acc[1][1], a2.y, b1);
            fma2(acc[0][2], a2.x, b2); fma2(acc[1][2], a2.y, b2);
            fma2(acc[0][3], a2.x, b3); fma2(acc[1][3], a2.y, b3);
        }
    }

#pragma unroll
    for (int i = 0; i < 2; ++i)
#pragma unroll
        for (int j = 0; j < 4; ++j) {
            float lo, hi;
            unpack2(lo, hi, acc[i][j]);
            red[ks * 1024 + (tm * 4 + 2 * i)     * 32 + tn * 4 + j] = lo;
            red[ks * 1024 + (tm * 4 + 2 * i + 1) * 32 + tn * 4 + j] = hi;
        }
    __syncthreads();
}

__device__ __forceinline__ float red4(const float* __restrict__ red, int m, int n)
{
    return red[m * 32 + n] + red[1024 + m * 32 + n] +
           red[2048 + m * 32 + n] + red[3072 + m * 32 + n];
}

// ---------------- z GEMM: red = s(32x512) @ W2s(512x16 [k][n]), pipelined --
__device__ __forceinline__ void gemmZ(const float* __restrict__ Abuf,
                                      const float* __restrict__ Ws,
                                      float* __restrict__ As,
                                      float* __restrict__ red,
                                      int m0, int tid)
{
    const int ks = tid >> 5, inner = tid & 31;
    const int tm = inner >> 2, tn = inner & 3;
    const int m  = tid & 31;
    const int kq = tid >> 5;
    const float* row = Abuf + (size_t)(m0 + m) * 512;

    unsigned long long acc[2][4] = {{0ULL,0ULL,0ULL,0ULL},{0ULL,0ULL,0ULL,0ULL}};

    float4 pf[8];
#pragma unroll
    for (int it = 0; it < 8; ++it)
        pf[it] = __ldcg((const float4*)(row + (it * 8 + kq) * 4));
#pragma unroll
    for (int it = 0; it < 8; ++it) {
        const int k = (it * 8 + kq) * 4;
        As[(k + 0) * 32 + m] = pf[it].x;
        As[(k + 1) * 32 + m] = pf[it].y;
        As[(k + 2) * 32 + m] = pf[it].z;
        As[(k + 3) * 32 + m] = pf[it].w;
    }
    __syncthreads();

#pragma unroll
    for (int it = 0; it < 8; ++it)
        pf[it] = __ldcg((const float4*)(row + 256 + (it * 8 + kq) * 4));

    {
        const float* Ag = As + ks * 32 * 32 + tm * 4;
        const float* Wg = Ws + (size_t)(ks * 32) * 16 + tn * 4;
#pragma unroll 8
        for (int i = 0; i < 32; ++i) {
            const ulonglong2 a2 = *(const ulonglong2*)(Ag + i * 32);
            const float4 b4 = *(const float4*)(Wg + i * 16);
            const unsigned long long b0 = pack2(b4.x), b1 = pack2(b4.y),
                                     b2 = pack2(b4.z), b3 = pack2(b4.w);
            fma2(acc[0][0], a2.x, b0); fma2(acc[1][0], a2.y, b0);
            fma2(acc[0][1], a2.x, b1); fma2(acc[1][1], a2.y, b1);
            fma2(acc[0][2], a2.x, b2); fma2(acc[1][2], a2.y, b2);
            fma2(acc[0][3], a2.x, b3); fma2(acc[1][3], a2.y, b3);
        }
    }
    __syncthreads();

#pragma unroll
    for (int it = 0; it < 8; ++it) {
        const int k = (it * 8 + kq) * 4;
        As[(k + 0) * 32 + m] = pf[it].x;
        As[(k + 1) * 32 + m] = pf[it].y;
        As[(k + 2) * 32 + m] = pf[it].z;
        As[(k + 3) * 32 + m] = pf[it].w;
    }
    __syncthreads();
    {
        const float* Ag = As + ks * 32 * 32 + tm * 4;
        const float* Wg = Ws + (size_t)(256 + ks * 32) * 16 + tn * 4;
#pragma unroll 8
        for (int i = 0; i < 32; ++i) {
            const ulonglong2 a2 = *(const ulonglong2*)(Ag + i * 32);
            const float4 b4 = *(const float4*)(Wg + i * 16);
            const unsigned long long b0 = pack2(b4.x), b1 = pack2(b4.y),
                                     b2 = pack2(b4.z), b3 = pack2(b4.w);
            fma2(acc[0][0], a2.x, b0); fma2(acc[1][0], a2.y, b0);
            fma2(acc[0][1], a2.x, b1); fma2(acc[1][1], a2.y, b1);
            fma2(acc[0][2], a2.x, b2); fma2(acc[1][2], a2.y, b2);
            fma2(acc[0][3], a2.x, b3); fma2(acc[1][3], a2.y, b3);
        }
    }

#pragma unroll
    for (int i = 0; i < 2; ++i)
#pragma unroll
        for (int j = 0; j < 4; ++j) {
            float lo, hi;
            unpack2(lo, hi, acc[i][j]);
            red[ks * 512 + (tm * 4 + 2 * i)     * 16 + tn * 4 + j] = lo;
            red[ks * 512 + (tm * 4 + 2 * i + 1) * 16 + tn * 4 + j] = hi;
        }
    __syncthreads();
}

// ---------------- persistent ODE kernel (w-space, reordered tail) ----------
__global__ void __launch_bounds__(256, 1) ode_kernel(
    const float* __restrict__ t,
    const float* __restrict__ fw0, const float* __restrict__ fb0,
    const float* __restrict__ fw1, const float* __restrict__ fb1,
    const float* __restrict__ fw2, const float* __restrict__ fb2,
    const float* __restrict__ Gm,  const float* __restrict__ g0,
    float* __restrict__ zbuf, float* __restrict__ h1buf,
    float* __restrict__ h2buf, float* __restrict__ sbuf)
{
    extern __shared__ float smem[];
    float* W1s = smem;                 // 512k x 32n = 16384 f (64 KB)
    float* Gs  = W1s + 16384;          // 512k x 32n = 16384 f (64 KB)
    float* W2s = Gs  + 16384;          // 512k x 16n =  8192 f (32 KB)
    float* As  = W2s + 8192;           // 256k x 32m =  8192 f (32 KB)
    float* red = As  + 8192;           //               4096 f (16 KB)
    float* bS  = red + 4096;           // b1(32) | g0(32) | b2(16) = 80 f

    const int tid = threadIdx.x;
    const int c   = blockIdx.x & 15;   // N-slice 0..15
    const int grp = blockIdx.x >> 4;   // batch group 0..7
    const int m0  = grp * 32;
    const int n0w = c * 32;
    const int nzw = c * 16;

    for (int e = tid; e < 32 * 512; e += 256) {
        const int n = e >> 9, k = e & 511;
        W1s[k * 32 + n] = fw1[(size_t)(n0w + n) * 512 + k];
        Gs [k * 32 + n] = Gm [(size_t)(n0w + n) * 512 + k];
    }
    for (int e = tid; e < 16 * 512; e += 256) {
        const int n = e >> 9, k = e & 511;
        W2s[k * 16 + n] = fw2[(size_t)(nzw + n) * 512 + k];
    }
    if (tid < 32)       bS[tid] = fb1[n0w + tid];
    else if (tid < 64)  bS[tid] = g0[n0w + tid - 32];
    else if (tid < 80)  bS[tid] = fb2[nzw + tid - 64];
    __syncthreads();

    const int mr = tid >> 5;
    const int nn = tid & 31;
    float w[4], u[4] = {0.f, 0.f, 0.f, 0.f}, s[4] = {0.f, 0.f, 0.f, 0.f};

    // ---- init w = W0 @ z0 + b0
    {
        const int m  = tid & 31;
        const int kq = tid >> 5;
        const float* row = zbuf + (size_t)(m0 + m) * 256;
#pragma unroll
        for (int it = 0; it < 8; ++it) {
            const int k = (it * 8 + kq) * 4;
            const float4 v = __ldcg((const float4*)(row + k));
            As[(k + 0) * 32 + m] = v.x; As[(k + 1) * 32 + m] = v.y;
            As[(k + 2) * 32 + m] = v.z; As[(k + 3) * 32 + m] = v.w;
        }
        __syncthreads();
        const float b0v = fb0[n0w + nn];
        float wa[4] = {b0v, b0v, b0v, b0v};
        const float* w0row = fw0 + (size_t)(n0w + nn) * 256;
        for (int l = 0; l < 256; l += 4) {
            const float4 wv = __ldcg((const float4*)(w0row + l));
#pragma unroll
            for (int j = 0; j < 4; ++j) {
                const float wj = (&wv.x)[j];
#pragma unroll
                for (int i = 0; i < 4; ++i)
                    wa[i] = fmaf(As[(l + j) * 32 + mr + 8 * i], wj, wa[i]);
            }
        }
#pragma unroll
        for (int i = 0; i < 4; ++i) w[i] = wa[i];
        __syncthreads();
    }

    unsigned* flags = &g_flags[grp * (GRPSZ * 32)];
    unsigned lg;
    asm volatile("ld.acquire.gpu.u32 %0, [%1];"
                 : "=r"(lg) : "l"(flags + c * 32) : "memory");

    // ---- preamble: publish h1 for step 0, stage 0 (= tanh(w))
#pragma unroll
    for (int it = 0; it < 4; ++it)
        h1buf[(size_t)(m0 + mr + 8 * it) * 512 + n0w + nn] = tanhf(w[it]);
    gpub(flags, c, lg);
    gwait(flags, GRPSZ, lg);

    for (int n = 0; n < TSTEPS - 1; ++n) {
        const float hh = __ldg(&t[n + 1]) - __ldg(&t[n]);
        const float h6 = hh * (1.f / 6.f);
        const float* zn = zbuf + (size_t)n * (BSZ * LATD);
        float* znx      = zbuf + (size_t)(n + 1) * (BSZ * LATD);

#pragma unroll 1
        for (int st = 0; st < 4; ++st) {
            // h2 = tanh(W1 @ h1 + b1); s += sw*h2
            gemm32(h1buf, W1s, As, red, m0, tid);
            const float sw = (st == 1 || st == 2) ? 2.f : 1.f;
#pragma unroll
            for (int it = 0; it < 4; ++it) {
                const int m = mr + 8 * it;
                float v = red4(red, m, nn) + bS[nn];
                v = tanhf(v);
                s[it] = fmaf(sw, v, s[it]);
                if (st < 3) h2buf[(size_t)(m0 + m) * 512 + n0w + nn] = v;
                else        sbuf [(size_t)(m0 + m) * 512 + n0w + nn] = s[it];
            }
            gpub(flags, c, lg);
            gwait(flags, GRPSZ, lg);

            if (st < 3) {
                // u = G @ h2 + g0 ;  h1_{st+1} = tanh(w + cc*u)
                const float cc = (st == 2) ? hh : 0.5f * hh;
                gemm32(h2buf, Gs, As, red, m0, tid);
#pragma unroll
                for (int it = 0; it < 4; ++it) {
                    u[it] = red4(red, mr + 8 * it, nn) + bS[32 + nn];
                    h1buf[(size_t)(m0 + mr + 8 * it) * 512 + n0w + nn] =
                        tanhf(fmaf(cc, u[it], w[it]));
                }
                gpub(flags, c, lg);
                gwait(flags, GRPSZ, lg);
            }
        }

        // ---- tail: w += (h/6) G s + h g0 ; publish next h1 EARLY;
        //      then z-update slides into the publish->wait gap.
        if (n < TSTEPS - 2) {
            gemm32(sbuf, Gs, As, red, m0, tid);
#pragma unroll
            for (int it = 0; it < 4; ++it) {
                w[it] += h6 * red4(red, mr + 8 * it, nn) + hh * bS[32 + nn];
                h1buf[(size_t)(m0 + mr + 8 * it) * 512 + n0w + nn] = tanhf(w[it]);
            }
            gpub(flags, c, lg);

            gemmZ(sbuf, W2s, As, red, m0, tid);
#pragma unroll
            for (int it = 0; it < 2; ++it) {
                const int e = it * 256 + tid;
                const int m = e >> 4, nz = e & 15;
                float v = 0.f;
#pragma unroll
                for (int q = 0; q < 8; ++q) v += red[q * 512 + m * 16 + nz];
                const size_t idx = (size_t)(m0 + m) * 256 + nzw + nz;
                znx[idx] = __ldcg(zn + idx) + h6 * v + hh * bS[64 + nz];
            }
            gwait(flags, GRPSZ, lg);
        } else {
            // last step: only the z-update is needed
            gemmZ(sbuf, W2s, As, red, m0, tid);
#pragma unroll
            for (int it = 0; it < 2; ++it) {
                const int e = it * 256 + tid;
                const int m = e >> 4, nz = e & 15;
                float v = 0.f;
#pragma unroll
                for (int q = 0; q < 8; ++q) v += red[q * 512 + m * 16 + nz];
                const size_t idx = (size_t)(m0 + m) * 256 + nzw + nz;
                znx[idx] = __ldcg(zn + idx) + h6 * v + hh * bS[64 + nz];
            }
        }
#pragma unroll
        for (int i = 0; i < 4; ++i) s[i] = 0.f;
    }
}

// ---------------- G = fw0 @ fw2 precompute (NN GEMM 512x512x256) -----------
__launch_bounds__(256)
__global__ void gemmG_kernel(const float* __restrict__ fw0,
                             const float* __restrict__ fw2,
                             float* __restrict__ G)
{
    __shared__ float As[16][68];
    __shared__ float Bs[16][68];
    const int tid = threadIdx.x;
    const int tx = tid & 15, ty = tid >> 4;
    const int m0 = blockIdx.y * 64, n0 = blockIdx.x * 64;

    float acc[4][4] = {};
    for (int k0 = 0; k0 < 256; k0 += 16) {
        {
            const int ar = tid >> 2, ak = (tid & 3) * 4;
            const float4 av = *(const float4*)(fw0 + (size_t)(m0 + ar) * 256 + k0 + ak);
            As[ak + 0][ar] = av.x; As[ak + 1][ar] = av.y;
            As[ak + 2][ar] = av.z; As[ak + 3][ar] = av.w;
            const int kk = tid >> 4, bn = (tid & 15) * 4;
            const float4 bv = *(const float4*)(fw2 + (size_t)(k0 + kk) * 512 + n0 + bn);
            *(float4*)&Bs[kk][bn] = bv;
        }
        __syncthreads();
#pragma unroll
        for (int k = 0; k < 16; ++k) {
            float a[4], b[4];
#pragma unroll
            for (int i = 0; i < 4; ++i) a[i] = As[k][ty * 4 + i];
#pragma unroll
            for (int j = 0; j < 4; ++j) b[j] = Bs[k][tx * 4 + j];
#pragma unroll
            for (int i = 0; i < 4; ++i)
#pragma unroll
                for (int j = 0; j < 4; ++j) acc[i][j] = fmaf(a[i], b[j], acc[i][j]);
        }
        __syncthreads();
    }
#pragma unroll
    for (int i = 0; i < 4; ++i)
#pragma unroll
        for (int j = 0; j < 4; ++j)
            G[(size_t)(m0 + ty * 4 + i) * 512 + n0 + tx * 4 + j] = acc[i][j];
}

__global__ void g0_kernel(const float* __restrict__ fw0,
                          const float* __restrict__ fb2,
                          float* __restrict__ g0)
{
    const int n = blockIdx.x * 256 + threadIdx.x;
    float acc = 0.f;
    for (int l = 0; l < 256; ++l)
        acc = fmaf(fw0[(size_t)n * 256 + l], fb2[l], acc);
    g0[n] = acc;
}

// ---------------- fused encoder: 3 gather-GEMM stages, one kernel ----------
template<int G>
__device__ __forceinline__ float gatherA(const float* __restrict__ src, int row, int c)
{
    if (G == 1) {
        const int l = row >> 8, b = row & 255;
        if (c < 192) {
            const int i = c / 3, kk = c - 3 * i, p = l + kk - 1;
            return (p >= 0) ? src[(size_t)b * 65536 + i * 1024 + p] : 0.f;
        }
        return src[(size_t)b * 65536 + (c - 192) * 1024 + l];
    } else if (G == 2) {
        const int l = row >> 8, b = row & 255;
        if (c < 768) {
            const int i = c / 3, kk = c - 3 * i, p = l + kk - 1;
            return (p >= 0) ? src[(size_t)(p * 256 + b) * 256 + i] : 0.f;
        }
        return src[(size_t)(l * 256 + b) * 256 + (c - 768)];
    } else {
        const int b = row;
        if (c < 256)  return src[(size_t)b * 256 + c];
        if (c < 512)  return src[(size_t)(256 + b) * 256 + (c - 256)];
        return src[(size_t)b * 256 + (c - 512)];
    }
}

template<int G>
__device__ __forceinline__ float gatherW(const float* __restrict__ ew,
                                         const float* __restrict__ rw, int o, int c)
{
    if (G == 1) {
        if (c < 192) return ew[o * 192 + c];
        return rw[o * 64 + (c - 192)];
    } else if (G == 2) {
        if (c < 768) return ew[o * 768 + c];
        return rw[o * 256 + (c - 768)];
    } else {
        if (c < 256)  return ew[o * 768 + c * 3 + 1];
        if (c < 512)  return ew[o * 768 + (c - 256) * 3 + 2];
        return rw[o * 256 + (c - 512)];
    }
}

template<int G, int TANH>
__device__ void enc_tile(const float* __restrict__ Asrc,
                         const float* __restrict__ ew, const float* __restrict__ rw,
                         const float* __restrict__ eb, const float* __restrict__ rb,
                         float* __restrict__ C, int K, int m0, int n0,
                         float (*As)[34], float (*Bs)[34])
{
    const int tid = threadIdx.x;
    const int tx  = tid & 15;
    const int ty  = tid >> 4;
    const int ar = tid >> 3;
    const int ak = (tid & 7) * 4;

    float acc[2][2] = {{0.f, 0.f}, {0.f, 0.f}};

    for (int k0 = 0; k0 < K; k0 += 32) {
        __syncthreads();
#pragma unroll
        for (int j = 0; j < 4; j++) {
            As[ak + j][ar] = gatherA<G>(Asrc, m0 + ar, k0 + ak + j);
            Bs[ak + j][ar] = gatherW<G>(ew, rw, n0 + ar, k0 + ak + j);
        }
        __syncthreads();
#pragma unroll
        for (int k = 0; k < 32; k++) {
            const float a0 = As[k][ty * 2], a1 = As[k][ty * 2 + 1];
            const float b0 = Bs[k][tx * 2], b1 = Bs[k][tx * 2 + 1];
            acc[0][0] = fmaf(a0, b0, acc[0][0]);
            acc[0][1] = fmaf(a0, b1, acc[0][1]);
            acc[1][0] = fmaf(a1, b0, acc[1][0]);
            acc[1][1] = fmaf(a1, b1, acc[1][1]);
        }
    }
    __syncthreads();

#pragma unroll
    for (int i = 0; i < 2; i++) {
        const int m = m0 + ty * 2 + i;
#pragma unroll
        for (int j = 0; j < 2; j++) {
            const int n = n0 + tx * 2 + j;
            float v = acc[i][j] + eb[n] + rb[n];
            if (TANH) v = tanhf(v);
            C[(size_t)m * 256 + n] = v;
        }
    }
}

__global__ __launch_bounds__(256) void enc_all(
    const float* __restrict__ y,
    const float* __restrict__ ew0, const float* __restrict__ rw0,
    const float* __restrict__ eb0, const float* __restrict__ rb0,
    const float* __restrict__ ew1, const float* __restrict__ rw1,
    const float* __restrict__ eb1, const float* __restrict__ rb1,
    const float* __restrict__ ew2, const float* __restrict__ rw2,
    const float* __restrict__ eb2, const float* __restrict__ rb2,
    float* __restrict__ x0, float* __restrict__ x1, float* __restrict__ z0)
{
    __shared__ float As[32][34];
    __shared__ float Bs[32][34];

    const int bid = blockIdx.x;   // 0..95
    unsigned lg;
    asm volatile("ld.acquire.gpu.u32 %0, [%1];"
                 : "=r"(lg) : "l"(&g_eflags[bid * 32]) : "memory");

    // stage 1: 192 tiles (8n x 24m); block does t=bid and t=bid+96
    {
        int t = bid;
        enc_tile<1, 1>(y, ew0, rw0, eb0, rb0, x0, 256,
                       (t >> 3) * 32, (t & 7) * 32, As, Bs);
        t = bid + 96;
        enc_tile<1, 1>(y, ew0, rw0, eb0, rb0, x0, 256,
                       (t >> 3) * 32, (t & 7) * 32, As, Bs);
    }
    gpub(g_eflags, bid, lg);
    gwait(g_eflags, EBLK, lg);

    // stage 2: 128 tiles (8n x 16m); t=bid (<96) and t=bid+96 (bid<32)
    {
        int t = bid;
        if (t < 128)
            enc_tile<2, 1>(x0, ew1, rw1, eb1, rb1, x1, 1024,
                           (t >> 3) * 32, (t & 7) * 32, As, Bs);
        t = bid + 96;
        if (t < 128)
            enc_tile<2, 1>(x0, ew1, rw1, eb1, rb1, x1, 1024,
                           (t >> 3) * 32, (t & 7) * 32, As, Bs);
    }
    gpub(g_eflags, bid, lg);
    gwait(g_eflags, EBLK, lg);

    // stage 3: 64 tiles (8n x 8m); blocks 0..63
    if (bid < 64)
        enc_tile<3, 0>(x1, ew2, rw2, eb2, rb2, z0, 768,
                       (bid >> 3) * 32, (bid & 7) * 32, As, Bs);
}

// ---------------- decoder GEMM: 64x64x16 tile, f32x2 inner ------------
template<int EPI>
__launch_bounds__(256)
__global__ void dec_gemm(const float* __restrict__ A,
                         const float* __restrict__ W,
                         const float* __restrict__ bias,
                         float* __restrict__ C,
                         int M, int N, int K)
{
    __shared__ float As[16][68];
    __shared__ float Bs[16][68];

    const int tid = threadIdx.x;
    const int tx  = tid & 15;
    const int ty  = tid >> 4;
    const int m0  = blockIdx.y * 64;
    const int n0  = blockIdx.x * 64;

    const int ar = tid >> 2;
    const int ak = (tid & 3) * 4;

    unsigned long long acc2[2][4];
#pragma unroll
    for (int i = 0; i < 2; i++)
#pragma unroll
        for (int j = 0; j < 4; j++) acc2[i][j] = 0ULL;

    const float* Aptr = A + (size_t)(m0 + ar) * K + ak;
    const float* Wptr = W + (size_t)(n0 + ar) * K + ak;

    for (int k0 = 0; k0 < K; k0 += 16) {
        const float4 av = *(const float4*)(Aptr + k0);
        const float4 bv = *(const float4*)(Wptr + k0);
        As[ak + 0][ar] = av.x; As[ak + 1][ar] = av.y;
        As[ak + 2][ar] = av.z; As[ak + 3][ar] = av.w;
        Bs[ak + 0][ar] = bv.x; Bs[ak + 1][ar] = bv.y;
        Bs[ak + 2][ar] = bv.z; Bs[ak + 3][ar] = bv.w;
        __syncthreads();
#pragma unroll
        for (int k = 0; k < 16; k++) {
            const ulonglong2 a2 = *(const ulonglong2*)(&As[k][ty * 4]);
            const float4 b4 = *(const float4*)(&Bs[k][tx * 4]);
            unsigned long long bb[4];
            bb[0] = pack2(b4.x); bb[1] = pack2(b4.y);
            bb[2] = pack2(b4.z); bb[3] = pack2(b4.w);
#pragma unroll
            for (int j = 0; j < 4; j++) {
                fma2(acc2[0][j], a2.x, bb[j]);
                fma2(acc2[1][j], a2.y, bb[j]);
            }
        }
        __syncthreads();
    }

#pragma unroll
    for (int i = 0; i < 2; i++) {
#pragma unroll
        for (int j = 0; j < 4; j++) {
            float lo, hi;
            unpack2(lo, hi, acc2[i][j]);
            const int n = n0 + tx * 4 + j;
            const float bval = bias[n];
#pragma unroll
            for (int half = 0; half < 2; half++) {
                const int m = m0 + ty * 4 + 2 * i + half;
                float v = (half == 0 ? lo : hi) + bval;
                if (EPI == 1) v = tanhf(v);
                if (EPI == 3) {
                    const int tt = m >> 8;
                    const int bb2 = m & 255;
                    C[(size_t)bb2 * (SIG * TSTEPS) + (size_t)n * TSTEPS + tt] = v;
                } else {
                    C[(size_t)m * N + n] = v;
                }
            }
        }
    }
}

extern "C" void kernel_launch(void* const* d_in, const int* in_sizes, int n_in,
                              void* d_out, int out_size)
{
    const float* y   = (const float*)d_in[0];
    const float* t   = (const float*)d_in[1];
    const float* ew0 = (const float*)d_in[2];
    const float* eb0 = (const float*)d_in[3];
    const float* rw0 = (const float*)d_in[4];
    const float* rb0 = (const float*)d_in[5];
    const float* ew1 = (const float*)d_in[6];
    const float* eb1 = (const float*)d_in[7];
    const float* rw1 = (const float*)d_in[8];
    const float* rb1 = (const float*)d_in[9];
    const float* ew2 = (const float*)d_in[10];
    const float* eb2 = (const float*)d_in[11];
    const float* rw2 = (const float*)d_in[12];
    const float* rb2 = (const float*)d_in[13];
    const float* fw0 = (const float*)d_in[14];
    const float* fb0 = (const float*)d_in[15];
    const float* fw1 = (const float*)d_in[16];
    const float* fb1 = (const float*)d_in[17];
    const float* fw2 = (const float*)d_in[18];
    const float* fb2 = (const float*)d_in[19];
    const float* dw0 = (const float*)d_in[20];
    const float* db0 = (const float*)d_in[21];
    const float* dw1 = (const float*)d_in[22];
    const float* db1 = (const float*)d_in[23];
    const float* dw2 = (const float*)d_in[24];
    const float* db2 = (const float*)d_in[25];
    float* out = (float*)d_out;

    float *zbuf, *h1, *h2, *sbuf, *Gm, *g0, *x0, *x1, *hd1, *hd2;
    cudaGetSymbolAddress((void**)&zbuf, g_z);
    cudaGetSymbolAddress((void**)&h1,   g_h1);
    cudaGetSymbolAddress((void**)&h2,   g_h2);
    cudaGetSymbolAddress((void**)&sbuf, g_s);
    cudaGetSymbolAddress((void**)&Gm,   g_G);
    cudaGetSymbolAddress((void**)&g0,   g_g0);
    cudaGetSymbolAddress((void**)&x0,   g_x0);
    cudaGetSymbolAddress((void**)&x1,   g_x1);
    cudaGetSymbolAddress((void**)&hd1,  g_hd1);
    cudaGetSymbolAddress((void**)&hd2,  g_hd2);

    // launch 1-2: precompute G = fw0 @ fw2, g0 = fw0 @ fb2
    { dim3 g(8, 8); gemmG_kernel<<<g, 256>>>(fw0, fw2, Gm); }
    g0_kernel<<<2, 256>>>(fw0, fb2, g0);

    // launch 3: fused encoder -> z0
    enc_all<<<EBLK, 256>>>(y, ew0, rw0, eb0, rb0, ew1, rw1, eb1, rb1,
                           ew2, rw2, eb2, rb2, x0, x1, zbuf);

    // launch 4 (profiled): RK4 ODE persistent kernel
    const int smem_bytes = (16384 + 16384 + 8192 + 8192 + 4096 + 80) * 4;
    cudaFuncSetAttribute(ode_kernel, cudaFuncAttributeMaxDynamicSharedMemorySize,
                         smem_bytes);
    ode_kernel<<<NBLK, 256, smem_bytes>>>(t, fw0, fb0, fw1, fb1, fw2, fb2,
                                          Gm, g0, zbuf, h1, h2, sbuf);

    // launches 5-7: decoder over all 200 states
    { dim3 g(DECH / 64, TSTEPS * BSZ / 64); dec_gemm<1><<<g, 256>>>(zbuf, dw0, db0, hd1, TSTEPS * BSZ, DECH, LATD); }
    { dim3 g(DECH / 64, TSTEPS * BSZ / 64); dec_gemm<1><<<g, 256>>>(hd1,  dw1, db1, hd2, TSTEPS * BSZ, DECH, DECH); }
    { dim3 g(SIG  / 64, TSTEPS * BSZ / 64); dec_gemm<3><<<g, 256>>>(hd2,  dw2, db2, out, TSTEPS * BSZ, SIG,  DECH); }
}